// round 9
// baseline (speedup 1.0000x reference)
#include <cuda_runtime.h>
#include <cuda_bf16.h>
#include <mma.h>
#include <math.h>
#include <cstdint>

using namespace nvcuda;

#define BATCH 4
#define SEQ 1024
#define DIM 1024
#define NHEADS 16
#define HDIM 64
#define MLP 4096
#define MTOT (BATCH*SEQ)        /* 4096 */
#define QKVW (5*NHEADS*HDIM)    /* 5120 */
#define ATTN_CLIP 100.0f
#define NORM_CLIP 1000.0f
#define EPSF 1e-6f

// ================= scratch =================
__device__ float g_x2 [MTOT*DIM];
__device__ __nv_bfloat16 g_ahi[(size_t)MTOT*MLP];
__device__ __nv_bfloat16 g_alo[(size_t)MTOT*MLP];
__device__ __nv_bfloat16 g_qhi[(size_t)MTOT*QKVW];
__device__ __nv_bfloat16 g_qlo[(size_t)MTOT*QKVW];
__device__ __nv_bfloat16 g_bhi[(size_t)QKVW*DIM];
__device__ __nv_bfloat16 g_blo[(size_t)QKVW*DIM];
__device__ __nv_bfloat16 g_vthi[(size_t)BATCH*NHEADS*HDIM*SEQ];
__device__ __nv_bfloat16 g_vtlo[(size_t)BATCH*NHEADS*HDIM*SEQ];
__device__ float g_part[BATCH*128];
__device__ float g_nx[BATCH];
__device__ float g_lam;

// ================= helpers =================
__device__ __forceinline__ uint32_t smem_u32(const void* p) {
    uint32_t a;
    asm("{ .reg .u64 t; cvta.to.shared.u64 t, %1; cvt.u32.u64 %0, t; }" : "=r"(a) : "l"(p));
    return a;
}
#define CP_ASYNC16(dst, src) \
    asm volatile("cp.async.cg.shared.global [%0], [%1], 16;" :: "r"(dst), "l"(src))
#define CP_COMMIT() asm volatile("cp.async.commit_group;" ::: "memory")
#define CP_WAIT(n)  asm volatile("cp.async.wait_group %0;" :: "n"(n) : "memory")

#define MMA_BF16(d, a, b) \
    asm volatile("mma.sync.aligned.m16n8k16.row.col.f32.bf16.bf16.f32 " \
        "{%0,%1,%2,%3}, {%4,%5,%6,%7}, {%8,%9}, {%0,%1,%2,%3};" \
        : "+f"((d)[0]), "+f"((d)[1]), "+f"((d)[2]), "+f"((d)[3]) \
        : "r"((a)[0]), "r"((a)[1]), "r"((a)[2]), "r"((a)[3]), \
          "r"((b)[0]), "r"((b)[1]))

__device__ __forceinline__ uint32_t pk2(float x, float y) {
    __nv_bfloat162 t = __floats2bfloat162_rn(x, y);
    return *(uint32_t*)&t;
}
__device__ __forceinline__ uint32_t pk2lo(float x, float y, uint32_t hipk) {
    __nv_bfloat162 hp = *(__nv_bfloat162*)&hipk;
    return pk2(x - __bfloat162float(hp.x), y - __bfloat162float(hp.y));
}

// ================= scalar kernels =================
__global__ void reduce_sq_kernel(const float* __restrict__ x) {
    const int b = blockIdx.y, blk = blockIdx.x;
    const int N = SEQ*DIM;
    const int per = N / 128;
    const float* p = x + (size_t)b*N + (size_t)blk*per;
    float s = 0.f;
    for (int i = threadIdx.x; i < per; i += 256) { float v = p[i]; s += v*v; }
    __shared__ float red[8];
    int lane = threadIdx.x & 31, w = threadIdx.x >> 5;
#pragma unroll
    for (int o = 16; o; o >>= 1) s += __shfl_down_sync(0xffffffffu, s, o);
    if (lane == 0) red[w] = s;
    __syncthreads();
    if (w == 0) {
        s = (lane < 8) ? red[lane] : 0.f;
#pragma unroll
        for (int o = 4; o; o >>= 1) s += __shfl_down_sync(0xffffffffu, s, o);
        if (lane == 0) g_part[b*128 + blk] = s;
    }
}

__global__ void compute_nx_kernel() {
    int b = threadIdx.x;
    if (b < BATCH) {
        float s = 0.f;
        for (int i = 0; i < 128; i++) s += g_part[b*128 + i];
        s = fminf(fmaxf(s, EPSF), NORM_CLIP);
        float gx = sqrtf(s);
        float nx = gx / (gx + EPSF);
        nx = fminf(fmaxf(nx, -NORM_CLIP), NORM_CLIP);
        g_nx[b] = nx;
    }
}

__global__ void compute_lam_kernel(const float* __restrict__ lq1, const float* __restrict__ lk1,
                                   const float* __restrict__ lq2, const float* __restrict__ lk2) {
    float s1 = 0.f, s2 = 0.f;
    for (int d = 0; d < HDIM; d++) { s1 += lq1[d]*lk1[d]; s2 += lq2[d]*lk2[d]; }
    s1 = fminf(fmaxf(s1, -10.f), 10.f);
    s2 = fminf(fmaxf(s2, -10.f), 10.f);
    float lam_init = 0.8f - 0.6f*expf(-0.0f);
    float lam = expf(s1) - expf(s2) + lam_init;
    g_lam = fminf(fmaxf(lam, 0.1f), 5.f);
}

// ================= GRN fused with hi/lo split =================
__global__ void grn_split_kernel(const float* __restrict__ x, const float* __restrict__ gamma,
                                 const float* __restrict__ beta,
                                 __nv_bfloat16* __restrict__ hi, __nv_bfloat16* __restrict__ lo) {
    int idx = blockIdx.x*blockDim.x + threadIdx.x;
    int e = idx * 4;
    int b = e >> 20;
    int d = e & (DIM-1);
    float nx = g_nx[b];
    float4 xv = *(const float4*)(x + e);
    float4 gv = *(const float4*)(gamma + d);
    float4 bv = *(const float4*)(beta + d);
    float r0 = gv.x*(xv.x*nx) + bv.x + xv.x;
    float r1 = gv.y*(xv.y*nx) + bv.y + xv.y;
    float r2 = gv.z*(xv.z*nx) + bv.z + xv.z;
    float r3 = gv.w*(xv.w*nx) + bv.w + xv.w;
    uint2 ph, pl;
    ph.x = pk2(r0, r1); ph.y = pk2(r2, r3);
    pl.x = pk2lo(r0, r1, ph.x); pl.y = pk2lo(r2, r3, ph.y);
    *(uint2*)(hi + e) = ph;
    *(uint2*)(lo + e) = pl;
}

// ================= weight transpose + split =================
__global__ void transpose_split_kernel(const float* __restrict__ w,
                                       __nv_bfloat16* __restrict__ thi,
                                       __nv_bfloat16* __restrict__ tlo,
                                       int K, int N) {
    __shared__ float tile[32][33];
    int n0 = blockIdx.x * 32, k0 = blockIdx.y * 32;
    int tx = threadIdx.x, ty = threadIdx.y;
#pragma unroll
    for (int i = 0; i < 4; i++)
        tile[ty + i*8][tx] = w[(size_t)(k0 + ty + i*8)*N + n0 + tx];
    __syncthreads();
#pragma unroll
    for (int i = 0; i < 4; i++) {
        float v = tile[tx][ty + i*8];
        __nv_bfloat16 h = __float2bfloat16(v);
        __nv_bfloat16 l = __float2bfloat16(v - __bfloat162float(h));
        size_t o = (size_t)(n0 + ty + i*8)*K + k0 + tx;
        thi[o] = h; tlo[o] = l;
    }
}

// ================= V transpose =================
__global__ void vtrans_kernel(const __nv_bfloat16* __restrict__ qHi,
                              const __nv_bfloat16* __restrict__ qLo,
                              __nv_bfloat16* __restrict__ vtHi,
                              __nv_bfloat16* __restrict__ vtLo) {
    __shared__ __nv_bfloat16 th[32][33], tl[32][33];
    const int b = blockIdx.z;
    const int t0 = blockIdx.x * 32;
    const int f0 = blockIdx.y * 32;
    const int tx = threadIdx.x, ty = threadIdx.y;
#pragma unroll
    for (int i = 0; i < 4; i++) {
        size_t src = (size_t)(b*SEQ + t0 + ty + i*8)*QKVW + 4096 + f0 + tx;
        th[ty + i*8][tx] = qHi[src];
        tl[ty + i*8][tx] = qLo[src];
    }
    __syncthreads();
#pragma unroll
    for (int i = 0; i < 4; i++) {
        int f = f0 + ty + i*8;
        int h = f >> 6, d = f & 63;
        size_t dst = ((size_t)(b*NHEADS + h)*HDIM + d)*SEQ + t0 + tx;
        vtHi[dst] = th[tx][ty + i*8];
        vtLo[dst] = tl[tx][ty + i*8];
    }
}

// ================= wmma bf16-split GEMM, 64x64 warp tiles =================
// 128 threads (4 warps, 2x2), CTA tile 128x128, K-chunk 32.
// EPI 2: fp32 C = acc + bias + res;  EPI 4: split(acc);  EPI 5: split(silu(acc+bias))
#define KC 32
#define LDA 40
#define TILE_ELEMS (128*LDA)
#define BUF_ELEMS (4*TILE_ELEMS)
#define SMEM_WG (2*BUF_ELEMS*2)      /* 81920 B */
#define SLD 132

template<int EPI>
__global__ __launch_bounds__(128, 2)
void wmma_gemm(const __nv_bfloat16* __restrict__ Ahi, const __nv_bfloat16* __restrict__ Alo,
               const __nv_bfloat16* __restrict__ Bhi, const __nv_bfloat16* __restrict__ Blo,
               float* __restrict__ C,
               __nv_bfloat16* __restrict__ CHi, __nv_bfloat16* __restrict__ CLo,
               int M, int N, int K,
               const float* __restrict__ bias, const float* __restrict__ res) {
    extern __shared__ char smem_raw[];
    __nv_bfloat16* sm = (__nv_bfloat16*)smem_raw;
    const uint32_t sm_addr = smem_u32(sm);

    const int tid = threadIdx.x;
    const int wid = tid >> 5;
    const int row0 = blockIdx.y * 128;
    const int col0 = blockIdx.x * 128;
    const int wr = (wid >> 1) * 64;
    const int wc = (wid & 1) * 64;

    const __nv_bfloat16* gA0 = Ahi + (size_t)row0*K;
    const __nv_bfloat16* gA1 = Alo + (size_t)row0*K;
    const __nv_bfloat16* gB0 = Bhi + (size_t)col0*K;
    const __nv_bfloat16* gB1 = Blo + (size_t)col0*K;

    auto issue_tile = [&](const __nv_bfloat16* src, int k0, uint32_t dbase) {
#pragma unroll
        for (int i = 0; i < 4; i++) {
            int idx = tid + i*128;          // 0..511 units of 16B
            int r = idx >> 2, c = (idx & 3) * 8;
            CP_ASYNC16(dbase + (uint32_t)(r*LDA + c)*2, src + (size_t)r*K + k0 + c);
        }
    };
    auto issue_chunk = [&](int k0, int buf) {
        uint32_t dbase = sm_addr + (uint32_t)buf * (BUF_ELEMS*2);
        issue_tile(gA0, k0, dbase);
        issue_tile(gA1, k0, dbase + TILE_ELEMS*2);
        issue_tile(gB0, k0, dbase + 2*TILE_ELEMS*2);
        issue_tile(gB1, k0, dbase + 3*TILE_ELEMS*2);
        CP_COMMIT();
    };

    wmma::fragment<wmma::accumulator, 16, 16, 16, float> acc[4][4];
#pragma unroll
    for (int i = 0; i < 4; i++)
#pragma unroll
        for (int j = 0; j < 4; j++) wmma::fill_fragment(acc[i][j], 0.f);

    const int nch = K / KC;
    issue_chunk(0, 0);

    for (int ch = 0; ch < nch; ch++) {
        const int cur = ch & 1;
        if (ch + 1 < nch) { issue_chunk((ch+1)*KC, cur ^ 1); CP_WAIT(1); }
        else              { CP_WAIT(0); }
        __syncthreads();

        const __nv_bfloat16* b0 = sm + cur * BUF_ELEMS;
        const __nv_bfloat16* tAhi = b0 + 0*TILE_ELEMS + wr*LDA;
        const __nv_bfloat16* tAlo = b0 + 1*TILE_ELEMS + wr*LDA;
        const __nv_bfloat16* tBhi = b0 + 2*TILE_ELEMS + wc*LDA;
        const __nv_bfloat16* tBlo = b0 + 3*TILE_ELEMS + wc*LDA;

#pragma unroll
        for (int ks = 0; ks < 2; ks++) {
            const int ko = ks * 16;
            wmma::fragment<wmma::matrix_a, 16, 16, 16, __nv_bfloat16, wmma::row_major> aH[4], aL[4];
            wmma::fragment<wmma::matrix_b, 16, 16, 16, __nv_bfloat16, wmma::col_major> bF[4];
#pragma unroll
            for (int i = 0; i < 4; i++)
                wmma::load_matrix_sync(aH[i], tAhi + i*16*LDA + ko, LDA);
#pragma unroll
            for (int j = 0; j < 4; j++)
                wmma::load_matrix_sync(bF[j], tBhi + j*16*LDA + ko, LDA);
            // hh
#pragma unroll
            for (int i = 0; i < 4; i++)
#pragma unroll
                for (int j = 0; j < 4; j++)
                    wmma::mma_sync(acc[i][j], aH[i], bF[j], acc[i][j]);
            // lh (reuse bF = Bhi)
#pragma unroll
            for (int i = 0; i < 4; i++)
                wmma::load_matrix_sync(aL[i], tAlo + i*16*LDA + ko, LDA);
#pragma unroll
            for (int i = 0; i < 4; i++)
#pragma unroll
                for (int j = 0; j < 4; j++)
                    wmma::mma_sync(acc[i][j], aL[i], bF[j], acc[i][j]);
            // hl (reuse aH)
#pragma unroll
            for (int j = 0; j < 4; j++)
                wmma::load_matrix_sync(bF[j], tBlo + j*16*LDA + ko, LDA);
#pragma unroll
            for (int i = 0; i < 4; i++)
#pragma unroll
                for (int j = 0; j < 4; j++)
                    wmma::mma_sync(acc[i][j], aH[i], bF[j], acc[i][j]);
        }
        __syncthreads();
    }

    float* stage = (float*)smem_raw;
#pragma unroll
    for (int i = 0; i < 4; i++)
#pragma unroll
        for (int j = 0; j < 4; j++)
            wmma::store_matrix_sync(stage + (wr + i*16)*SLD + wc + j*16,
                                    acc[i][j], SLD, wmma::mem_row_major);
    __syncthreads();

    const int r = tid;                 // each thread owns one row
    const int row = row0 + r;

    if (EPI == 2) {
        size_t obase = (size_t)row*N + col0;
#pragma unroll 8
        for (int j = 0; j < 32; j++) {
            float4 v = *(float4*)(stage + r*SLD + j*4);
            float4 w;
            float* vi = (float*)&v; float* wi = (float*)&w;
#pragma unroll
            for (int q = 0; q < 4; q++)
                wi[q] = vi[q] + bias[col0 + j*4 + q] + res[obase + j*4 + q];
            *(float4*)(C + obase + j*4) = w;
        }
    } else {
        __nv_bfloat16* dh = CHi + (size_t)row*N + col0;
        __nv_bfloat16* dl = CLo + (size_t)row*N + col0;
#pragma unroll 4
        for (int j = 0; j < 16; j++) {
            float t[8];
#pragma unroll
            for (int q = 0; q < 8; q++) {
                float v = stage[r*SLD + j*8 + q];
                if (EPI == 5) {
                    v += bias[col0 + j*8 + q];
                    v = v / (1.f + __expf(-v));
                }
                t[q] = v;
            }
            uint4 ph, pl;
            uint32_t* phi = (uint32_t*)&ph;
            uint32_t* pli = (uint32_t*)&pl;
#pragma unroll
            for (int q = 0; q < 4; q++) {
                phi[q] = pk2(t[2*q], t[2*q+1]);
                pli[q] = pk2lo(t[2*q], t[2*q+1], phi[q]);
            }
            *(uint4*)(dh + j*8) = ph;
            *(uint4*)(dl + j*8) = pl;
        }
    }
}

// ================= tensor-core differential flash attention (unchanged) =================
#define AP 72
#define TQ1H 0
#define TQ1L 4608
#define TQ2H 9216
#define TQ2L 13824
#define TK1H 18432
#define TK1L 23040
#define TK2H 27648
#define TK2L 32256
#define TVH  36864
#define TVL  41472
#define SMEM_ATT (46080*2)

__device__ __forceinline__ void softmax_upd(float sc[8][4], float m[2], float l[2],
                                            float oc[8][4]) {
    float t0 = -1e30f, t1 = -1e30f;
#pragma unroll
    for (int nb = 0; nb < 8; nb++) {
        t0 = fmaxf(t0, fmaxf(sc[nb][0], sc[nb][1]));
        t1 = fmaxf(t1, fmaxf(sc[nb][2], sc[nb][3]));
    }
    t0 = fmaxf(t0, __shfl_xor_sync(0xffffffffu, t0, 1));
    t0 = fmaxf(t0, __shfl_xor_sync(0xffffffffu, t0, 2));
    t1 = fmaxf(t1, __shfl_xor_sync(0xffffffffu, t1, 1));
    t1 = fmaxf(t1, __shfl_xor_sync(0xffffffffu, t1, 2));
    float nm0 = fmaxf(m[0], t0), nm1 = fmaxf(m[1], t1);
    float c0 = __expf(m[0] - nm0), c1 = __expf(m[1] - nm1);
    float s0 = 0.f, s1 = 0.f;
#pragma unroll
    for (int nb = 0; nb < 8; nb++) {
        float p0 = __expf(sc[nb][0] - nm0); sc[nb][0] = p0; s0 += p0;
        float p1 = __expf(sc[nb][1] - nm0); sc[nb][1] = p1; s0 += p1;
        float p2 = __expf(sc[nb][2] - nm1); sc[nb][2] = p2; s1 += p2;
        float p3 = __expf(sc[nb][3] - nm1); sc[nb][3] = p3; s1 += p3;
    }
    s0 += __shfl_xor_sync(0xffffffffu, s0, 1);
    s0 += __shfl_xor_sync(0xffffffffu, s0, 2);
    s1 += __shfl_xor_sync(0xffffffffu, s1, 1);
    s1 += __shfl_xor_sync(0xffffffffu, s1, 2);
    l[0] = l[0]*c0 + s0;  l[1] = l[1]*c1 + s1;
#pragma unroll
    for (int db = 0; db < 8; db++) {
        oc[db][0] *= c0; oc[db][1] *= c0;
        oc[db][2] *= c1; oc[db][3] *= c1;
    }
    m[0] = nm0; m[1] = nm1;
}

__global__ __launch_bounds__(128)
void diff_attn_mma(const __nv_bfloat16* __restrict__ qHi, const __nv_bfloat16* __restrict__ qLo,
                   const __nv_bfloat16* __restrict__ vtHi, const __nv_bfloat16* __restrict__ vtLo,
                   __nv_bfloat16* __restrict__ oHi, __nv_bfloat16* __restrict__ oLo) {
    extern __shared__ __nv_bfloat16 sb[];
    const uint32_t smb = smem_u32(sb);
    const int tid = threadIdx.x;
    const int wid = tid >> 5, lane = tid & 31;
    const int g4 = lane >> 2, t4 = lane & 3;
    const int qt = blockIdx.x, h = blockIdx.y, b = blockIdx.z;
    const int q0 = qt * 64;
    const float lam = g_lam;

    auto ld_tile = [&](int tileEls, const __nv_bfloat16* src, int rowStride) {
#pragma unroll
        for (int i = 0; i < 4; i++) {
            int idx = tid + i*128;
            int r = idx >> 3, c8 = idx & 7;
            CP_ASYNC16(smb + (uint32_t)tileEls*2 + r*144 + c8*16,
                       src + (size_t)r*rowStride + c8*8);
        }
    };

    {
        const size_t qb = (size_t)(b*SEQ + q0)*QKVW + h*HDIM;
        ld_tile(TQ1H, qHi + qb,        QKVW);
        ld_tile(TQ1L, qLo + qb,        QKVW);
        ld_tile(TQ2H, qHi + qb + 1024, QKVW);
        ld_tile(TQ2L, qLo + qb + 1024, QKVW);
        CP_COMMIT();
    }

    float oc1[8][4], oc2[8][4];
#pragma unroll
    for (int i = 0; i < 8; i++)
#pragma unroll
        for (int j = 0; j < 4; j++) { oc1[i][j] = 0.f; oc2[i][j] = 0.f; }
    float m1[2] = {-1e30f, -1e30f}, l1[2] = {0.f, 0.f};
    float m2[2] = {-1e30f, -1e30f}, l2[2] = {0.f, 0.f};

    for (int kt = 0; kt < 16; kt++) {
        __syncthreads();
        const int k0 = kt * 64;
        {
            const size_t kb = (size_t)(b*SEQ + k0)*QKVW + h*HDIM;
            const size_t vb = ((size_t)(b*NHEADS + h)*HDIM)*SEQ + k0;
            ld_tile(TK1H, qHi + kb + 2048, QKVW);
            ld_tile(TK1L, qLo + kb + 2048, QKVW);
            ld_tile(TK2H, qHi + kb + 3072, QKVW);
            ld_tile(TK2L, qLo + kb + 3072, QKVW);
            ld_tile(TVH,  vtHi + vb, SEQ);
            ld_tile(TVL,  vtLo + vb, SEQ);
            CP_COMMIT();
        }
        CP_WAIT(0);
        __syncthreads();

        float sc1[8][4], sc2[8][4];
#pragma unroll
        for (int i = 0; i < 8; i++)
#pragma unroll
            for (int j = 0; j < 4; j++) { sc1[i][j] = 0.f; sc2[i][j] = 0.f; }

#pragma unroll
        for (int dc = 0; dc < 4; dc++) {
            const int ar = wid*16 + g4;
            const int ac = dc*16 + t4*2;
            uint32_t a1h[4], a1l[4], a2h[4], a2l[4];
            a1h[0] = *(const uint32_t*)&sb[TQ1H + ar*AP + ac];
            a1h[1] = *(const uint32_t*)&sb[TQ1H + (ar+8)*AP + ac];
            a1h[2] = *(const uint32_t*)&sb[TQ1H + ar*AP + ac + 8];
            a1h[3] = *(const uint32_t*)&sb[TQ1H + (ar+8)*AP + ac + 8];
            a1l[0] = *(const uint32_t*)&sb[TQ1L + ar*AP + ac];
            a1l[1] = *(const uint32_t*)&sb[TQ1L + (ar+8)*AP + ac];
            a1l[2] = *(const uint32_t*)&sb[TQ1L + ar*AP + ac + 8];
            a1l[3] = *(const uint32_t*)&sb[TQ1L + (ar+8)*AP + ac + 8];
            a2h[0] = *(const uint32_t*)&sb[TQ2H + ar*AP + ac];
            a2h[1] = *(const uint32_t*)&sb[TQ2H + (ar+8)*AP + ac];
            a2h[2] = *(const uint32_t*)&sb[TQ2H + ar*AP + ac + 8];
            a2h[3] = *(const uint32_t*)&sb[TQ2H + (ar+8)*AP + ac + 8];
            a2l[0] = *(const uint32_t*)&sb[TQ2L + ar*AP + ac];
            a2l[1] = *(const uint32_t*)&sb[TQ2L + (ar+8)*AP + ac];
            a2l[2] = *(const uint32_t*)&sb[TQ2L + ar*AP + ac + 8];
            a2l[3] = *(const uint32_t*)&sb[TQ2L + (ar+8)*AP + ac + 8];
#pragma unroll
            for (int nb = 0; nb < 8; nb++) {
                const int bo = (nb*8 + g4)*AP + dc*16 + t4*2;
                uint32_t b1h[2], b1l[2], b2h[2], b2l[2];
                b1h[0] = *(const uint32_t*)&sb[TK1H + bo];
                b1h[1] = *(const uint32_t*)&sb[TK1H + bo + 8];
                b1l[0] = *(const uint32_t*)&sb[TK1L + bo];
                b1l[1] = *(const uint32_t*)&sb[TK1L + bo + 8];
                b2h[0] = *(const uint32_t*)&sb[TK2H + bo];
                b2h[1] = *(const uint32_t*)&sb[TK2H + bo + 8];
                b2l[0] = *(const uint32_t*)&sb[TK2L + bo];
                b2l[1] = *(const uint32_t*)&sb[TK2L + bo + 8];
                MMA_BF16(sc1[nb], a1h, b1h);
                MMA_BF16(sc1[nb], a1l, b1h);
                MMA_BF16(sc1[nb], a1h, b1l);
                MMA_BF16(sc2[nb], a2h, b2h);
                MMA_BF16(sc2[nb], a2l, b2h);
                MMA_BF16(sc2[nb], a2h, b2l);
            }
        }

#pragma unroll
        for (int nb = 0; nb < 8; nb++)
#pragma unroll
            for (int j = 0; j < 4; j++) {
                sc1[nb][j] = fminf(fmaxf(sc1[nb][j]*0.125f, -ATTN_CLIP), ATTN_CLIP);
                sc2[nb][j] = fminf(fmaxf(sc2[nb][j]*0.125f, -ATTN_CLIP), ATTN_CLIP);
            }

        softmax_upd(sc1, m1, l1, oc1);
        softmax_upd(sc2, m2, l2, oc2);

#pragma unroll
        for (int kc = 0; kc < 4; kc++) {
            uint32_t p1h[4], p1l[4], p2h[4], p2l[4];
            p1h[0] = pk2(sc1[2*kc][0],   sc1[2*kc][1]);
            p1h[1] = pk2(sc1[2*kc][2],   sc1[2*kc][3]);
            p1h[2] = pk2(sc1[2*kc+1][0], sc1[2*kc+1][1]);
            p1h[3] = pk2(sc1[2*kc+1][2], sc1[2*kc+1][3]);
            p1l[0] = pk2lo(sc1[2*kc][0],   sc1[2*kc][1],   p1h[0]);
            p1l[1] = pk2lo(sc1[2*kc][2],   sc1[2*kc][3],   p1h[1]);
            p1l[2] = pk2lo(sc1[2*kc+1][0], sc1[2*kc+1][1], p1h[2]);
            p1l[3] = pk2lo(sc1[2*kc+1][2], sc1[2*kc+1][3], p1h[3]);
            p2h[0] = pk2(sc2[2*kc][0],   sc2[2*kc][1]);
            p2h[1] = pk2(sc2[2*kc][2],   sc2[2*kc][3]);
            p2h[2] = pk2(sc2[2*kc+1][0], sc2[2*kc+1][1]);
            p2h[3] = pk2(sc2[2*kc+1][2], sc2[2*kc+1][3]);
            p2l[0] = pk2lo(sc2[2*kc][0],   sc2[2*kc][1],   p2h[0]);
            p2l[1] = pk2lo(sc2[2*kc][2],   sc2[2*kc][3],   p2h[1]);
            p2l[2] = pk2lo(sc2[2*kc+1][0], sc2[2*kc+1][1], p2h[2]);
            p2l[3] = pk2lo(sc2[2*kc+1][2], sc2[2*kc+1][3], p2h[3]);
#pragma unroll
            for (int db = 0; db < 8; db++) {
                const int vo = (db*8 + g4)*AP + kc*16 + t4*2;
                uint32_t bvh[2], bvl[2];
                bvh[0] = *(const uint32_t*)&sb[TVH + vo];
                bvh[1] = *(const uint32_t*)&sb[TVH + vo + 8];
                bvl[0] = *(const uint32_t*)&sb[TVL + vo];
                bvl[1] = *(const uint32_t*)&sb[TVL + vo + 8];
                MMA_BF16(oc1[db], p1h, bvh);
                MMA_BF16(oc1[db], p1l, bvh);
                MMA_BF16(oc1[db], p1h, bvl);
                MMA_BF16(oc2[db], p2h, bvh);
                MMA_BF16(oc2[db], p2l, bvh);
                MMA_BF16(oc2[db], p2h, bvl);
            }
        }
    }

    const float i10 = 1.f/(l1[0]+EPSF), i11 = 1.f/(l1[1]+EPSF);
    const float i20 = 1.f/(l2[0]+EPSF), i21 = 1.f/(l2[1]+EPSF);
    const int r0 = q0 + wid*16 + g4;
    size_t ob0 = ((size_t)b*SEQ + r0)*DIM + (size_t)h*HDIM;
    size_t ob1 = ob0 + (size_t)8*DIM;
#pragma unroll
    for (int db = 0; db < 8; db++) {
        const int c = db*8 + t4*2;
        float v0 = oc1[db][0]*i10 - lam*(oc2[db][0]*i20);
        float v1 = oc1[db][1]*i10 - lam*(oc2[db][1]*i20);
        float v2 = oc1[db][2]*i11 - lam*(oc2[db][2]*i21);
        float v3 = oc1[db][3]*i11 - lam*(oc2[db][3]*i21);
        uint32_t h01 = pk2(v0, v1), h23 = pk2(v2, v3);
        *(uint32_t*)(oHi + ob0 + c) = h01;
        *(uint32_t*)(oLo + ob0 + c) = pk2lo(v0, v1, h01);
        *(uint32_t*)(oHi + ob1 + c) = h23;
        *(uint32_t*)(oLo + ob1 + c) = pk2lo(v2, v3, h23);
    }
}

// ================= launch =================
extern "C" void kernel_launch(void* const* d_in, const int* in_sizes, int n_in,
                              void* d_out, int out_size) {
    const float* x      = (const float*)d_in[0];
    const float* w_qkv  = (const float*)d_in[1];
    const float* lq1    = (const float*)d_in[2];
    const float* lk1    = (const float*)d_in[3];
    const float* lq2    = (const float*)d_in[4];
    const float* lk2    = (const float*)d_in[5];
    const float* w_proj = (const float*)d_in[6];
    const float* b_proj = (const float*)d_in[7];
    const float* gamma1 = (const float*)d_in[8];
    const float* beta1  = (const float*)d_in[9];
    const float* gamma2 = (const float*)d_in[10];
    const float* beta2  = (const float*)d_in[11];
    const float* w1     = (const float*)d_in[12];
    const float* b1     = (const float*)d_in[13];
    const float* w2     = (const float*)d_in[14];
    const float* b2     = (const float*)d_in[15];
    float* out = (float*)d_out;

    float *p_x2;
    __nv_bfloat16 *p_ahi, *p_alo, *p_qhi, *p_qlo, *p_bhi, *p_blo, *p_vthi, *p_vtlo;
    cudaGetSymbolAddress((void**)&p_x2,   g_x2);
    cudaGetSymbolAddress((void**)&p_ahi,  g_ahi);
    cudaGetSymbolAddress((void**)&p_alo,  g_alo);
    cudaGetSymbolAddress((void**)&p_qhi,  g_qhi);
    cudaGetSymbolAddress((void**)&p_qlo,  g_qlo);
    cudaGetSymbolAddress((void**)&p_bhi,  g_bhi);
    cudaGetSymbolAddress((void**)&p_blo,  g_blo);
    cudaGetSymbolAddress((void**)&p_vthi, g_vthi);
    cudaGetSymbolAddress((void**)&p_vtlo, g_vtlo);

    cudaFuncSetAttribute(diff_attn_mma,
                         cudaFuncAttributeMaxDynamicSharedMemorySize, SMEM_ATT);
    cudaFuncSetAttribute(wmma_gemm<2>, cudaFuncAttributeMaxDynamicSharedMemorySize, SMEM_WG);
    cudaFuncSetAttribute(wmma_gemm<4>, cudaFuncAttributeMaxDynamicSharedMemorySize, SMEM_WG);
    cudaFuncSetAttribute(wmma_gemm<5>, cudaFuncAttributeMaxDynamicSharedMemorySize, SMEM_WG);

    // scalars
    reduce_sq_kernel<<<dim3(128, BATCH), 256>>>(x);
    compute_nx_kernel<<<1, 32>>>();
    compute_lam_kernel<<<1, 1>>>(lq1, lk1, lq2, lk2);

    // GRN1 fused split -> a (hi/lo)
    grn_split_kernel<<<(MTOT*DIM)/4/256, 256>>>(x, gamma1, beta1, p_ahi, p_alo);

    // QKV GEMM -> qkv bf16 hi/lo
    transpose_split_kernel<<<dim3(QKVW/32, DIM/32), dim3(32, 8)>>>(w_qkv, p_bhi, p_blo, DIM, QKVW);
    wmma_gemm<4><<<dim3(QKVW/128, MTOT/128), 128, SMEM_WG>>>(
        p_ahi, p_alo, p_bhi, p_blo, nullptr, p_qhi, p_qlo, MTOT, QKVW, DIM, nullptr, nullptr);

    // V transpose -> vt[bh][d][kk]
    vtrans_kernel<<<dim3(SEQ/32, 32, BATCH), dim3(32, 8)>>>(p_qhi, p_qlo, p_vthi, p_vtlo);

    // attention -> o hi/lo (reuses a arrays)
    diff_attn_mma<<<dim3(SEQ/64, NHEADS, BATCH), 128, SMEM_ATT>>>(
        p_qhi, p_qlo, p_vthi, p_vtlo, p_ahi, p_alo);

    // proj + bias + residual(x) -> x2 fp32
    transpose_split_kernel<<<dim3(DIM/32, DIM/32), dim3(32, 8)>>>(w_proj, p_bhi, p_blo, DIM, DIM);
    wmma_gemm<2><<<dim3(DIM/128, MTOT/128), 128, SMEM_WG>>>(
        p_ahi, p_alo, p_bhi, p_blo, p_x2, nullptr, nullptr, MTOT, DIM, DIM, b_proj, x);

    // GRN2 fused split -> a (hi/lo)
    reduce_sq_kernel<<<dim3(128, BATCH), 256>>>(p_x2);
    compute_nx_kernel<<<1, 32>>>();
    grn_split_kernel<<<(MTOT*DIM)/4/256, 256>>>(p_x2, gamma2, beta2, p_ahi, p_alo);

    // FFN1: silu(h2 @ w1 + b1) -> f bf16 hi/lo (into q arrays)
    transpose_split_kernel<<<dim3(MLP/32, DIM/32), dim3(32, 8)>>>(w1, p_bhi, p_blo, DIM, MLP);
    wmma_gemm<5><<<dim3(MLP/128, MTOT/128), 128, SMEM_WG>>>(
        p_ahi, p_alo, p_bhi, p_blo, nullptr, p_qhi, p_qlo, MTOT, MLP, DIM, b1, nullptr);

    // FFN2: f @ w2 + b2 + residual(x2) -> out
    transpose_split_kernel<<<dim3(DIM/32, MLP/32), dim3(32, 8)>>>(w2, p_bhi, p_blo, MLP, DIM);
    wmma_gemm<2><<<dim3(DIM/128, MTOT/128), 128, SMEM_WG>>>(
        p_qhi, p_qlo, p_bhi, p_blo, out, nullptr, nullptr, MTOT, DIM, MLP, b2, p_x2);
}

// round 10
// speedup vs baseline: 1.3302x; 1.3302x over previous
#include <cuda_runtime.h>
#include <cuda_bf16.h>
#include <mma.h>
#include <math.h>
#include <cstdint>

using namespace nvcuda;

#define BATCH 4
#define SEQ 1024
#define DIM 1024
#define NHEADS 16
#define HDIM 64
#define MLP 4096
#define MTOT (BATCH*SEQ)        /* 4096 */
#define QKVW (5*NHEADS*HDIM)    /* 5120 */
#define ATTN_CLIP 100.0f
#define NORM_CLIP 1000.0f
#define EPSF 1e-6f

// ================= scratch =================
__device__ float g_x2 [MTOT*DIM];
__device__ __nv_bfloat16 g_ahi[(size_t)MTOT*MLP];
__device__ __nv_bfloat16 g_alo[(size_t)MTOT*MLP];
__device__ __nv_bfloat16 g_qhi[(size_t)MTOT*QKVW];
__device__ __nv_bfloat16 g_qlo[(size_t)MTOT*QKVW];
__device__ __nv_bfloat16 g_bhi[(size_t)QKVW*DIM];
__device__ __nv_bfloat16 g_blo[(size_t)QKVW*DIM];
__device__ __nv_bfloat16 g_vthi[(size_t)BATCH*NHEADS*HDIM*SEQ];
__device__ __nv_bfloat16 g_vtlo[(size_t)BATCH*NHEADS*HDIM*SEQ];
__device__ float g_part[BATCH*128];
__device__ float g_nx[BATCH];
__device__ float g_lam;

// ================= helpers =================
__device__ __forceinline__ uint32_t smem_u32(const void* p) {
    uint32_t a;
    asm("{ .reg .u64 t; cvta.to.shared.u64 t, %1; cvt.u32.u64 %0, t; }" : "=r"(a) : "l"(p));
    return a;
}
#define CP_ASYNC16(dst, src) \
    asm volatile("cp.async.cg.shared.global [%0], [%1], 16;" :: "r"(dst), "l"(src))
#define CP_COMMIT() asm volatile("cp.async.commit_group;" ::: "memory")
#define CP_WAIT(n)  asm volatile("cp.async.wait_group %0;" :: "n"(n) : "memory")

#define MMA_BF16(d, a, b) \
    asm volatile("mma.sync.aligned.m16n8k16.row.col.f32.bf16.bf16.f32 " \
        "{%0,%1,%2,%3}, {%4,%5,%6,%7}, {%8,%9}, {%0,%1,%2,%3};" \
        : "+f"((d)[0]), "+f"((d)[1]), "+f"((d)[2]), "+f"((d)[3]) \
        : "r"((a)[0]), "r"((a)[1]), "r"((a)[2]), "r"((a)[3]), \
          "r"((b)[0]), "r"((b)[1]))

__device__ __forceinline__ uint32_t pk2(float x, float y) {
    __nv_bfloat162 t = __floats2bfloat162_rn(x, y);
    return *(uint32_t*)&t;
}
__device__ __forceinline__ uint32_t pk2lo(float x, float y, uint32_t hipk) {
    __nv_bfloat162 hp = *(__nv_bfloat162*)&hipk;
    return pk2(x - __bfloat162float(hp.x), y - __bfloat162float(hp.y));
}

// ================= scalar kernels =================
__global__ void reduce_sq_kernel(const float* __restrict__ x) {
    const int b = blockIdx.y, blk = blockIdx.x;
    const int N = SEQ*DIM;
    const int per = N / 128;
    const float* p = x + (size_t)b*N + (size_t)blk*per;
    float s = 0.f;
    for (int i = threadIdx.x; i < per; i += 256) { float v = p[i]; s += v*v; }
    __shared__ float red[8];
    int lane = threadIdx.x & 31, w = threadIdx.x >> 5;
#pragma unroll
    for (int o = 16; o; o >>= 1) s += __shfl_down_sync(0xffffffffu, s, o);
    if (lane == 0) red[w] = s;
    __syncthreads();
    if (w == 0) {
        s = (lane < 8) ? red[lane] : 0.f;
#pragma unroll
        for (int o = 4; o; o >>= 1) s += __shfl_down_sync(0xffffffffu, s, o);
        if (lane == 0) g_part[b*128 + blk] = s;
    }
}

__global__ void compute_nx_kernel() {
    int b = threadIdx.x;
    if (b < BATCH) {
        float s = 0.f;
        for (int i = 0; i < 128; i++) s += g_part[b*128 + i];
        s = fminf(fmaxf(s, EPSF), NORM_CLIP);
        float gx = sqrtf(s);
        float nx = gx / (gx + EPSF);
        nx = fminf(fmaxf(nx, -NORM_CLIP), NORM_CLIP);
        g_nx[b] = nx;
    }
}

__global__ void compute_lam_kernel(const float* __restrict__ lq1, const float* __restrict__ lk1,
                                   const float* __restrict__ lq2, const float* __restrict__ lk2) {
    float s1 = 0.f, s2 = 0.f;
    for (int d = 0; d < HDIM; d++) { s1 += lq1[d]*lk1[d]; s2 += lq2[d]*lk2[d]; }
    s1 = fminf(fmaxf(s1, -10.f), 10.f);
    s2 = fminf(fmaxf(s2, -10.f), 10.f);
    float lam_init = 0.8f - 0.6f*expf(-0.0f);
    float lam = expf(s1) - expf(s2) + lam_init;
    g_lam = fminf(fmaxf(lam, 0.1f), 5.f);
}

// ================= GRN fused with hi/lo split =================
__global__ void grn_split_kernel(const float* __restrict__ x, const float* __restrict__ gamma,
                                 const float* __restrict__ beta,
                                 __nv_bfloat16* __restrict__ hi, __nv_bfloat16* __restrict__ lo) {
    int idx = blockIdx.x*blockDim.x + threadIdx.x;
    int e = idx * 4;
    int b = e >> 20;
    int d = e & (DIM-1);
    float nx = g_nx[b];
    float4 xv = *(const float4*)(x + e);
    float4 gv = *(const float4*)(gamma + d);
    float4 bv = *(const float4*)(beta + d);
    float r0 = gv.x*(xv.x*nx) + bv.x + xv.x;
    float r1 = gv.y*(xv.y*nx) + bv.y + xv.y;
    float r2 = gv.z*(xv.z*nx) + bv.z + xv.z;
    float r3 = gv.w*(xv.w*nx) + bv.w + xv.w;
    uint2 ph, pl;
    ph.x = pk2(r0, r1); ph.y = pk2(r2, r3);
    pl.x = pk2lo(r0, r1, ph.x); pl.y = pk2lo(r2, r3, ph.y);
    *(uint2*)(hi + e) = ph;
    *(uint2*)(lo + e) = pl;
}

// ================= weight transpose + split =================
__global__ void transpose_split_kernel(const float* __restrict__ w,
                                       __nv_bfloat16* __restrict__ thi,
                                       __nv_bfloat16* __restrict__ tlo,
                                       int K, int N) {
    __shared__ float tile[32][33];
    int n0 = blockIdx.x * 32, k0 = blockIdx.y * 32;
    int tx = threadIdx.x, ty = threadIdx.y;
#pragma unroll
    for (int i = 0; i < 4; i++)
        tile[ty + i*8][tx] = w[(size_t)(k0 + ty + i*8)*N + n0 + tx];
    __syncthreads();
#pragma unroll
    for (int i = 0; i < 4; i++) {
        float v = tile[tx][ty + i*8];
        __nv_bfloat16 h = __float2bfloat16(v);
        __nv_bfloat16 l = __float2bfloat16(v - __bfloat162float(h));
        size_t o = (size_t)(n0 + ty + i*8)*K + k0 + tx;
        thi[o] = h; tlo[o] = l;
    }
}

// ================= V transpose =================
__global__ void vtrans_kernel(const __nv_bfloat16* __restrict__ qHi,
                              const __nv_bfloat16* __restrict__ qLo,
                              __nv_bfloat16* __restrict__ vtHi,
                              __nv_bfloat16* __restrict__ vtLo) {
    __shared__ __nv_bfloat16 th[32][33], tl[32][33];
    const int b = blockIdx.z;
    const int t0 = blockIdx.x * 32;
    const int f0 = blockIdx.y * 32;
    const int tx = threadIdx.x, ty = threadIdx.y;
#pragma unroll
    for (int i = 0; i < 4; i++) {
        size_t src = (size_t)(b*SEQ + t0 + ty + i*8)*QKVW + 4096 + f0 + tx;
        th[ty + i*8][tx] = qHi[src];
        tl[ty + i*8][tx] = qLo[src];
    }
    __syncthreads();
#pragma unroll
    for (int i = 0; i < 4; i++) {
        int f = f0 + ty + i*8;
        int h = f >> 6, d = f & 63;
        size_t dst = ((size_t)(b*NHEADS + h)*HDIM + d)*SEQ + t0 + tx;
        vtHi[dst] = th[tx][ty + i*8];
        vtLo[dst] = tl[tx][ty + i*8];
    }
}

// ================= wmma bf16-split GEMM (round-7 verbatim: 256 thr, 32x64 warp tiles) =================
#define KC 32
#define LDA 40
#define TILE_ELEMS (128*LDA)
#define BUF_ELEMS (4*TILE_ELEMS)
#define SMEM_WG (2*BUF_ELEMS*2)
#define SLD 132

template<int EPI>
__global__ __launch_bounds__(256, 2)
void wmma_gemm(const __nv_bfloat16* __restrict__ Ahi, const __nv_bfloat16* __restrict__ Alo,
               const __nv_bfloat16* __restrict__ Bhi, const __nv_bfloat16* __restrict__ Blo,
               float* __restrict__ C,
               __nv_bfloat16* __restrict__ CHi, __nv_bfloat16* __restrict__ CLo,
               int M, int N, int K,
               const float* __restrict__ bias, const float* __restrict__ res) {
    extern __shared__ char smem_raw[];
    __nv_bfloat16* sm = (__nv_bfloat16*)smem_raw;
    const uint32_t sm_addr = smem_u32(sm);

    const int tid = threadIdx.x;
    const int wid = tid >> 5;
    const int row0 = blockIdx.y * 128;
    const int col0 = blockIdx.x * 128;
    const int wr = (wid >> 1) * 32;
    const int wc = (wid & 1) * 64;

    const __nv_bfloat16* gsrc[4] = {
        Ahi + (size_t)row0*K, Alo + (size_t)row0*K,
        Bhi + (size_t)col0*K, Blo + (size_t)col0*K };

    int u_arr[8], u_row[8], u_col[8];
#pragma unroll
    for (int i = 0; i < 8; i++) {
        int idx = tid + i*256;
        u_arr[i] = idx >> 9;
        int rem = idx & 511;
        u_row[i] = rem >> 2;
        u_col[i] = (rem & 3) * 8;
    }

    auto issue_chunk = [&](int k0, int buf) {
        uint32_t dbase = sm_addr + (uint32_t)buf * (BUF_ELEMS*2);
#pragma unroll
        for (int i = 0; i < 8; i++) {
            const __nv_bfloat16* src = gsrc[u_arr[i]] + (size_t)u_row[i]*K + k0 + u_col[i];
            uint32_t dst = dbase + (uint32_t)(u_arr[i]*TILE_ELEMS + u_row[i]*LDA + u_col[i]) * 2;
            CP_ASYNC16(dst, src);
        }
        CP_COMMIT();
    };

    wmma::fragment<wmma::accumulator, 16, 16, 16, float> acc[2][4];
#pragma unroll
    for (int i = 0; i < 2; i++)
#pragma unroll
        for (int j = 0; j < 4; j++) wmma::fill_fragment(acc[i][j], 0.f);

    const int nch = K / KC;
    issue_chunk(0, 0);

    for (int ch = 0; ch < nch; ch++) {
        const int cur = ch & 1;
        if (ch + 1 < nch) { issue_chunk((ch+1)*KC, cur ^ 1); CP_WAIT(1); }
        else              { CP_WAIT(0); }
        __syncthreads();

        const __nv_bfloat16* b0 = sm + cur * BUF_ELEMS;
        const __nv_bfloat16* tAhi = b0 + 0*TILE_ELEMS + wr*LDA;
        const __nv_bfloat16* tAlo = b0 + 1*TILE_ELEMS + wr*LDA;
        const __nv_bfloat16* tBhi = b0 + 2*TILE_ELEMS + wc*LDA;
        const __nv_bfloat16* tBlo = b0 + 3*TILE_ELEMS + wc*LDA;

#pragma unroll
        for (int ks = 0; ks < 2; ks++) {
            wmma::fragment<wmma::matrix_a, 16, 16, 16, __nv_bfloat16, wmma::row_major> aH[2], aL[2];
            wmma::fragment<wmma::matrix_b, 16, 16, 16, __nv_bfloat16, wmma::col_major> bF[4];
            const int ko = ks * 16;
#pragma unroll
            for (int i = 0; i < 2; i++)
                wmma::load_matrix_sync(aH[i], tAhi + i*16*LDA + ko, LDA);
#pragma unroll
            for (int j = 0; j < 4; j++)
                wmma::load_matrix_sync(bF[j], tBhi + j*16*LDA + ko, LDA);
#pragma unroll
            for (int i = 0; i < 2; i++)
#pragma unroll
                for (int j = 0; j < 4; j++)
                    wmma::mma_sync(acc[i][j], aH[i], bF[j], acc[i][j]);
#pragma unroll
            for (int i = 0; i < 2; i++)
                wmma::load_matrix_sync(aL[i], tAlo + i*16*LDA + ko, LDA);
#pragma unroll
            for (int i = 0; i < 2; i++)
#pragma unroll
                for (int j = 0; j < 4; j++)
                    wmma::mma_sync(acc[i][j], aL[i], bF[j], acc[i][j]);
#pragma unroll
            for (int j = 0; j < 4; j++)
                wmma::load_matrix_sync(bF[j], tBlo + j*16*LDA + ko, LDA);
#pragma unroll
            for (int i = 0; i < 2; i++)
#pragma unroll
                for (int j = 0; j < 4; j++)
                    wmma::mma_sync(acc[i][j], aH[i], bF[j], acc[i][j]);
        }
        __syncthreads();
    }

    float* stage = (float*)smem_raw;
#pragma unroll
    for (int i = 0; i < 2; i++)
#pragma unroll
        for (int j = 0; j < 4; j++)
            wmma::store_matrix_sync(stage + (wr + i*16)*SLD + wc + j*16,
                                    acc[i][j], SLD, wmma::mem_row_major);
    __syncthreads();

    const int r = tid >> 1;
    const int c0 = (tid & 1) * 64;
    const int row = row0 + r;

    if (EPI == 2) {
        size_t obase = (size_t)row*N + col0 + c0;
#pragma unroll
        for (int j = 0; j < 16; j++) {
            float4 v = *(float4*)(stage + r*SLD + c0 + j*4);
            float4 w;
            float* vi = (float*)&v; float* wi = (float*)&w;
#pragma unroll
            for (int q = 0; q < 4; q++)
                wi[q] = vi[q] + bias[col0 + c0 + j*4 + q] + res[obase + j*4 + q];
            *(float4*)(C + obase + j*4) = w;
        }
    } else {
        __nv_bfloat16* dh = CHi + (size_t)row*N + col0 + c0;
        __nv_bfloat16* dl = CLo + (size_t)row*N + col0 + c0;
#pragma unroll
        for (int j = 0; j < 8; j++) {
            float t[8];
#pragma unroll
            for (int q = 0; q < 8; q++) {
                float v = stage[r*SLD + c0 + j*8 + q];
                if (EPI == 5) {
                    v += bias[col0 + c0 + j*8 + q];
                    v = v / (1.f + __expf(-v));
                }
                t[q] = v;
            }
            uint4 ph, pl;
            uint32_t* phi = (uint32_t*)&ph;
            uint32_t* pli = (uint32_t*)&pl;
#pragma unroll
            for (int q = 0; q < 4; q++) {
                phi[q] = pk2(t[2*q], t[2*q+1]);
                pli[q] = pk2lo(t[2*q], t[2*q+1], phi[q]);
            }
            *(uint4*)(dh + j*8) = ph;
            *(uint4*)(dl + j*8) = pl;
        }
    }
}

// ================= tensor-core differential flash attention: Q-tile 128, 256 threads =================
// 8 warps x 16 query rows. K-tile 64. K/V tiles serve 128 queries (2x reuse vs r7).
#define AP 72
#define TQ1H 0
#define TQ1L 9216
#define TQ2H 18432
#define TQ2L 27648
#define TK1H 36864
#define TK1L 41472
#define TK2H 46080
#define TK2L 50688
#define TVH  55296
#define TVL  59904
#define SMEM_ATT (64512*2)

__device__ __forceinline__ void softmax_upd(float sc[8][4], float m[2], float l[2],
                                            float oc[8][4]) {
    float t0 = -1e30f, t1 = -1e30f;
#pragma unroll
    for (int nb = 0; nb < 8; nb++) {
        t0 = fmaxf(t0, fmaxf(sc[nb][0], sc[nb][1]));
        t1 = fmaxf(t1, fmaxf(sc[nb][2], sc[nb][3]));
    }
    t0 = fmaxf(t0, __shfl_xor_sync(0xffffffffu, t0, 1));
    t0 = fmaxf(t0, __shfl_xor_sync(0xffffffffu, t0, 2));
    t1 = fmaxf(t1, __shfl_xor_sync(0xffffffffu, t1, 1));
    t1 = fmaxf(t1, __shfl_xor_sync(0xffffffffu, t1, 2));
    float nm0 = fmaxf(m[0], t0), nm1 = fmaxf(m[1], t1);
    float c0 = __expf(m[0] - nm0), c1 = __expf(m[1] - nm1);
    float s0 = 0.f, s1 = 0.f;
#pragma unroll
    for (int nb = 0; nb < 8; nb++) {
        float p0 = __expf(sc[nb][0] - nm0); sc[nb][0] = p0; s0 += p0;
        float p1 = __expf(sc[nb][1] - nm0); sc[nb][1] = p1; s0 += p1;
        float p2 = __expf(sc[nb][2] - nm1); sc[nb][2] = p2; s1 += p2;
        float p3 = __expf(sc[nb][3] - nm1); sc[nb][3] = p3; s1 += p3;
    }
    s0 += __shfl_xor_sync(0xffffffffu, s0, 1);
    s0 += __shfl_xor_sync(0xffffffffu, s0, 2);
    s1 += __shfl_xor_sync(0xffffffffu, s1, 1);
    s1 += __shfl_xor_sync(0xffffffffu, s1, 2);
    l[0] = l[0]*c0 + s0;  l[1] = l[1]*c1 + s1;
#pragma unroll
    for (int db = 0; db < 8; db++) {
        oc[db][0] *= c0; oc[db][1] *= c0;
        oc[db][2] *= c1; oc[db][3] *= c1;
    }
    m[0] = nm0; m[1] = nm1;
}

__global__ __launch_bounds__(256)
void diff_attn_mma(const __nv_bfloat16* __restrict__ qHi, const __nv_bfloat16* __restrict__ qLo,
                   const __nv_bfloat16* __restrict__ vtHi, const __nv_bfloat16* __restrict__ vtLo,
                   __nv_bfloat16* __restrict__ oHi, __nv_bfloat16* __restrict__ oLo) {
    extern __shared__ __nv_bfloat16 sb[];
    const uint32_t smb = smem_u32(sb);
    const int tid = threadIdx.x;
    const int wid = tid >> 5, lane = tid & 31;
    const int g4 = lane >> 2, t4 = lane & 3;
    const int qt = blockIdx.x, h = blockIdx.y, b = blockIdx.z;
    const int q0 = qt * 128;
    const float lam = g_lam;

    // rows-parametrized cp.async tile loader (row pitch 144B in smem)
    auto ld_tile128 = [&](int tileEls, const __nv_bfloat16* src, int rowStride) {
#pragma unroll
        for (int i = 0; i < 4; i++) {
            int idx = tid + i*256;              // 1024 units
            int r = idx >> 3, c8 = idx & 7;
            CP_ASYNC16(smb + (uint32_t)tileEls*2 + r*144 + c8*16,
                       src + (size_t)r*rowStride + c8*8);
        }
    };
    auto ld_tile64 = [&](int tileEls, const __nv_bfloat16* src, int rowStride) {
#pragma unroll
        for (int i = 0; i < 2; i++) {
            int idx = tid + i*256;              // 512 units
            int r = idx >> 3, c8 = idx & 7;
            CP_ASYNC16(smb + (uint32_t)tileEls*2 + r*144 + c8*16,
                       src + (size_t)r*rowStride + c8*8);
        }
    };

    // Q tiles: 128 rows each
    {
        const size_t qb = (size_t)(b*SEQ + q0)*QKVW + h*HDIM;
        ld_tile128(TQ1H, qHi + qb,        QKVW);
        ld_tile128(TQ1L, qLo + qb,        QKVW);
        ld_tile128(TQ2H, qHi + qb + 1024, QKVW);
        ld_tile128(TQ2L, qLo + qb + 1024, QKVW);
        CP_COMMIT();
    }

    float oc1[8][4], oc2[8][4];
#pragma unroll
    for (int i = 0; i < 8; i++)
#pragma unroll
        for (int j = 0; j < 4; j++) { oc1[i][j] = 0.f; oc2[i][j] = 0.f; }
    float m1[2] = {-1e30f, -1e30f}, l1[2] = {0.f, 0.f};
    float m2[2] = {-1e30f, -1e30f}, l2[2] = {0.f, 0.f};

    for (int kt = 0; kt < 16; kt++) {
        __syncthreads();
        const int k0 = kt * 64;
        {
            const size_t kb = (size_t)(b*SEQ + k0)*QKVW + h*HDIM;
            const size_t vb = ((size_t)(b*NHEADS + h)*HDIM)*SEQ + k0;
            ld_tile64(TK1H, qHi + kb + 2048, QKVW);
            ld_tile64(TK1L, qLo + kb + 2048, QKVW);
            ld_tile64(TK2H, qHi + kb + 3072, QKVW);
            ld_tile64(TK2L, qLo + kb + 3072, QKVW);
            ld_tile64(TVH,  vtHi + vb, SEQ);
            ld_tile64(TVL,  vtLo + vb, SEQ);
            CP_COMMIT();
        }
        CP_WAIT(0);
        __syncthreads();

        float sc1[8][4], sc2[8][4];
#pragma unroll
        for (int i = 0; i < 8; i++)
#pragma unroll
            for (int j = 0; j < 4; j++) { sc1[i][j] = 0.f; sc2[i][j] = 0.f; }

#pragma unroll
        for (int dc = 0; dc < 4; dc++) {
            const int ar = wid*16 + g4;        // 0..127
            const int ac = dc*16 + t4*2;
            uint32_t a1h[4], a1l[4], a2h[4], a2l[4];
            a1h[0] = *(const uint32_t*)&sb[TQ1H + ar*AP + ac];
            a1h[1] = *(const uint32_t*)&sb[TQ1H + (ar+8)*AP + ac];
            a1h[2] = *(const uint32_t*)&sb[TQ1H + ar*AP + ac + 8];
            a1h[3] = *(const uint32_t*)&sb[TQ1H + (ar+8)*AP + ac + 8];
            a1l[0] = *(const uint32_t*)&sb[TQ1L + ar*AP + ac];
            a1l[1] = *(const uint32_t*)&sb[TQ1L + (ar+8)*AP + ac];
            a1l[2] = *(const uint32_t*)&sb[TQ1L + ar*AP + ac + 8];
            a1l[3] = *(const uint32_t*)&sb[TQ1L + (ar+8)*AP + ac + 8];
            a2h[0] = *(const uint32_t*)&sb[TQ2H + ar*AP + ac];
            a2h[1] = *(const uint32_t*)&sb[TQ2H + (ar+8)*AP + ac];
            a2h[2] = *(const uint32_t*)&sb[TQ2H + ar*AP + ac + 8];
            a2h[3] = *(const uint32_t*)&sb[TQ2H + (ar+8)*AP + ac + 8];
            a2l[0] = *(const uint32_t*)&sb[TQ2L + ar*AP + ac];
            a2l[1] = *(const uint32_t*)&sb[TQ2L + (ar+8)*AP + ac];
            a2l[2] = *(const uint32_t*)&sb[TQ2L + ar*AP + ac + 8];
            a2l[3] = *(const uint32_t*)&sb[TQ2L + (ar+8)*AP + ac + 8];
#pragma unroll
            for (int nb = 0; nb < 8; nb++) {
                const int bo = (nb*8 + g4)*AP + dc*16 + t4*2;
                uint32_t b1h[2], b1l[2], b2h[2], b2l[2];
                b1h[0] = *(const uint32_t*)&sb[TK1H + bo];
                b1h[1] = *(const uint32_t*)&sb[TK1H + bo + 8];
                b1l[0] = *(const uint32_t*)&sb[TK1L + bo];
                b1l[1] = *(const uint32_t*)&sb[TK1L + bo + 8];
                b2h[0] = *(const uint32_t*)&sb[TK2H + bo];
                b2h[1] = *(const uint32_t*)&sb[TK2H + bo + 8];
                b2l[0] = *(const uint32_t*)&sb[TK2L + bo];
                b2l[1] = *(const uint32_t*)&sb[TK2L + bo + 8];
                MMA_BF16(sc1[nb], a1h, b1h);
                MMA_BF16(sc1[nb], a1l, b1h);
                MMA_BF16(sc1[nb], a1h, b1l);
                MMA_BF16(sc2[nb], a2h, b2h);
                MMA_BF16(sc2[nb], a2l, b2h);
                MMA_BF16(sc2[nb], a2h, b2l);
            }
        }

#pragma unroll
        for (int nb = 0; nb < 8; nb++)
#pragma unroll
            for (int j = 0; j < 4; j++) {
                sc1[nb][j] = fminf(fmaxf(sc1[nb][j]*0.125f, -ATTN_CLIP), ATTN_CLIP);
                sc2[nb][j] = fminf(fmaxf(sc2[nb][j]*0.125f, -ATTN_CLIP), ATTN_CLIP);
            }

        softmax_upd(sc1, m1, l1, oc1);
        softmax_upd(sc2, m2, l2, oc2);

#pragma unroll
        for (int kc = 0; kc < 4; kc++) {
            uint32_t p1h[4], p1l[4], p2h[4], p2l[4];
            p1h[0] = pk2(sc1[2*kc][0],   sc1[2*kc][1]);
            p1h[1] = pk2(sc1[2*kc][2],   sc1[2*kc][3]);
            p1h[2] = pk2(sc1[2*kc+1][0], sc1[2*kc+1][1]);
            p1h[3] = pk2(sc1[2*kc+1][2], sc1[2*kc+1][3]);
            p1l[0] = pk2lo(sc1[2*kc][0],   sc1[2*kc][1],   p1h[0]);
            p1l[1] = pk2lo(sc1[2*kc][2],   sc1[2*kc][3],   p1h[1]);
            p1l[2] = pk2lo(sc1[2*kc+1][0], sc1[2*kc+1][1], p1h[2]);
            p1l[3] = pk2lo(sc1[2*kc+1][2], sc1[2*kc+1][3], p1h[3]);
            p2h[0] = pk2(sc2[2*kc][0],   sc2[2*kc][1]);
            p2h[1] = pk2(sc2[2*kc][2],   sc2[2*kc][3]);
            p2h[2] = pk2(sc2[2*kc+1][0], sc2[2*kc+1][1]);
            p2h[3] = pk2(sc2[2*kc+1][2], sc2[2*kc+1][3]);
            p2l[0] = pk2lo(sc2[2*kc][0],   sc2[2*kc][1],   p2h[0]);
            p2l[1] = pk2lo(sc2[2*kc][2],   sc2[2*kc][3],   p2h[1]);
            p2l[2] = pk2lo(sc2[2*kc+1][0], sc2[2*kc+1][1], p2h[2]);
            p2l[3] = pk2lo(sc2[2*kc+1][2], sc2[2*kc+1][3], p2h[3]);
#pragma unroll
            for (int db = 0; db < 8; db++) {
                const int vo = (db*8 + g4)*AP + kc*16 + t4*2;
                uint32_t bvh[2], bvl[2];
                bvh[0] = *(const uint32_t*)&sb[TVH + vo];
                bvh[1] = *(const uint32_t*)&sb[TVH + vo + 8];
                bvl[0] = *(const uint32_t*)&sb[TVL + vo];
                bvl[1] = *(const uint32_t*)&sb[TVL + vo + 8];
                MMA_BF16(oc1[db], p1h, bvh);
                MMA_BF16(oc1[db], p1l, bvh);
                MMA_BF16(oc1[db], p1h, bvl);
                MMA_BF16(oc2[db], p2h, bvh);
                MMA_BF16(oc2[db], p2l, bvh);
                MMA_BF16(oc2[db], p2h, bvl);
            }
        }
    }

    const float i10 = 1.f/(l1[0]+EPSF), i11 = 1.f/(l1[1]+EPSF);
    const float i20 = 1.f/(l2[0]+EPSF), i21 = 1.f/(l2[1]+EPSF);
    const int r0 = q0 + wid*16 + g4;
    size_t ob0 = ((size_t)b*SEQ + r0)*DIM + (size_t)h*HDIM;
    size_t ob1 = ob0 + (size_t)8*DIM;
#pragma unroll
    for (int db = 0; db < 8; db++) {
        const int c = db*8 + t4*2;
        float v0 = oc1[db][0]*i10 - lam*(oc2[db][0]*i20);
        float v1 = oc1[db][1]*i10 - lam*(oc2[db][1]*i20);
        float v2 = oc1[db][2]*i11 - lam*(oc2[db][2]*i21);
        float v3 = oc1[db][3]*i11 - lam*(oc2[db][3]*i21);
        uint32_t h01 = pk2(v0, v1), h23 = pk2(v2, v3);
        *(uint32_t*)(oHi + ob0 + c) = h01;
        *(uint32_t*)(oLo + ob0 + c) = pk2lo(v0, v1, h01);
        *(uint32_t*)(oHi + ob1 + c) = h23;
        *(uint32_t*)(oLo + ob1 + c) = pk2lo(v2, v3, h23);
    }
}

// ================= launch =================
extern "C" void kernel_launch(void* const* d_in, const int* in_sizes, int n_in,
                              void* d_out, int out_size) {
    const float* x      = (const float*)d_in[0];
    const float* w_qkv  = (const float*)d_in[1];
    const float* lq1    = (const float*)d_in[2];
    const float* lk1    = (const float*)d_in[3];
    const float* lq2    = (const float*)d_in[4];
    const float* lk2    = (const float*)d_in[5];
    const float* w_proj = (const float*)d_in[6];
    const float* b_proj = (const float*)d_in[7];
    const float* gamma1 = (const float*)d_in[8];
    const float* beta1  = (const float*)d_in[9];
    const float* gamma2 = (const float*)d_in[10];
    const float* beta2  = (const float*)d_in[11];
    const float* w1     = (const float*)d_in[12];
    const float* b1     = (const float*)d_in[13];
    const float* w2     = (const float*)d_in[14];
    const float* b2     = (const float*)d_in[15];
    float* out = (float*)d_out;

    float *p_x2;
    __nv_bfloat16 *p_ahi, *p_alo, *p_qhi, *p_qlo, *p_bhi, *p_blo, *p_vthi, *p_vtlo;
    cudaGetSymbolAddress((void**)&p_x2,   g_x2);
    cudaGetSymbolAddress((void**)&p_ahi,  g_ahi);
    cudaGetSymbolAddress((void**)&p_alo,  g_alo);
    cudaGetSymbolAddress((void**)&p_qhi,  g_qhi);
    cudaGetSymbolAddress((void**)&p_qlo,  g_qlo);
    cudaGetSymbolAddress((void**)&p_bhi,  g_bhi);
    cudaGetSymbolAddress((void**)&p_blo,  g_blo);
    cudaGetSymbolAddress((void**)&p_vthi, g_vthi);
    cudaGetSymbolAddress((void**)&p_vtlo, g_vtlo);

    cudaFuncSetAttribute(diff_attn_mma,
                         cudaFuncAttributeMaxDynamicSharedMemorySize, SMEM_ATT);
    cudaFuncSetAttribute(wmma_gemm<2>, cudaFuncAttributeMaxDynamicSharedMemorySize, SMEM_WG);
    cudaFuncSetAttribute(wmma_gemm<4>, cudaFuncAttributeMaxDynamicSharedMemorySize, SMEM_WG);
    cudaFuncSetAttribute(wmma_gemm<5>, cudaFuncAttributeMaxDynamicSharedMemorySize, SMEM_WG);

    // scalars
    reduce_sq_kernel<<<dim3(128, BATCH), 256>>>(x);
    compute_nx_kernel<<<1, 32>>>();
    compute_lam_kernel<<<1, 1>>>(lq1, lk1, lq2, lk2);

    // GRN1 fused split -> a (hi/lo)
    grn_split_kernel<<<(MTOT*DIM)/4/256, 256>>>(x, gamma1, beta1, p_ahi, p_alo);

    // QKV GEMM -> qkv bf16 hi/lo
    transpose_split_kernel<<<dim3(QKVW/32, DIM/32), dim3(32, 8)>>>(w_qkv, p_bhi, p_blo, DIM, QKVW);
    wmma_gemm<4><<<dim3(QKVW/128, MTOT/128), 256, SMEM_WG>>>(
        p_ahi, p_alo, p_bhi, p_blo, nullptr, p_qhi, p_qlo, MTOT, QKVW, DIM, nullptr, nullptr);

    // V transpose -> vt[bh][d][kk]
    vtrans_kernel<<<dim3(SEQ/32, 32, BATCH), dim3(32, 8)>>>(p_qhi, p_qlo, p_vthi, p_vtlo);

    // attention (Q-tile 128) -> o hi/lo (reuses a arrays)
    diff_attn_mma<<<dim3(SEQ/128, NHEADS, BATCH), 256, SMEM_ATT>>>(
        p_qhi, p_qlo, p_vthi, p_vtlo, p_ahi, p_alo);

    // proj + bias + residual(x) -> x2 fp32
    transpose_split_kernel<<<dim3(DIM/32, DIM/32), dim3(32, 8)>>>(w_proj, p_bhi, p_blo, DIM, DIM);
    wmma_gemm<2><<<dim3(DIM/128, MTOT/128), 256, SMEM_WG>>>(
        p_ahi, p_alo, p_bhi, p_blo, p_x2, nullptr, nullptr, MTOT, DIM, DIM, b_proj, x);

    // GRN2 fused split -> a (hi/lo)
    reduce_sq_kernel<<<dim3(128, BATCH), 256>>>(p_x2);
    compute_nx_kernel<<<1, 32>>>();
    grn_split_kernel<<<(MTOT*DIM)/4/256, 256>>>(p_x2, gamma2, beta2, p_ahi, p_alo);

    // FFN1: silu(h2 @ w1 + b1) -> f bf16 hi/lo (into q arrays)
    transpose_split_kernel<<<dim3(MLP/32, DIM/32), dim3(32, 8)>>>(w1, p_bhi, p_blo, DIM, MLP);
    wmma_gemm<5><<<dim3(MLP/128, MTOT/128), 256, SMEM_WG>>>(
        p_ahi, p_alo, p_bhi, p_blo, nullptr, p_qhi, p_qlo, MTOT, MLP, DIM, b1, nullptr);

    // FFN2: f @ w2 + b2 + residual(x2) -> out
    transpose_split_kernel<<<dim3(DIM/32, MLP/32), dim3(32, 8)>>>(w2, p_bhi, p_blo, MLP, DIM);
    wmma_gemm<2><<<dim3(DIM/128, MTOT/128), 256, SMEM_WG>>>(
        p_qhi, p_qlo, p_bhi, p_blo, out, nullptr, nullptr, MTOT, DIM, MLP, b2, p_x2);
}

// round 11
// speedup vs baseline: 1.3810x; 1.0381x over previous
#include <cuda_runtime.h>
#include <cuda_bf16.h>
#include <mma.h>
#include <math.h>
#include <cstdint>

using namespace nvcuda;

#define BATCH 4
#define SEQ 1024
#define DIM 1024
#define NHEADS 16
#define HDIM 64
#define MLP 4096
#define MTOT (BATCH*SEQ)        /* 4096 */
#define QKVW (5*NHEADS*HDIM)    /* 5120 */
#define ATTN_CLIP 100.0f
#define NORM_CLIP 1000.0f
#define EPSF 1e-6f

// ================= scratch =================
__device__ float g_x2 [MTOT*DIM];
__device__ __nv_bfloat16 g_ahi[(size_t)MTOT*MLP];
__device__ __nv_bfloat16 g_alo[(size_t)MTOT*MLP];
__device__ __nv_bfloat16 g_qhi[(size_t)MTOT*QKVW];
__device__ __nv_bfloat16 g_qlo[(size_t)MTOT*QKVW];
__device__ __nv_bfloat16 g_bhi[(size_t)QKVW*DIM];
__device__ __nv_bfloat16 g_blo[(size_t)QKVW*DIM];
__device__ __nv_bfloat16 g_vthi[(size_t)BATCH*NHEADS*HDIM*SEQ];
__device__ __nv_bfloat16 g_vtlo[(size_t)BATCH*NHEADS*HDIM*SEQ];
__device__ float g_part[BATCH*128];
__device__ float g_nx[BATCH];
__device__ float g_lam;

// ================= helpers =================
__device__ __forceinline__ uint32_t smem_u32(const void* p) {
    uint32_t a;
    asm("{ .reg .u64 t; cvta.to.shared.u64 t, %1; cvt.u32.u64 %0, t; }" : "=r"(a) : "l"(p));
    return a;
}
#define CP_ASYNC16(dst, src) \
    asm volatile("cp.async.cg.shared.global [%0], [%1], 16;" :: "r"(dst), "l"(src))
#define CP_COMMIT() asm volatile("cp.async.commit_group;" ::: "memory")
#define CP_WAIT(n)  asm volatile("cp.async.wait_group %0;" :: "n"(n) : "memory")

#define MMA_BF16(d, a, b) \
    asm volatile("mma.sync.aligned.m16n8k16.row.col.f32.bf16.bf16.f32 " \
        "{%0,%1,%2,%3}, {%4,%5,%6,%7}, {%8,%9}, {%0,%1,%2,%3};" \
        : "+f"((d)[0]), "+f"((d)[1]), "+f"((d)[2]), "+f"((d)[3]) \
        : "r"((a)[0]), "r"((a)[1]), "r"((a)[2]), "r"((a)[3]), \
          "r"((b)[0]), "r"((b)[1]))

__device__ __forceinline__ uint32_t pk2(float x, float y) {
    __nv_bfloat162 t = __floats2bfloat162_rn(x, y);
    return *(uint32_t*)&t;
}
__device__ __forceinline__ uint32_t pk2lo(float x, float y, uint32_t hipk) {
    __nv_bfloat162 hp = *(__nv_bfloat162*)&hipk;
    return pk2(x - __bfloat162float(hp.x), y - __bfloat162float(hp.y));
}

// ================= scalar kernels =================
__global__ void reduce_sq_kernel(const float* __restrict__ x) {
    const int b = blockIdx.y, blk = blockIdx.x;
    const int N = SEQ*DIM;
    const int per = N / 128;
    const float* p = x + (size_t)b*N + (size_t)blk*per;
    float s = 0.f;
    for (int i = threadIdx.x; i < per; i += 256) { float v = p[i]; s += v*v; }
    __shared__ float red[8];
    int lane = threadIdx.x & 31, w = threadIdx.x >> 5;
#pragma unroll
    for (int o = 16; o; o >>= 1) s += __shfl_down_sync(0xffffffffu, s, o);
    if (lane == 0) red[w] = s;
    __syncthreads();
    if (w == 0) {
        s = (lane < 8) ? red[lane] : 0.f;
#pragma unroll
        for (int o = 4; o; o >>= 1) s += __shfl_down_sync(0xffffffffu, s, o);
        if (lane == 0) g_part[b*128 + blk] = s;
    }
}

__global__ void compute_nx_kernel() {
    int b = threadIdx.x;
    if (b < BATCH) {
        float s = 0.f;
        for (int i = 0; i < 128; i++) s += g_part[b*128 + i];
        s = fminf(fmaxf(s, EPSF), NORM_CLIP);
        float gx = sqrtf(s);
        float nx = gx / (gx + EPSF);
        nx = fminf(fmaxf(nx, -NORM_CLIP), NORM_CLIP);
        g_nx[b] = nx;
    }
}

__global__ void compute_lam_kernel(const float* __restrict__ lq1, const float* __restrict__ lk1,
                                   const float* __restrict__ lq2, const float* __restrict__ lk2) {
    float s1 = 0.f, s2 = 0.f;
    for (int d = 0; d < HDIM; d++) { s1 += lq1[d]*lk1[d]; s2 += lq2[d]*lk2[d]; }
    s1 = fminf(fmaxf(s1, -10.f), 10.f);
    s2 = fminf(fmaxf(s2, -10.f), 10.f);
    float lam_init = 0.8f - 0.6f*expf(-0.0f);
    float lam = expf(s1) - expf(s2) + lam_init;
    g_lam = fminf(fmaxf(lam, 0.1f), 5.f);
}

// ================= GRN fused with hi/lo split =================
__global__ void grn_split_kernel(const float* __restrict__ x, const float* __restrict__ gamma,
                                 const float* __restrict__ beta,
                                 __nv_bfloat16* __restrict__ hi, __nv_bfloat16* __restrict__ lo) {
    int idx = blockIdx.x*blockDim.x + threadIdx.x;
    int e = idx * 4;
    int b = e >> 20;
    int d = e & (DIM-1);
    float nx = g_nx[b];
    float4 xv = *(const float4*)(x + e);
    float4 gv = *(const float4*)(gamma + d);
    float4 bv = *(const float4*)(beta + d);
    float r0 = gv.x*(xv.x*nx) + bv.x + xv.x;
    float r1 = gv.y*(xv.y*nx) + bv.y + xv.y;
    float r2 = gv.z*(xv.z*nx) + bv.z + xv.z;
    float r3 = gv.w*(xv.w*nx) + bv.w + xv.w;
    uint2 ph, pl;
    ph.x = pk2(r0, r1); ph.y = pk2(r2, r3);
    pl.x = pk2lo(r0, r1, ph.x); pl.y = pk2lo(r2, r3, ph.y);
    *(uint2*)(hi + e) = ph;
    *(uint2*)(lo + e) = pl;
}

// ================= weight transpose + split =================
__global__ void transpose_split_kernel(const float* __restrict__ w,
                                       __nv_bfloat16* __restrict__ thi,
                                       __nv_bfloat16* __restrict__ tlo,
                                       int K, int N) {
    __shared__ float tile[32][33];
    int n0 = blockIdx.x * 32, k0 = blockIdx.y * 32;
    int tx = threadIdx.x, ty = threadIdx.y;
#pragma unroll
    for (int i = 0; i < 4; i++)
        tile[ty + i*8][tx] = w[(size_t)(k0 + ty + i*8)*N + n0 + tx];
    __syncthreads();
#pragma unroll
    for (int i = 0; i < 4; i++) {
        float v = tile[tx][ty + i*8];
        __nv_bfloat16 h = __float2bfloat16(v);
        __nv_bfloat16 l = __float2bfloat16(v - __bfloat162float(h));
        size_t o = (size_t)(n0 + ty + i*8)*K + k0 + tx;
        thi[o] = h; tlo[o] = l;
    }
}

// ================= V transpose =================
__global__ void vtrans_kernel(const __nv_bfloat16* __restrict__ qHi,
                              const __nv_bfloat16* __restrict__ qLo,
                              __nv_bfloat16* __restrict__ vtHi,
                              __nv_bfloat16* __restrict__ vtLo) {
    __shared__ __nv_bfloat16 th[32][33], tl[32][33];
    const int b = blockIdx.z;
    const int t0 = blockIdx.x * 32;
    const int f0 = blockIdx.y * 32;
    const int tx = threadIdx.x, ty = threadIdx.y;
#pragma unroll
    for (int i = 0; i < 4; i++) {
        size_t src = (size_t)(b*SEQ + t0 + ty + i*8)*QKVW + 4096 + f0 + tx;
        th[ty + i*8][tx] = qHi[src];
        tl[ty + i*8][tx] = qLo[src];
    }
    __syncthreads();
#pragma unroll
    for (int i = 0; i < 4; i++) {
        int f = f0 + ty + i*8;
        int h = f >> 6, d = f & 63;
        size_t dst = ((size_t)(b*NHEADS + h)*HDIM + d)*SEQ + t0 + tx;
        vtHi[dst] = th[tx][ty + i*8];
        vtLo[dst] = tl[tx][ty + i*8];
    }
}

// ================= wmma bf16-split GEMM (round-7 verbatim) =================
#define KC 32
#define LDA 40
#define TILE_ELEMS (128*LDA)
#define BUF_ELEMS (4*TILE_ELEMS)
#define SMEM_WG (2*BUF_ELEMS*2)
#define SLD 132

template<int EPI>
__global__ __launch_bounds__(256, 2)
void wmma_gemm(const __nv_bfloat16* __restrict__ Ahi, const __nv_bfloat16* __restrict__ Alo,
               const __nv_bfloat16* __restrict__ Bhi, const __nv_bfloat16* __restrict__ Blo,
               float* __restrict__ C,
               __nv_bfloat16* __restrict__ CHi, __nv_bfloat16* __restrict__ CLo,
               int M, int N, int K,
               const float* __restrict__ bias, const float* __restrict__ res) {
    extern __shared__ char smem_raw[];
    __nv_bfloat16* sm = (__nv_bfloat16*)smem_raw;
    const uint32_t sm_addr = smem_u32(sm);

    const int tid = threadIdx.x;
    const int wid = tid >> 5;
    const int row0 = blockIdx.y * 128;
    const int col0 = blockIdx.x * 128;
    const int wr = (wid >> 1) * 32;
    const int wc = (wid & 1) * 64;

    const __nv_bfloat16* gsrc[4] = {
        Ahi + (size_t)row0*K, Alo + (size_t)row0*K,
        Bhi + (size_t)col0*K, Blo + (size_t)col0*K };

    int u_arr[8], u_row[8], u_col[8];
#pragma unroll
    for (int i = 0; i < 8; i++) {
        int idx = tid + i*256;
        u_arr[i] = idx >> 9;
        int rem = idx & 511;
        u_row[i] = rem >> 2;
        u_col[i] = (rem & 3) * 8;
    }

    auto issue_chunk = [&](int k0, int buf) {
        uint32_t dbase = sm_addr + (uint32_t)buf * (BUF_ELEMS*2);
#pragma unroll
        for (int i = 0; i < 8; i++) {
            const __nv_bfloat16* src = gsrc[u_arr[i]] + (size_t)u_row[i]*K + k0 + u_col[i];
            uint32_t dst = dbase + (uint32_t)(u_arr[i]*TILE_ELEMS + u_row[i]*LDA + u_col[i]) * 2;
            CP_ASYNC16(dst, src);
        }
        CP_COMMIT();
    };

    wmma::fragment<wmma::accumulator, 16, 16, 16, float> acc[2][4];
#pragma unroll
    for (int i = 0; i < 2; i++)
#pragma unroll
        for (int j = 0; j < 4; j++) wmma::fill_fragment(acc[i][j], 0.f);

    const int nch = K / KC;
    issue_chunk(0, 0);

    for (int ch = 0; ch < nch; ch++) {
        const int cur = ch & 1;
        if (ch + 1 < nch) { issue_chunk((ch+1)*KC, cur ^ 1); CP_WAIT(1); }
        else              { CP_WAIT(0); }
        __syncthreads();

        const __nv_bfloat16* b0 = sm + cur * BUF_ELEMS;
        const __nv_bfloat16* tAhi = b0 + 0*TILE_ELEMS + wr*LDA;
        const __nv_bfloat16* tAlo = b0 + 1*TILE_ELEMS + wr*LDA;
        const __nv_bfloat16* tBhi = b0 + 2*TILE_ELEMS + wc*LDA;
        const __nv_bfloat16* tBlo = b0 + 3*TILE_ELEMS + wc*LDA;

#pragma unroll
        for (int ks = 0; ks < 2; ks++) {
            wmma::fragment<wmma::matrix_a, 16, 16, 16, __nv_bfloat16, wmma::row_major> aH[2], aL[2];
            wmma::fragment<wmma::matrix_b, 16, 16, 16, __nv_bfloat16, wmma::col_major> bF[4];
            const int ko = ks * 16;
#pragma unroll
            for (int i = 0; i < 2; i++)
                wmma::load_matrix_sync(aH[i], tAhi + i*16*LDA + ko, LDA);
#pragma unroll
            for (int j = 0; j < 4; j++)
                wmma::load_matrix_sync(bF[j], tBhi + j*16*LDA + ko, LDA);
#pragma unroll
            for (int i = 0; i < 2; i++)
#pragma unroll
                for (int j = 0; j < 4; j++)
                    wmma::mma_sync(acc[i][j], aH[i], bF[j], acc[i][j]);
#pragma unroll
            for (int i = 0; i < 2; i++)
                wmma::load_matrix_sync(aL[i], tAlo + i*16*LDA + ko, LDA);
#pragma unroll
            for (int i = 0; i < 2; i++)
#pragma unroll
                for (int j = 0; j < 4; j++)
                    wmma::mma_sync(acc[i][j], aL[i], bF[j], acc[i][j]);
#pragma unroll
            for (int j = 0; j < 4; j++)
                wmma::load_matrix_sync(bF[j], tBlo + j*16*LDA + ko, LDA);
#pragma unroll
            for (int i = 0; i < 2; i++)
#pragma unroll
                for (int j = 0; j < 4; j++)
                    wmma::mma_sync(acc[i][j], aH[i], bF[j], acc[i][j]);
        }
        __syncthreads();
    }

    float* stage = (float*)smem_raw;
#pragma unroll
    for (int i = 0; i < 2; i++)
#pragma unroll
        for (int j = 0; j < 4; j++)
            wmma::store_matrix_sync(stage + (wr + i*16)*SLD + wc + j*16,
                                    acc[i][j], SLD, wmma::mem_row_major);
    __syncthreads();

    const int r = tid >> 1;
    const int c0 = (tid & 1) * 64;
    const int row = row0 + r;

    if (EPI == 2) {
        size_t obase = (size_t)row*N + col0 + c0;
#pragma unroll
        for (int j = 0; j < 16; j++) {
            float4 v = *(float4*)(stage + r*SLD + c0 + j*4);
            float4 w;
            float* vi = (float*)&v; float* wi = (float*)&w;
#pragma unroll
            for (int q = 0; q < 4; q++)
                wi[q] = vi[q] + bias[col0 + c0 + j*4 + q] + res[obase + j*4 + q];
            *(float4*)(C + obase + j*4) = w;
        }
    } else {
        __nv_bfloat16* dh = CHi + (size_t)row*N + col0 + c0;
        __nv_bfloat16* dl = CLo + (size_t)row*N + col0 + c0;
#pragma unroll
        for (int j = 0; j < 8; j++) {
            float t[8];
#pragma unroll
            for (int q = 0; q < 8; q++) {
                float v = stage[r*SLD + c0 + j*8 + q];
                if (EPI == 5) {
                    v += bias[col0 + c0 + j*8 + q];
                    v = v / (1.f + __expf(-v));
                }
                t[q] = v;
            }
            uint4 ph, pl;
            uint32_t* phi = (uint32_t*)&ph;
            uint32_t* pli = (uint32_t*)&pl;
#pragma unroll
            for (int q = 0; q < 4; q++) {
                phi[q] = pk2(t[2*q], t[2*q+1]);
                pli[q] = pk2lo(t[2*q], t[2*q+1], phi[q]);
            }
            *(uint4*)(dh + j*8) = ph;
            *(uint4*)(dl + j*8) = pl;
        }
    }
}

// ================= tensor-core differential flash attention =================
// Q-tile 64, 128 threads, Q fragments in registers, K/V double-buffered.
#define AP 72
#define KVBUF 27648            /* elems per K/V buffer */
#define TK1H 0
#define TK1L 4608
#define TK2H 9216
#define TK2L 13824
#define TVH  18432
#define TVL  23040
#define SMEM_ATT (2*KVBUF*2)   /* 110592 bytes */

__device__ __forceinline__ void softmax_upd(float sc[8][4], float m[2], float l[2],
                                            float oc[8][4]) {
    float t0 = -1e30f, t1 = -1e30f;
#pragma unroll
    for (int nb = 0; nb < 8; nb++) {
        t0 = fmaxf(t0, fmaxf(sc[nb][0], sc[nb][1]));
        t1 = fmaxf(t1, fmaxf(sc[nb][2], sc[nb][3]));
    }
    t0 = fmaxf(t0, __shfl_xor_sync(0xffffffffu, t0, 1));
    t0 = fmaxf(t0, __shfl_xor_sync(0xffffffffu, t0, 2));
    t1 = fmaxf(t1, __shfl_xor_sync(0xffffffffu, t1, 1));
    t1 = fmaxf(t1, __shfl_xor_sync(0xffffffffu, t1, 2));
    float nm0 = fmaxf(m[0], t0), nm1 = fmaxf(m[1], t1);
    float c0 = __expf(m[0] - nm0), c1 = __expf(m[1] - nm1);
    float s0 = 0.f, s1 = 0.f;
#pragma unroll
    for (int nb = 0; nb < 8; nb++) {
        float p0 = __expf(sc[nb][0] - nm0); sc[nb][0] = p0; s0 += p0;
        float p1 = __expf(sc[nb][1] - nm0); sc[nb][1] = p1; s0 += p1;
        float p2 = __expf(sc[nb][2] - nm1); sc[nb][2] = p2; s1 += p2;
        float p3 = __expf(sc[nb][3] - nm1); sc[nb][3] = p3; s1 += p3;
    }
    s0 += __shfl_xor_sync(0xffffffffu, s0, 1);
    s0 += __shfl_xor_sync(0xffffffffu, s0, 2);
    s1 += __shfl_xor_sync(0xffffffffu, s1, 1);
    s1 += __shfl_xor_sync(0xffffffffu, s1, 2);
    l[0] = l[0]*c0 + s0;  l[1] = l[1]*c1 + s1;
#pragma unroll
    for (int db = 0; db < 8; db++) {
        oc[db][0] *= c0; oc[db][1] *= c0;
        oc[db][2] *= c1; oc[db][3] *= c1;
    }
    m[0] = nm0; m[1] = nm1;
}

__global__ __launch_bounds__(128)
void diff_attn_mma(const __nv_bfloat16* __restrict__ qHi, const __nv_bfloat16* __restrict__ qLo,
                   const __nv_bfloat16* __restrict__ vtHi, const __nv_bfloat16* __restrict__ vtLo,
                   __nv_bfloat16* __restrict__ oHi, __nv_bfloat16* __restrict__ oLo) {
    extern __shared__ __nv_bfloat16 sb[];
    const uint32_t smb = smem_u32(sb);
    const int tid = threadIdx.x;
    const int wid = tid >> 5, lane = tid & 31;
    const int g4 = lane >> 2, t4 = lane & 3;
    const int qt = blockIdx.x, h = blockIdx.y, b = blockIdx.z;
    const int q0 = qt * 64;
    const float lam = g_lam;

    // 64-row tile -> smem at elem-offset tileEls (row pitch 72 elems / 144B)
    auto ld_tile = [&](uint32_t tileEls, const __nv_bfloat16* src, int rowStride) {
#pragma unroll
        for (int i = 0; i < 4; i++) {
            int idx = tid + i*128;
            int r = idx >> 3, c8 = idx & 7;
            CP_ASYNC16(smb + tileEls*2 + r*144 + c8*16,
                       src + (size_t)r*rowStride + c8*8);
        }
    };

    // ---- stage Q in buffer 0, hoist fragments to registers ----
    {
        const size_t qb = (size_t)(b*SEQ + q0)*QKVW + h*HDIM;
        ld_tile(TK1H, qHi + qb,        QKVW);   // q1 hi
        ld_tile(TK1L, qLo + qb,        QKVW);   // q1 lo
        ld_tile(TK2H, qHi + qb + 1024, QKVW);   // q2 hi
        ld_tile(TK2L, qLo + qb + 1024, QKVW);   // q2 lo
        CP_COMMIT();
        CP_WAIT(0);
        __syncthreads();
    }

    uint32_t qa1h[16], qa1l[16], qa2h[16], qa2l[16];
    {
        const int ar = wid*16 + g4;
#pragma unroll
        for (int dc = 0; dc < 4; dc++) {
            const int ac = dc*16 + t4*2;
            qa1h[dc*4+0] = *(const uint32_t*)&sb[TK1H + ar*AP + ac];
            qa1h[dc*4+1] = *(const uint32_t*)&sb[TK1H + (ar+8)*AP + ac];
            qa1h[dc*4+2] = *(const uint32_t*)&sb[TK1H + ar*AP + ac + 8];
            qa1h[dc*4+3] = *(const uint32_t*)&sb[TK1H + (ar+8)*AP + ac + 8];
            qa1l[dc*4+0] = *(const uint32_t*)&sb[TK1L + ar*AP + ac];
            qa1l[dc*4+1] = *(const uint32_t*)&sb[TK1L + (ar+8)*AP + ac];
            qa1l[dc*4+2] = *(const uint32_t*)&sb[TK1L + ar*AP + ac + 8];
            qa1l[dc*4+3] = *(const uint32_t*)&sb[TK1L + (ar+8)*AP + ac + 8];
            qa2h[dc*4+0] = *(const uint32_t*)&sb[TK2H + ar*AP + ac];
            qa2h[dc*4+1] = *(const uint32_t*)&sb[TK2H + (ar+8)*AP + ac];
            qa2h[dc*4+2] = *(const uint32_t*)&sb[TK2H + ar*AP + ac + 8];
            qa2h[dc*4+3] = *(const uint32_t*)&sb[TK2H + (ar+8)*AP + ac + 8];
            qa2l[dc*4+0] = *(const uint32_t*)&sb[TK2L + ar*AP + ac];
            qa2l[dc*4+1] = *(const uint32_t*)&sb[TK2L + (ar+8)*AP + ac];
            qa2l[dc*4+2] = *(const uint32_t*)&sb[TK2L + ar*AP + ac + 8];
            qa2l[dc*4+3] = *(const uint32_t*)&sb[TK2L + (ar+8)*AP + ac + 8];
        }
    }
    __syncthreads();   // all Q reads done before KV[0] overwrites buffer 0

    const size_t kbase = (size_t)b*SEQ*QKVW + h*HDIM;
    const size_t vbase = ((size_t)(b*NHEADS + h)*HDIM)*SEQ;

    auto issue_kv = [&](int kt, int buf) {
        const uint32_t bo = (uint32_t)buf * KVBUF;
        const size_t kb = kbase + (size_t)(kt*64)*QKVW;
        const size_t vb = vbase + kt*64;
        ld_tile(bo + TK1H, qHi + kb + 2048, QKVW);
        ld_tile(bo + TK1L, qLo + kb + 2048, QKVW);
        ld_tile(bo + TK2H, qHi + kb + 3072, QKVW);
        ld_tile(bo + TK2L, qLo + kb + 3072, QKVW);
        ld_tile(bo + TVH,  vtHi + vb, SEQ);
        ld_tile(bo + TVL,  vtLo + vb, SEQ);
        CP_COMMIT();
    };

    issue_kv(0, 0);

    float oc1[8][4], oc2[8][4];
#pragma unroll
    for (int i = 0; i < 8; i++)
#pragma unroll
        for (int j = 0; j < 4; j++) { oc1[i][j] = 0.f; oc2[i][j] = 0.f; }
    float m1[2] = {-1e30f, -1e30f}, l1[2] = {0.f, 0.f};
    float m2[2] = {-1e30f, -1e30f}, l2[2] = {0.f, 0.f};

    for (int kt = 0; kt < 16; kt++) {
        const int cur = kt & 1;
        if (kt + 1 < 16) { issue_kv(kt + 1, cur ^ 1); CP_WAIT(1); }
        else             { CP_WAIT(0); }
        __syncthreads();          // KV[kt] visible to all warps

        const uint32_t kv = (uint32_t)cur * KVBUF;

        // ---- S = Q K^T (3-pass split, both streams) ----
        float sc1[8][4], sc2[8][4];
#pragma unroll
        for (int i = 0; i < 8; i++)
#pragma unroll
            for (int j = 0; j < 4; j++) { sc1[i][j] = 0.f; sc2[i][j] = 0.f; }

#pragma unroll
        for (int dc = 0; dc < 4; dc++) {
            const uint32_t* a1h = &qa1h[dc*4];
            const uint32_t* a1l = &qa1l[dc*4];
            const uint32_t* a2h = &qa2h[dc*4];
            const uint32_t* a2l = &qa2l[dc*4];
#pragma unroll
            for (int nb = 0; nb < 8; nb++) {
                const int bo = (nb*8 + g4)*AP + dc*16 + t4*2;
                uint32_t b1h[2], b1l[2], b2h[2], b2l[2];
                b1h[0] = *(const uint32_t*)&sb[kv + TK1H + bo];
                b1h[1] = *(const uint32_t*)&sb[kv + TK1H + bo + 8];
                b1l[0] = *(const uint32_t*)&sb[kv + TK1L + bo];
                b1l[1] = *(const uint32_t*)&sb[kv + TK1L + bo + 8];
                b2h[0] = *(const uint32_t*)&sb[kv + TK2H + bo];
                b2h[1] = *(const uint32_t*)&sb[kv + TK2H + bo + 8];
                b2l[0] = *(const uint32_t*)&sb[kv + TK2L + bo];
                b2l[1] = *(const uint32_t*)&sb[kv + TK2L + bo + 8];
                MMA_BF16(sc1[nb], a1h, b1h);
                MMA_BF16(sc1[nb], a1l, b1h);
                MMA_BF16(sc1[nb], a1h, b1l);
                MMA_BF16(sc2[nb], a2h, b2h);
                MMA_BF16(sc2[nb], a2l, b2h);
                MMA_BF16(sc2[nb], a2h, b2l);
            }
        }

#pragma unroll
        for (int nb = 0; nb < 8; nb++)
#pragma unroll
            for (int j = 0; j < 4; j++) {
                sc1[nb][j] = fminf(fmaxf(sc1[nb][j]*0.125f, -ATTN_CLIP), ATTN_CLIP);
                sc2[nb][j] = fminf(fmaxf(sc2[nb][j]*0.125f, -ATTN_CLIP), ATTN_CLIP);
            }

        softmax_upd(sc1, m1, l1, oc1);
        softmax_upd(sc2, m2, l2, oc2);

        // ---- O += P V ----
#pragma unroll
        for (int kc = 0; kc < 4; kc++) {
            uint32_t p1h[4], p1l[4], p2h[4], p2l[4];
            p1h[0] = pk2(sc1[2*kc][0],   sc1[2*kc][1]);
            p1h[1] = pk2(sc1[2*kc][2],   sc1[2*kc][3]);
            p1h[2] = pk2(sc1[2*kc+1][0], sc1[2*kc+1][1]);
            p1h[3] = pk2(sc1[2*kc+1][2], sc1[2*kc+1][3]);
            p1l[0] = pk2lo(sc1[2*kc][0],   sc1[2*kc][1],   p1h[0]);
            p1l[1] = pk2lo(sc1[2*kc][2],   sc1[2*kc][3],   p1h[1]);
            p1l[2] = pk2lo(sc1[2*kc+1][0], sc1[2*kc+1][1], p1h[2]);
            p1l[3] = pk2lo(sc1[2*kc+1][2], sc1[2*kc+1][3], p1h[3]);
            p2h[0] = pk2(sc2[2*kc][0],   sc2[2*kc][1]);
            p2h[1] = pk2(sc2[2*kc][2],   sc2[2*kc][3]);
            p2h[2] = pk2(sc2[2*kc+1][0], sc2[2*kc+1][1]);
            p2h[3] = pk2(sc2[2*kc+1][2], sc2[2*kc+1][3]);
            p2l[0] = pk2lo(sc2[2*kc][0],   sc2[2*kc][1],   p2h[0]);
            p2l[1] = pk2lo(sc2[2*kc][2],   sc2[2*kc][3],   p2h[1]);
            p2l[2] = pk2lo(sc2[2*kc+1][0], sc2[2*kc+1][1], p2h[2]);
            p2l[3] = pk2lo(sc2[2*kc+1][2], sc2[2*kc+1][3], p2h[3]);
#pragma unroll
            for (int db = 0; db < 8; db++) {
                const int vo = (db*8 + g4)*AP + kc*16 + t4*2;
                uint32_t bvh[2], bvl[2];
                bvh[0] = *(const uint32_t*)&sb[kv + TVH + vo];
                bvh[1] = *(const uint32_t*)&sb[kv + TVH + vo + 8];
                bvl[0] = *(const uint32_t*)&sb[kv + TVL + vo];
                bvl[1] = *(const uint32_t*)&sb[kv + TVL + vo + 8];
                MMA_BF16(oc1[db], p1h, bvh);
                MMA_BF16(oc1[db], p1l, bvh);
                MMA_BF16(oc1[db], p1h, bvl);
                MMA_BF16(oc2[db], p2h, bvh);
                MMA_BF16(oc2[db], p2l, bvh);
                MMA_BF16(oc2[db], p2h, bvl);
            }
        }
        __syncthreads();          // all reads of buf[cur] done before it is refilled
    }

    const float i10 = 1.f/(l1[0]+EPSF), i11 = 1.f/(l1[1]+EPSF);
    const float i20 = 1.f/(l2[0]+EPSF), i21 = 1.f/(l2[1]+EPSF);
    const int r0 = q0 + wid*16 + g4;
    size_t ob0 = ((size_t)b*SEQ + r0)*DIM + (size_t)h*HDIM;
    size_t ob1 = ob0 + (size_t)8*DIM;
#pragma unroll
    for (int db = 0; db < 8; db++) {
        const int c = db*8 + t4*2;
        float v0 = oc1[db][0]*i10 - lam*(oc2[db][0]*i20);
        float v1 = oc1[db][1]*i10 - lam*(oc2[db][1]*i20);
        float v2 = oc1[db][2]*i11 - lam*(oc2[db][2]*i21);
        float v3 = oc1[db][3]*i11 - lam*(oc2[db][3]*i21);
        uint32_t h01 = pk2(v0, v1), h23 = pk2(v2, v3);
        *(uint32_t*)(oHi + ob0 + c) = h01;
        *(uint32_t*)(oLo + ob0 + c) = pk2lo(v0, v1, h01);
        *(uint32_t*)(oHi + ob1 + c) = h23;
        *(uint32_t*)(oLo + ob1 + c) = pk2lo(v2, v3, h23);
    }
}

// ================= launch =================
extern "C" void kernel_launch(void* const* d_in, const int* in_sizes, int n_in,
                              void* d_out, int out_size) {
    const float* x      = (const float*)d_in[0];
    const float* w_qkv  = (const float*)d_in[1];
    const float* lq1    = (const float*)d_in[2];
    const float* lk1    = (const float*)d_in[3];
    const float* lq2    = (const float*)d_in[4];
    const float* lk2    = (const float*)d_in[5];
    const float* w_proj = (const float*)d_in[6];
    const float* b_proj = (const float*)d_in[7];
    const float* gamma1 = (const float*)d_in[8];
    const float* beta1  = (const float*)d_in[9];
    const float* gamma2 = (const float*)d_in[10];
    const float* beta2  = (const float*)d_in[11];
    const float* w1     = (const float*)d_in[12];
    const float* b1     = (const float*)d_in[13];
    const float* w2     = (const float*)d_in[14];
    const float* b2     = (const float*)d_in[15];
    float* out = (float*)d_out;

    float *p_x2;
    __nv_bfloat16 *p_ahi, *p_alo, *p_qhi, *p_qlo, *p_bhi, *p_blo, *p_vthi, *p_vtlo;
    cudaGetSymbolAddress((void**)&p_x2,   g_x2);
    cudaGetSymbolAddress((void**)&p_ahi,  g_ahi);
    cudaGetSymbolAddress((void**)&p_alo,  g_alo);
    cudaGetSymbolAddress((void**)&p_qhi,  g_qhi);
    cudaGetSymbolAddress((void**)&p_qlo,  g_qlo);
    cudaGetSymbolAddress((void**)&p_bhi,  g_bhi);
    cudaGetSymbolAddress((void**)&p_blo,  g_blo);
    cudaGetSymbolAddress((void**)&p_vthi, g_vthi);
    cudaGetSymbolAddress((void**)&p_vtlo, g_vtlo);

    cudaFuncSetAttribute(diff_attn_mma,
                         cudaFuncAttributeMaxDynamicSharedMemorySize, SMEM_ATT);
    cudaFuncSetAttribute(wmma_gemm<2>, cudaFuncAttributeMaxDynamicSharedMemorySize, SMEM_WG);
    cudaFuncSetAttribute(wmma_gemm<4>, cudaFuncAttributeMaxDynamicSharedMemorySize, SMEM_WG);
    cudaFuncSetAttribute(wmma_gemm<5>, cudaFuncAttributeMaxDynamicSharedMemorySize, SMEM_WG);

    // scalars
    reduce_sq_kernel<<<dim3(128, BATCH), 256>>>(x);
    compute_nx_kernel<<<1, 32>>>();
    compute_lam_kernel<<<1, 1>>>(lq1, lk1, lq2, lk2);

    // GRN1 fused split -> a (hi/lo)
    grn_split_kernel<<<(MTOT*DIM)/4/256, 256>>>(x, gamma1, beta1, p_ahi, p_alo);

    // QKV GEMM -> qkv bf16 hi/lo
    transpose_split_kernel<<<dim3(QKVW/32, DIM/32), dim3(32, 8)>>>(w_qkv, p_bhi, p_blo, DIM, QKVW);
    wmma_gemm<4><<<dim3(QKVW/128, MTOT/128), 256, SMEM_WG>>>(
        p_ahi, p_alo, p_bhi, p_blo, nullptr, p_qhi, p_qlo, MTOT, QKVW, DIM, nullptr, nullptr);

    // V transpose -> vt[bh][d][kk]
    vtrans_kernel<<<dim3(SEQ/32, 32, BATCH), dim3(32, 8)>>>(p_qhi, p_qlo, p_vthi, p_vtlo);

    // attention (Q-tile 64, Q-in-regs, KV double-buffered) -> o hi/lo
    diff_attn_mma<<<dim3(SEQ/64, NHEADS, BATCH), 128, SMEM_ATT>>>(
        p_qhi, p_qlo, p_vthi, p_vtlo, p_ahi, p_alo);

    // proj + bias + residual(x) -> x2 fp32
    transpose_split_kernel<<<dim3(DIM/32, DIM/32), dim3(32, 8)>>>(w_proj, p_bhi, p_blo, DIM, DIM);
    wmma_gemm<2><<<dim3(DIM/128, MTOT/128), 256, SMEM_WG>>>(
        p_ahi, p_alo, p_bhi, p_blo, p_x2, nullptr, nullptr, MTOT, DIM, DIM, b_proj, x);

    // GRN2 fused split -> a (hi/lo)
    reduce_sq_kernel<<<dim3(128, BATCH), 256>>>(p_x2);
    compute_nx_kernel<<<1, 32>>>();
    grn_split_kernel<<<(MTOT*DIM)/4/256, 256>>>(p_x2, gamma2, beta2, p_ahi, p_alo);

    // FFN1: silu(h2 @ w1 + b1) -> f bf16 hi/lo (into q arrays)
    transpose_split_kernel<<<dim3(MLP/32, DIM/32), dim3(32, 8)>>>(w1, p_bhi, p_blo, DIM, MLP);
    wmma_gemm<5><<<dim3(MLP/128, MTOT/128), 256, SMEM_WG>>>(
        p_ahi, p_alo, p_bhi, p_blo, nullptr, p_qhi, p_qlo, MTOT, MLP, DIM, b1, nullptr);

    // FFN2: f @ w2 + b2 + residual(x2) -> out
    transpose_split_kernel<<<dim3(DIM/32, MLP/32), dim3(32, 8)>>>(w2, p_bhi, p_blo, MLP, DIM);
    wmma_gemm<2><<<dim3(DIM/128, MTOT/128), 256, SMEM_WG>>>(
        p_qhi, p_qlo, p_bhi, p_blo, out, nullptr, nullptr, MTOT, DIM, MLP, b2, p_x2);
}

// round 12
// speedup vs baseline: 1.8862x; 1.3658x over previous
#include <cuda_runtime.h>
#include <cuda_bf16.h>
#include <cuda_fp16.h>
#include <mma.h>
#include <math.h>
#include <cstdint>

using namespace nvcuda;

#define BATCH 4
#define SEQ 1024
#define DIM 1024
#define NHEADS 16
#define HDIM 64
#define MLP 4096
#define MTOT (BATCH*SEQ)        /* 4096 */
#define QKVW (5*NHEADS*HDIM)    /* 5120 */
#define ATTN_CLIP 100.0f
#define NORM_CLIP 1000.0f
#define EPSF 1e-6f

// ================= scratch =================
__device__ float g_x2 [MTOT*DIM];
__device__ __half g_ahi[(size_t)MTOT*MLP];                   // GEMM A hi (h/o/h2)
__device__ __half g_alo[(size_t)MTOT*MLP];                   // GEMM A lo
__device__ __nv_bfloat16 g_qhi[(size_t)MTOT*QKVW];           // qkv bf16 hi; later f (half)
__device__ __nv_bfloat16 g_qlo[(size_t)MTOT*QKVW];
__device__ __half g_bh [(size_t)QKVW*DIM];                   // weights^T fp16
__device__ __nv_bfloat16 g_vthi[(size_t)BATCH*NHEADS*HDIM*SEQ];
__device__ __nv_bfloat16 g_vtlo[(size_t)BATCH*NHEADS*HDIM*SEQ];
__device__ float g_part[BATCH*128];
__device__ float g_nx[BATCH];
__device__ float g_lam;

// ================= helpers =================
__device__ __forceinline__ uint32_t smem_u32(const void* p) {
    uint32_t a;
    asm("{ .reg .u64 t; cvta.to.shared.u64 t, %1; cvt.u32.u64 %0, t; }" : "=r"(a) : "l"(p));
    return a;
}
#define CP_ASYNC16(dst, src) \
    asm volatile("cp.async.cg.shared.global [%0], [%1], 16;" :: "r"(dst), "l"(src))
#define CP_COMMIT() asm volatile("cp.async.commit_group;" ::: "memory")
#define CP_WAIT(n)  asm volatile("cp.async.wait_group %0;" :: "n"(n) : "memory")

#define MMA_BF16(d, a, b) \
    asm volatile("mma.sync.aligned.m16n8k16.row.col.f32.bf16.bf16.f32 " \
        "{%0,%1,%2,%3}, {%4,%5,%6,%7}, {%8,%9}, {%0,%1,%2,%3};" \
        : "+f"((d)[0]), "+f"((d)[1]), "+f"((d)[2]), "+f"((d)[3]) \
        : "r"((a)[0]), "r"((a)[1]), "r"((a)[2]), "r"((a)[3]), \
          "r"((b)[0]), "r"((b)[1]))

// bf16 packers (attention path)
__device__ __forceinline__ uint32_t pk2(float x, float y) {
    __nv_bfloat162 t = __floats2bfloat162_rn(x, y);
    return *(uint32_t*)&t;
}
__device__ __forceinline__ uint32_t pk2lo(float x, float y, uint32_t hipk) {
    __nv_bfloat162 hp = *(__nv_bfloat162*)&hipk;
    return pk2(x - __bfloat162float(hp.x), y - __bfloat162float(hp.y));
}
// fp16 packers (GEMM path)
__device__ __forceinline__ uint32_t pk2h(float x, float y) {
    __half2 t = __floats2half2_rn(x, y);
    return *(uint32_t*)&t;
}
__device__ __forceinline__ uint32_t pk2hlo(float x, float y, uint32_t hipk) {
    __half2 hp = *(__half2*)&hipk;
    return pk2h(x - __half2float(hp.x), y - __half2float(hp.y));
}

// ================= scalar kernels =================
__global__ void reduce_sq_kernel(const float* __restrict__ x) {
    const int b = blockIdx.y, blk = blockIdx.x;
    const int N = SEQ*DIM;
    const int per = N / 128;
    const float* p = x + (size_t)b*N + (size_t)blk*per;
    float s = 0.f;
    for (int i = threadIdx.x; i < per; i += 256) { float v = p[i]; s += v*v; }
    __shared__ float red[8];
    int lane = threadIdx.x & 31, w = threadIdx.x >> 5;
#pragma unroll
    for (int o = 16; o; o >>= 1) s += __shfl_down_sync(0xffffffffu, s, o);
    if (lane == 0) red[w] = s;
    __syncthreads();
    if (w == 0) {
        s = (lane < 8) ? red[lane] : 0.f;
#pragma unroll
        for (int o = 4; o; o >>= 1) s += __shfl_down_sync(0xffffffffu, s, o);
        if (lane == 0) g_part[b*128 + blk] = s;
    }
}

__global__ void compute_nx_kernel() {
    int b = threadIdx.x;
    if (b < BATCH) {
        float s = 0.f;
        for (int i = 0; i < 128; i++) s += g_part[b*128 + i];
        s = fminf(fmaxf(s, EPSF), NORM_CLIP);
        float gx = sqrtf(s);
        float nx = gx / (gx + EPSF);
        nx = fminf(fmaxf(nx, -NORM_CLIP), NORM_CLIP);
        g_nx[b] = nx;
    }
}

__global__ void compute_lam_kernel(const float* __restrict__ lq1, const float* __restrict__ lk1,
                                   const float* __restrict__ lq2, const float* __restrict__ lk2) {
    float s1 = 0.f, s2 = 0.f;
    for (int d = 0; d < HDIM; d++) { s1 += lq1[d]*lk1[d]; s2 += lq2[d]*lk2[d]; }
    s1 = fminf(fmaxf(s1, -10.f), 10.f);
    s2 = fminf(fmaxf(s2, -10.f), 10.f);
    float lam_init = 0.8f - 0.6f*expf(-0.0f);
    float lam = expf(s1) - expf(s2) + lam_init;
    g_lam = fminf(fmaxf(lam, 0.1f), 5.f);
}

// ================= GRN fused with fp16 hi/lo split =================
__global__ void grn_split_kernel(const float* __restrict__ x, const float* __restrict__ gamma,
                                 const float* __restrict__ beta,
                                 __half* __restrict__ hi, __half* __restrict__ lo) {
    int idx = blockIdx.x*blockDim.x + threadIdx.x;
    int e = idx * 4;
    int b = e >> 20;
    int d = e & (DIM-1);
    float nx = g_nx[b];
    float4 xv = *(const float4*)(x + e);
    float4 gv = *(const float4*)(gamma + d);
    float4 bv = *(const float4*)(beta + d);
    float r0 = gv.x*(xv.x*nx) + bv.x + xv.x;
    float r1 = gv.y*(xv.y*nx) + bv.y + xv.y;
    float r2 = gv.z*(xv.z*nx) + bv.z + xv.z;
    float r3 = gv.w*(xv.w*nx) + bv.w + xv.w;
    uint2 ph, pl;
    ph.x = pk2h(r0, r1); ph.y = pk2h(r2, r3);
    pl.x = pk2hlo(r0, r1, ph.x); pl.y = pk2hlo(r2, r3, ph.y);
    *(uint2*)(hi + e) = ph;
    *(uint2*)(lo + e) = pl;
}

// ================= weight transpose to fp16: w[K][N] -> t[N][K] =================
__global__ void transpose_half_kernel(const float* __restrict__ w,
                                      __half* __restrict__ th, int K, int N) {
    __shared__ float tile[32][33];
    int n0 = blockIdx.x * 32, k0 = blockIdx.y * 32;
    int tx = threadIdx.x, ty = threadIdx.y;
#pragma unroll
    for (int i = 0; i < 4; i++)
        tile[ty + i*8][tx] = w[(size_t)(k0 + ty + i*8)*N + n0 + tx];
    __syncthreads();
#pragma unroll
    for (int i = 0; i < 4; i++) {
        float v = tile[tx][ty + i*8];
        th[(size_t)(n0 + ty + i*8)*K + k0 + tx] = __float2half(v);
    }
}

// ================= V transpose (bf16, attention path) =================
__global__ void vtrans_kernel(const __nv_bfloat16* __restrict__ qHi,
                              const __nv_bfloat16* __restrict__ qLo,
                              __nv_bfloat16* __restrict__ vtHi,
                              __nv_bfloat16* __restrict__ vtLo) {
    __shared__ __nv_bfloat16 th[32][33], tl[32][33];
    const int b = blockIdx.z;
    const int t0 = blockIdx.x * 32;
    const int f0 = blockIdx.y * 32;
    const int tx = threadIdx.x, ty = threadIdx.y;
#pragma unroll
    for (int i = 0; i < 4; i++) {
        size_t src = (size_t)(b*SEQ + t0 + ty + i*8)*QKVW + 4096 + f0 + tx;
        th[ty + i*8][tx] = qHi[src];
        tl[ty + i*8][tx] = qLo[src];
    }
    __syncthreads();
#pragma unroll
    for (int i = 0; i < 4; i++) {
        int f = f0 + ty + i*8;
        int h = f >> 6, d = f & 63;
        size_t dst = ((size_t)(b*NHEADS + h)*HDIM + d)*SEQ + t0 + tx;
        vtHi[dst] = th[tx][ty + i*8];
        vtLo[dst] = tl[tx][ty + i*8];
    }
}

// ================= fp16 2-pass wmma GEMM =================
// D = (Ahi + Alo) * Bh   (A split fp16 hi/lo; B rounded to fp16)
// EPI 2: fp32 C = acc+bias+res; EPI 4: bf16 split(acc); EPI 5: fp16 split(silu(acc+bias))
#define KC 32
#define LDA 40
#define TILE_ELEMS (128*LDA)
#define BUF_ELEMS (3*TILE_ELEMS)     /* Ahi, Alo, Bh */
#define SMEM_WG (128*132*4)          /* 67584 > 2*BUF_ELEMS*2 = 61440 */
#define SLD 132

template<int EPI>
__global__ __launch_bounds__(256, 2)
void wmma_gemm(const __half* __restrict__ Ahi, const __half* __restrict__ Alo,
               const __half* __restrict__ Bh,
               float* __restrict__ C, void* __restrict__ CHv, void* __restrict__ CLv,
               int M, int N, int K,
               const float* __restrict__ bias, const float* __restrict__ res) {
    extern __shared__ char smem_raw[];
    __half* sm = (__half*)smem_raw;
    const uint32_t sm_addr = smem_u32(sm);

    const int tid = threadIdx.x;
    const int wid = tid >> 5;
    const int row0 = blockIdx.y * 128;
    const int col0 = blockIdx.x * 128;
    const int wr = (wid >> 1) * 32;
    const int wc = (wid & 1) * 64;

    const __half* gsrc[3] = {
        Ahi + (size_t)row0*K, Alo + (size_t)row0*K, Bh + (size_t)col0*K };

    int u_arr[6], u_row[6], u_col[6];
#pragma unroll
    for (int i = 0; i < 6; i++) {
        int idx = tid + i*256;               // 0..1535 units of 16B
        u_arr[i] = idx >> 9;
        int rem = idx & 511;
        u_row[i] = rem >> 2;
        u_col[i] = (rem & 3) * 8;
    }

    auto issue_chunk = [&](int k0, int buf) {
        uint32_t dbase = sm_addr + (uint32_t)buf * (BUF_ELEMS*2);
#pragma unroll
        for (int i = 0; i < 6; i++) {
            const __half* src = gsrc[u_arr[i]] + (size_t)u_row[i]*K + k0 + u_col[i];
            uint32_t dst = dbase + (uint32_t)(u_arr[i]*TILE_ELEMS + u_row[i]*LDA + u_col[i]) * 2;
            CP_ASYNC16(dst, src);
        }
        CP_COMMIT();
    };

    wmma::fragment<wmma::accumulator, 16, 16, 16, float> acc[2][4];
#pragma unroll
    for (int i = 0; i < 2; i++)
#pragma unroll
        for (int j = 0; j < 4; j++) wmma::fill_fragment(acc[i][j], 0.f);

    const int nch = K / KC;
    issue_chunk(0, 0);

    for (int ch = 0; ch < nch; ch++) {
        const int cur = ch & 1;
        if (ch + 1 < nch) { issue_chunk((ch+1)*KC, cur ^ 1); CP_WAIT(1); }
        else              { CP_WAIT(0); }
        __syncthreads();

        const __half* b0 = sm + cur * BUF_ELEMS;
        const __half* tAhi = b0 + 0*TILE_ELEMS + wr*LDA;
        const __half* tAlo = b0 + 1*TILE_ELEMS + wr*LDA;
        const __half* tBh  = b0 + 2*TILE_ELEMS + wc*LDA;

#pragma unroll
        for (int ks = 0; ks < 2; ks++) {
            wmma::fragment<wmma::matrix_a, 16, 16, 16, __half, wmma::row_major> aH[2], aL[2];
            wmma::fragment<wmma::matrix_b, 16, 16, 16, __half, wmma::col_major> bF[4];
            const int ko = ks * 16;
#pragma unroll
            for (int i = 0; i < 2; i++)
                wmma::load_matrix_sync(aH[i], tAhi + i*16*LDA + ko, LDA);
#pragma unroll
            for (int j = 0; j < 4; j++)
                wmma::load_matrix_sync(bF[j], tBh + j*16*LDA + ko, LDA);
            // hh
#pragma unroll
            for (int i = 0; i < 2; i++)
#pragma unroll
                for (int j = 0; j < 4; j++)
                    wmma::mma_sync(acc[i][j], aH[i], bF[j], acc[i][j]);
            // lh (reuse bF)
#pragma unroll
            for (int i = 0; i < 2; i++)
                wmma::load_matrix_sync(aL[i], tAlo + i*16*LDA + ko, LDA);
#pragma unroll
            for (int i = 0; i < 2; i++)
#pragma unroll
                for (int j = 0; j < 4; j++)
                    wmma::mma_sync(acc[i][j], aL[i], bF[j], acc[i][j]);
        }
        __syncthreads();
    }

    float* stage = (float*)smem_raw;
#pragma unroll
    for (int i = 0; i < 2; i++)
#pragma unroll
        for (int j = 0; j < 4; j++)
            wmma::store_matrix_sync(stage + (wr + i*16)*SLD + wc + j*16,
                                    acc[i][j], SLD, wmma::mem_row_major);
    __syncthreads();

    const int r = tid >> 1;
    const int c0 = (tid & 1) * 64;
    const int row = row0 + r;

    if (EPI == 2) {
        size_t obase = (size_t)row*N + col0 + c0;
#pragma unroll
        for (int j = 0; j < 16; j++) {
            float4 v = *(float4*)(stage + r*SLD + c0 + j*4);
            float4 w;
            float* vi = (float*)&v; float* wi = (float*)&w;
#pragma unroll
            for (int q = 0; q < 4; q++)
                wi[q] = vi[q] + bias[col0 + c0 + j*4 + q] + res[obase + j*4 + q];
            *(float4*)(C + obase + j*4) = w;
        }
    } else if (EPI == 4) {
        // bf16 split (attention input)
        __nv_bfloat16* dh = (__nv_bfloat16*)CHv + (size_t)row*N + col0 + c0;
        __nv_bfloat16* dl = (__nv_bfloat16*)CLv + (size_t)row*N + col0 + c0;
#pragma unroll
        for (int j = 0; j < 8; j++) {
            float t[8];
#pragma unroll
            for (int q = 0; q < 8; q++) t[q] = stage[r*SLD + c0 + j*8 + q];
            uint4 ph, pl;
            uint32_t* phi = (uint32_t*)&ph;
            uint32_t* pli = (uint32_t*)&pl;
#pragma unroll
            for (int q = 0; q < 4; q++) {
                phi[q] = pk2(t[2*q], t[2*q+1]);
                pli[q] = pk2lo(t[2*q], t[2*q+1], phi[q]);
            }
            *(uint4*)(dh + j*8) = ph;
            *(uint4*)(dl + j*8) = pl;
        }
    } else {
        // EPI 5: fp16 split of silu(acc+bias)
        __half* dh = (__half*)CHv + (size_t)row*N + col0 + c0;
        __half* dl = (__half*)CLv + (size_t)row*N + col0 + c0;
#pragma unroll
        for (int j = 0; j < 8; j++) {
            float t[8];
#pragma unroll
            for (int q = 0; q < 8; q++) {
                float v = stage[r*SLD + c0 + j*8 + q] + bias[col0 + c0 + j*8 + q];
                t[q] = v / (1.f + __expf(-v));
            }
            uint4 ph, pl;
            uint32_t* phi = (uint32_t*)&ph;
            uint32_t* pli = (uint32_t*)&pl;
#pragma unroll
            for (int q = 0; q < 4; q++) {
                phi[q] = pk2h(t[2*q], t[2*q+1]);
                pli[q] = pk2hlo(t[2*q], t[2*q+1], phi[q]);
            }
            *(uint4*)(dh + j*8) = ph;
            *(uint4*)(dl + j*8) = pl;
        }
    }
}

// ================= tensor-core differential flash attention (bf16, unchanged core) =================
#define AP 72
#define KVBUF 27648
#define TK1H 0
#define TK1L 4608
#define TK2H 9216
#define TK2L 13824
#define TVH  18432
#define TVL  23040
#define SMEM_ATT (2*KVBUF*2)

__device__ __forceinline__ void softmax_upd(float sc[8][4], float m[2], float l[2],
                                            float oc[8][4]) {
    float t0 = -1e30f, t1 = -1e30f;
#pragma unroll
    for (int nb = 0; nb < 8; nb++) {
        t0 = fmaxf(t0, fmaxf(sc[nb][0], sc[nb][1]));
        t1 = fmaxf(t1, fmaxf(sc[nb][2], sc[nb][3]));
    }
    t0 = fmaxf(t0, __shfl_xor_sync(0xffffffffu, t0, 1));
    t0 = fmaxf(t0, __shfl_xor_sync(0xffffffffu, t0, 2));
    t1 = fmaxf(t1, __shfl_xor_sync(0xffffffffu, t1, 1));
    t1 = fmaxf(t1, __shfl_xor_sync(0xffffffffu, t1, 2));
    float nm0 = fmaxf(m[0], t0), nm1 = fmaxf(m[1], t1);
    float c0 = __expf(m[0] - nm0), c1 = __expf(m[1] - nm1);
    float s0 = 0.f, s1 = 0.f;
#pragma unroll
    for (int nb = 0; nb < 8; nb++) {
        float p0 = __expf(sc[nb][0] - nm0); sc[nb][0] = p0; s0 += p0;
        float p1 = __expf(sc[nb][1] - nm0); sc[nb][1] = p1; s0 += p1;
        float p2 = __expf(sc[nb][2] - nm1); sc[nb][2] = p2; s1 += p2;
        float p3 = __expf(sc[nb][3] - nm1); sc[nb][3] = p3; s1 += p3;
    }
    s0 += __shfl_xor_sync(0xffffffffu, s0, 1);
    s0 += __shfl_xor_sync(0xffffffffu, s0, 2);
    s1 += __shfl_xor_sync(0xffffffffu, s1, 1);
    s1 += __shfl_xor_sync(0xffffffffu, s1, 2);
    l[0] = l[0]*c0 + s0;  l[1] = l[1]*c1 + s1;
#pragma unroll
    for (int db = 0; db < 8; db++) {
        oc[db][0] *= c0; oc[db][1] *= c0;
        oc[db][2] *= c1; oc[db][3] *= c1;
    }
    m[0] = nm0; m[1] = nm1;
}

__global__ __launch_bounds__(128)
void diff_attn_mma(const __nv_bfloat16* __restrict__ qHi, const __nv_bfloat16* __restrict__ qLo,
                   const __nv_bfloat16* __restrict__ vtHi, const __nv_bfloat16* __restrict__ vtLo,
                   __half* __restrict__ oHi, __half* __restrict__ oLo) {
    extern __shared__ __nv_bfloat16 sb[];
    const uint32_t smb = smem_u32(sb);
    const int tid = threadIdx.x;
    const int wid = tid >> 5, lane = tid & 31;
    const int g4 = lane >> 2, t4 = lane & 3;
    const int qt = blockIdx.x, h = blockIdx.y, b = blockIdx.z;
    const int q0 = qt * 64;
    const float lam = g_lam;

    auto ld_tile = [&](uint32_t tileEls, const __nv_bfloat16* src, int rowStride) {
#pragma unroll
        for (int i = 0; i < 4; i++) {
            int idx = tid + i*128;
            int r = idx >> 3, c8 = idx & 7;
            CP_ASYNC16(smb + tileEls*2 + r*144 + c8*16,
                       src + (size_t)r*rowStride + c8*8);
        }
    };

    // stage Q in buffer 0, hoist fragments to registers
    {
        const size_t qb = (size_t)(b*SEQ + q0)*QKVW + h*HDIM;
        ld_tile(TK1H, qHi + qb,        QKVW);
        ld_tile(TK1L, qLo + qb,        QKVW);
        ld_tile(TK2H, qHi + qb + 1024, QKVW);
        ld_tile(TK2L, qLo + qb + 1024, QKVW);
        CP_COMMIT();
        CP_WAIT(0);
        __syncthreads();
    }

    uint32_t qa1h[16], qa1l[16], qa2h[16], qa2l[16];
    {
        const int ar = wid*16 + g4;
#pragma unroll
        for (int dc = 0; dc < 4; dc++) {
            const int ac = dc*16 + t4*2;
            qa1h[dc*4+0] = *(const uint32_t*)&sb[TK1H + ar*AP + ac];
            qa1h[dc*4+1] = *(const uint32_t*)&sb[TK1H + (ar+8)*AP + ac];
            qa1h[dc*4+2] = *(const uint32_t*)&sb[TK1H + ar*AP + ac + 8];
            qa1h[dc*4+3] = *(const uint32_t*)&sb[TK1H + (ar+8)*AP + ac + 8];
            qa1l[dc*4+0] = *(const uint32_t*)&sb[TK1L + ar*AP + ac];
            qa1l[dc*4+1] = *(const uint32_t*)&sb[TK1L + (ar+8)*AP + ac];
            qa1l[dc*4+2] = *(const uint32_t*)&sb[TK1L + ar*AP + ac + 8];
            qa1l[dc*4+3] = *(const uint32_t*)&sb[TK1L + (ar+8)*AP + ac + 8];
            qa2h[dc*4+0] = *(const uint32_t*)&sb[TK2H + ar*AP + ac];
            qa2h[dc*4+1] = *(const uint32_t*)&sb[TK2H + (ar+8)*AP + ac];
            qa2h[dc*4+2] = *(const uint32_t*)&sb[TK2H + ar*AP + ac + 8];
            qa2h[dc*4+3] = *(const uint32_t*)&sb[TK2H + (ar+8)*AP + ac + 8];
            qa2l[dc*4+0] = *(const uint32_t*)&sb[TK2L + ar*AP + ac];
            qa2l[dc*4+1] = *(const uint32_t*)&sb[TK2L + (ar+8)*AP + ac];
            qa2l[dc*4+2] = *(const uint32_t*)&sb[TK2L + ar*AP + ac + 8];
            qa2l[dc*4+3] = *(const uint32_t*)&sb[TK2L + (ar+8)*AP + ac + 8];
        }
    }
    __syncthreads();

    const size_t kbase = (size_t)b*SEQ*QKVW + h*HDIM;
    const size_t vbase = ((size_t)(b*NHEADS + h)*HDIM)*SEQ;

    auto issue_kv = [&](int kt, int buf) {
        const uint32_t bo = (uint32_t)buf * KVBUF;
        const size_t kb = kbase + (size_t)(kt*64)*QKVW;
        const size_t vb = vbase + kt*64;
        ld_tile(bo + TK1H, qHi + kb + 2048, QKVW);
        ld_tile(bo + TK1L, qLo + kb + 2048, QKVW);
        ld_tile(bo + TK2H, qHi + kb + 3072, QKVW);
        ld_tile(bo + TK2L, qLo + kb + 3072, QKVW);
        ld_tile(bo + TVH,  vtHi + vb, SEQ);
        ld_tile(bo + TVL,  vtLo + vb, SEQ);
        CP_COMMIT();
    };

    issue_kv(0, 0);

    float oc1[8][4], oc2[8][4];
#pragma unroll
    for (int i = 0; i < 8; i++)
#pragma unroll
        for (int j = 0; j < 4; j++) { oc1[i][j] = 0.f; oc2[i][j] = 0.f; }
    float m1[2] = {-1e30f, -1e30f}, l1[2] = {0.f, 0.f};
    float m2[2] = {-1e30f, -1e30f}, l2[2] = {0.f, 0.f};

    for (int kt = 0; kt < 16; kt++) {
        const int cur = kt & 1;
        if (kt + 1 < 16) { issue_kv(kt + 1, cur ^ 1); CP_WAIT(1); }
        else             { CP_WAIT(0); }
        __syncthreads();

        const uint32_t kv = (uint32_t)cur * KVBUF;

        float sc1[8][4], sc2[8][4];
#pragma unroll
        for (int i = 0; i < 8; i++)
#pragma unroll
            for (int j = 0; j < 4; j++) { sc1[i][j] = 0.f; sc2[i][j] = 0.f; }

#pragma unroll
        for (int dc = 0; dc < 4; dc++) {
            const uint32_t* a1h = &qa1h[dc*4];
            const uint32_t* a1l = &qa1l[dc*4];
            const uint32_t* a2h = &qa2h[dc*4];
            const uint32_t* a2l = &qa2l[dc*4];
#pragma unroll
            for (int nb = 0; nb < 8; nb++) {
                const int bo = (nb*8 + g4)*AP + dc*16 + t4*2;
                uint32_t b1h[2], b1l[2], b2h[2], b2l[2];
                b1h[0] = *(const uint32_t*)&sb[kv + TK1H + bo];
                b1h[1] = *(const uint32_t*)&sb[kv + TK1H + bo + 8];
                b1l[0] = *(const uint32_t*)&sb[kv + TK1L + bo];
                b1l[1] = *(const uint32_t*)&sb[kv + TK1L + bo + 8];
                b2h[0] = *(const uint32_t*)&sb[kv + TK2H + bo];
                b2h[1] = *(const uint32_t*)&sb[kv + TK2H + bo + 8];
                b2l[0] = *(const uint32_t*)&sb[kv + TK2L + bo];
                b2l[1] = *(const uint32_t*)&sb[kv + TK2L + bo + 8];
                MMA_BF16(sc1[nb], a1h, b1h);
                MMA_BF16(sc1[nb], a1l, b1h);
                MMA_BF16(sc1[nb], a1h, b1l);
                MMA_BF16(sc2[nb], a2h, b2h);
                MMA_BF16(sc2[nb], a2l, b2h);
                MMA_BF16(sc2[nb], a2h, b2l);
            }
        }

#pragma unroll
        for (int nb = 0; nb < 8; nb++)
#pragma unroll
            for (int j = 0; j < 4; j++) {
                sc1[nb][j] = fminf(fmaxf(sc1[nb][j]*0.125f, -ATTN_CLIP), ATTN_CLIP);
                sc2[nb][j] = fminf(fmaxf(sc2[nb][j]*0.125f, -ATTN_CLIP), ATTN_CLIP);
            }

        softmax_upd(sc1, m1, l1, oc1);
        softmax_upd(sc2, m2, l2, oc2);

#pragma unroll
        for (int kc = 0; kc < 4; kc++) {
            uint32_t p1h[4], p1l[4], p2h[4], p2l[4];
            p1h[0] = pk2(sc1[2*kc][0],   sc1[2*kc][1]);
            p1h[1] = pk2(sc1[2*kc][2],   sc1[2*kc][3]);
            p1h[2] = pk2(sc1[2*kc+1][0], sc1[2*kc+1][1]);
            p1h[3] = pk2(sc1[2*kc+1][2], sc1[2*kc+1][3]);
            p1l[0] = pk2lo(sc1[2*kc][0],   sc1[2*kc][1],   p1h[0]);
            p1l[1] = pk2lo(sc1[2*kc][2],   sc1[2*kc][3],   p1h[1]);
            p1l[2] = pk2lo(sc1[2*kc+1][0], sc1[2*kc+1][1], p1h[2]);
            p1l[3] = pk2lo(sc1[2*kc+1][2], sc1[2*kc+1][3], p1h[3]);
            p2h[0] = pk2(sc2[2*kc][0],   sc2[2*kc][1]);
            p2h[1] = pk2(sc2[2*kc][2],   sc2[2*kc][3]);
            p2h[2] = pk2(sc2[2*kc+1][0], sc2[2*kc+1][1]);
            p2h[3] = pk2(sc2[2*kc+1][2], sc2[2*kc+1][3]);
            p2l[0] = pk2lo(sc2[2*kc][0],   sc2[2*kc][1],   p2h[0]);
            p2l[1] = pk2lo(sc2[2*kc][2],   sc2[2*kc][3],   p2h[1]);
            p2l[2] = pk2lo(sc2[2*kc+1][0], sc2[2*kc+1][1], p2h[2]);
            p2l[3] = pk2lo(sc2[2*kc+1][2], sc2[2*kc+1][3], p2h[3]);
#pragma unroll
            for (int db = 0; db < 8; db++) {
                const int vo = (db*8 + g4)*AP + kc*16 + t4*2;
                uint32_t bvh[2], bvl[2];
                bvh[0] = *(const uint32_t*)&sb[kv + TVH + vo];
                bvh[1] = *(const uint32_t*)&sb[kv + TVH + vo + 8];
                bvl[0] = *(const uint32_t*)&sb[kv + TVL + vo];
                bvl[1] = *(const uint32_t*)&sb[kv + TVL + vo + 8];
                MMA_BF16(oc1[db], p1h, bvh);
                MMA_BF16(oc1[db], p1l, bvh);
                MMA_BF16(oc1[db], p1h, bvl);
                MMA_BF16(oc2[db], p2h, bvh);
                MMA_BF16(oc2[db], p2l, bvh);
                MMA_BF16(oc2[db], p2h, bvl);
            }
        }
        __syncthreads();
    }

    // epilogue: combine streams -> fp16 hi/lo (proj GEMM input)
    const float i10 = 1.f/(l1[0]+EPSF), i11 = 1.f/(l1[1]+EPSF);
    const float i20 = 1.f/(l2[0]+EPSF), i21 = 1.f/(l2[1]+EPSF);
    const int r0 = q0 + wid*16 + g4;
    size_t ob0 = ((size_t)b*SEQ + r0)*DIM + (size_t)h*HDIM;
    size_t ob1 = ob0 + (size_t)8*DIM;
#pragma unroll
    for (int db = 0; db < 8; db++) {
        const int c = db*8 + t4*2;
        float v0 = oc1[db][0]*i10 - lam*(oc2[db][0]*i20);
        float v1 = oc1[db][1]*i10 - lam*(oc2[db][1]*i20);
        float v2 = oc1[db][2]*i11 - lam*(oc2[db][2]*i21);
        float v3 = oc1[db][3]*i11 - lam*(oc2[db][3]*i21);
        uint32_t h01 = pk2h(v0, v1), h23 = pk2h(v2, v3);
        *(uint32_t*)(oHi + ob0 + c) = h01;
        *(uint32_t*)(oLo + ob0 + c) = pk2hlo(v0, v1, h01);
        *(uint32_t*)(oHi + ob1 + c) = h23;
        *(uint32_t*)(oLo + ob1 + c) = pk2hlo(v2, v3, h23);
    }
}

// ================= launch =================
extern "C" void kernel_launch(void* const* d_in, const int* in_sizes, int n_in,
                              void* d_out, int out_size) {
    const float* x      = (const float*)d_in[0];
    const float* w_qkv  = (const float*)d_in[1];
    const float* lq1    = (const float*)d_in[2];
    const float* lk1    = (const float*)d_in[3];
    const float* lq2    = (const float*)d_in[4];
    const float* lk2    = (const float*)d_in[5];
    const float* w_proj = (const float*)d_in[6];
    const float* b_proj = (const float*)d_in[7];
    const float* gamma1 = (const float*)d_in[8];
    const float* beta1  = (const float*)d_in[9];
    const float* gamma2 = (const float*)d_in[10];
    const float* beta2  = (const float*)d_in[11];
    const float* w1     = (const float*)d_in[12];
    const float* b1     = (const float*)d_in[13];
    const float* w2     = (const float*)d_in[14];
    const float* b2     = (const float*)d_in[15];
    float* out = (float*)d_out;

    float *p_x2;
    __half *p_ahi, *p_alo, *p_bh;
    __nv_bfloat16 *p_qhi, *p_qlo, *p_vthi, *p_vtlo;
    cudaGetSymbolAddress((void**)&p_x2,   g_x2);
    cudaGetSymbolAddress((void**)&p_ahi,  g_ahi);
    cudaGetSymbolAddress((void**)&p_alo,  g_alo);
    cudaGetSymbolAddress((void**)&p_qhi,  g_qhi);
    cudaGetSymbolAddress((void**)&p_qlo,  g_qlo);
    cudaGetSymbolAddress((void**)&p_bh,   g_bh);
    cudaGetSymbolAddress((void**)&p_vthi, g_vthi);
    cudaGetSymbolAddress((void**)&p_vtlo, g_vtlo);

    cudaFuncSetAttribute(diff_attn_mma,
                         cudaFuncAttributeMaxDynamicSharedMemorySize, SMEM_ATT);
    cudaFuncSetAttribute(wmma_gemm<2>, cudaFuncAttributeMaxDynamicSharedMemorySize, SMEM_WG);
    cudaFuncSetAttribute(wmma_gemm<4>, cudaFuncAttributeMaxDynamicSharedMemorySize, SMEM_WG);
    cudaFuncSetAttribute(wmma_gemm<5>, cudaFuncAttributeMaxDynamicSharedMemorySize, SMEM_WG);

    // scalars
    reduce_sq_kernel<<<dim3(128, BATCH), 256>>>(x);
    compute_nx_kernel<<<1, 32>>>();
    compute_lam_kernel<<<1, 1>>>(lq1, lk1, lq2, lk2);

    // GRN1 fused fp16 split -> a (hi/lo)
    grn_split_kernel<<<(MTOT*DIM)/4/256, 256>>>(x, gamma1, beta1, p_ahi, p_alo);

    // QKV GEMM -> qkv bf16 hi/lo (attention input)
    transpose_half_kernel<<<dim3(QKVW/32, DIM/32), dim3(32, 8)>>>(w_qkv, p_bh, DIM, QKVW);
    wmma_gemm<4><<<dim3(QKVW/128, MTOT/128), 256, SMEM_WG>>>(
        p_ahi, p_alo, p_bh, nullptr, p_qhi, p_qlo, MTOT, QKVW, DIM, nullptr, nullptr);

    // V transpose -> vt[bh][d][kk] (bf16)
    vtrans_kernel<<<dim3(SEQ/32, 32, BATCH), dim3(32, 8)>>>(p_qhi, p_qlo, p_vthi, p_vtlo);

    // attention -> o fp16 hi/lo (into a arrays)
    diff_attn_mma<<<dim3(SEQ/64, NHEADS, BATCH), 128, SMEM_ATT>>>(
        p_qhi, p_qlo, p_vthi, p_vtlo, p_ahi, p_alo);

    // proj + bias + residual(x) -> x2 fp32
    transpose_half_kernel<<<dim3(DIM/32, DIM/32), dim3(32, 8)>>>(w_proj, p_bh, DIM, DIM);
    wmma_gemm<2><<<dim3(DIM/128, MTOT/128), 256, SMEM_WG>>>(
        p_ahi, p_alo, p_bh, p_x2, nullptr, nullptr, MTOT, DIM, DIM, b_proj, x);

    // GRN2 fused fp16 split -> a (hi/lo)
    reduce_sq_kernel<<<dim3(128, BATCH), 256>>>(p_x2);
    compute_nx_kernel<<<1, 32>>>();
    grn_split_kernel<<<(MTOT*DIM)/4/256, 256>>>(p_x2, gamma2, beta2, p_ahi, p_alo);

    // FFN1: silu(h2 @ w1 + b1) -> f fp16 hi/lo (into q arrays)
    transpose_half_kernel<<<dim3(MLP/32, DIM/32), dim3(32, 8)>>>(w1, p_bh, DIM, MLP);
    wmma_gemm<5><<<dim3(MLP/128, MTOT/128), 256, SMEM_WG>>>(
        p_ahi, p_alo, p_bh, nullptr, (void*)p_qhi, (void*)p_qlo, MTOT, MLP, DIM, b1, nullptr);

    // FFN2: f @ w2 + b2 + residual(x2) -> out
    transpose_half_kernel<<<dim3(DIM/32, MLP/32), dim3(32, 8)>>>(w2, p_bh, MLP, DIM);
    wmma_gemm<2><<<dim3(DIM/128, MTOT/128), 256, SMEM_WG>>>(
        (const __half*)p_qhi, (const __half*)p_qlo, p_bh, out, nullptr, nullptr,
        MTOT, DIM, MLP, b2, p_x2);
}

// round 14
// speedup vs baseline: 2.5957x; 1.3762x over previous
#include <cuda_runtime.h>
#include <cuda_bf16.h>
#include <cuda_fp16.h>
#include <mma.h>
#include <math.h>
#include <cstdint>

using namespace nvcuda;

#define BATCH 4
#define SEQ 1024
#define DIM 1024
#define NHEADS 16
#define HDIM 64
#define MLP 4096
#define MTOT (BATCH*SEQ)        /* 4096 */
#define QKVW (5*NHEADS*HDIM)    /* 5120 */
#define ATTN_CLIP 100.0f
#define NORM_CLIP 1000.0f
#define EPSF 1e-6f

// ================= scratch =================
__device__ float g_x2 [MTOT*DIM];
__device__ __half g_ah [(size_t)MTOT*MLP];                   // GEMM A (h / o / h2) fp16
__device__ __nv_bfloat16 g_qhi[(size_t)MTOT*QKVW];           // qkv bf16 hi; later f (half)
__device__ __nv_bfloat16 g_qlo[(size_t)MTOT*QKVW];
__device__ __half g_bh [(size_t)QKVW*DIM];                   // weights^T fp16
__device__ __nv_bfloat16 g_vthi[(size_t)BATCH*NHEADS*HDIM*SEQ];
__device__ __nv_bfloat16 g_vtlo[(size_t)BATCH*NHEADS*HDIM*SEQ];
__device__ float g_part[BATCH*128];
__device__ float g_nx[BATCH];
__device__ float g_lam;

// ================= helpers =================
__device__ __forceinline__ uint32_t smem_u32(const void* p) {
    uint32_t a;
    asm("{ .reg .u64 t; cvta.to.shared.u64 t, %1; cvt.u32.u64 %0, t; }" : "=r"(a) : "l"(p));
    return a;
}
#define CP_ASYNC16(dst, src) \
    asm volatile("cp.async.cg.shared.global [%0], [%1], 16;" :: "r"(dst), "l"(src))
#define CP_COMMIT() asm volatile("cp.async.commit_group;" ::: "memory")
#define CP_WAIT(n)  asm volatile("cp.async.wait_group %0;" :: "n"(n) : "memory")

#define MMA_BF16(d, a, b) \
    asm volatile("mma.sync.aligned.m16n8k16.row.col.f32.bf16.bf16.f32 " \
        "{%0,%1,%2,%3}, {%4,%5,%6,%7}, {%8,%9}, {%0,%1,%2,%3};" \
        : "+f"((d)[0]), "+f"((d)[1]), "+f"((d)[2]), "+f"((d)[3]) \
        : "r"((a)[0]), "r"((a)[1]), "r"((a)[2]), "r"((a)[3]), \
          "r"((b)[0]), "r"((b)[1]))

// bf16 packers (attention path)
__device__ __forceinline__ uint32_t pk2(float x, float y) {
    __nv_bfloat162 t = __floats2bfloat162_rn(x, y);
    return *(uint32_t*)&t;
}
__device__ __forceinline__ uint32_t pk2lo(float x, float y, uint32_t hipk) {
    __nv_bfloat162 hp = *(__nv_bfloat162*)&hipk;
    return pk2(x - __bfloat162float(hp.x), y - __bfloat162float(hp.y));
}
// fp16 packer (GEMM path)
__device__ __forceinline__ uint32_t pk2h(float x, float y) {
    __half2 t = __floats2half2_rn(x, y);
    return *(uint32_t*)&t;
}

// ================= scalar kernels =================
__global__ void reduce_sq_kernel(const float* __restrict__ x) {
    const int b = blockIdx.y, blk = blockIdx.x;
    const int N = SEQ*DIM;
    const int per = N / 128;
    const float* p = x + (size_t)b*N + (size_t)blk*per;
    float s = 0.f;
    for (int i = threadIdx.x; i < per; i += 256) { float v = p[i]; s += v*v; }
    __shared__ float red[8];
    int lane = threadIdx.x & 31, w = threadIdx.x >> 5;
#pragma unroll
    for (int o = 16; o; o >>= 1) s += __shfl_down_sync(0xffffffffu, s, o);
    if (lane == 0) red[w] = s;
    __syncthreads();
    if (w == 0) {
        s = (lane < 8) ? red[lane] : 0.f;
#pragma unroll
        for (int o = 4; o; o >>= 1) s += __shfl_down_sync(0xffffffffu, s, o);
        if (lane == 0) g_part[b*128 + blk] = s;
    }
}

__global__ void compute_nx_kernel() {
    int b = threadIdx.x;
    if (b < BATCH) {
        float s = 0.f;
        for (int i = 0; i < 128; i++) s += g_part[b*128 + i];
        s = fminf(fmaxf(s, EPSF), NORM_CLIP);
        float gx = sqrtf(s);
        float nx = gx / (gx + EPSF);
        nx = fminf(fmaxf(nx, -NORM_CLIP), NORM_CLIP);
        g_nx[b] = nx;
    }
}

__global__ void compute_lam_kernel(const float* __restrict__ lq1, const float* __restrict__ lk1,
                                   const float* __restrict__ lq2, const float* __restrict__ lk2) {
    float s1 = 0.f, s2 = 0.f;
    for (int d = 0; d < HDIM; d++) { s1 += lq1[d]*lk1[d]; s2 += lq2[d]*lk2[d]; }
    s1 = fminf(fmaxf(s1, -10.f), 10.f);
    s2 = fminf(fmaxf(s2, -10.f), 10.f);
    float lam_init = 0.8f - 0.6f*expf(-0.0f);
    float lam = expf(s1) - expf(s2) + lam_init;
    g_lam = fminf(fmaxf(lam, 0.1f), 5.f);
}

// ================= GRN fused, fp16 output =================
__global__ void grn_half_kernel(const float* __restrict__ x, const float* __restrict__ gamma,
                                const float* __restrict__ beta, __half* __restrict__ o) {
    int idx = blockIdx.x*blockDim.x + threadIdx.x;
    int e = idx * 4;
    int b = e >> 20;
    int d = e & (DIM-1);
    float nx = g_nx[b];
    float4 xv = *(const float4*)(x + e);
    float4 gv = *(const float4*)(gamma + d);
    float4 bv = *(const float4*)(beta + d);
    float r0 = gv.x*(xv.x*nx) + bv.x + xv.x;
    float r1 = gv.y*(xv.y*nx) + bv.y + xv.y;
    float r2 = gv.z*(xv.z*nx) + bv.z + xv.z;
    float r3 = gv.w*(xv.w*nx) + bv.w + xv.w;
    uint2 ph;
    ph.x = pk2h(r0, r1); ph.y = pk2h(r2, r3);
    *(uint2*)(o + e) = ph;
}

// ================= weight transpose to fp16: w[K][N] -> t[N][K] =================
__global__ void transpose_half_kernel(const float* __restrict__ w,
                                      __half* __restrict__ th, int K, int N) {
    __shared__ float tile[32][33];
    int n0 = blockIdx.x * 32, k0 = blockIdx.y * 32;
    int tx = threadIdx.x, ty = threadIdx.y;
#pragma unroll
    for (int i = 0; i < 4; i++)
        tile[ty + i*8][tx] = w[(size_t)(k0 + ty + i*8)*N + n0 + tx];
    __syncthreads();
#pragma unroll
    for (int i = 0; i < 4; i++) {
        float v = tile[tx][ty + i*8];
        th[(size_t)(n0 + ty + i*8)*K + k0 + tx] = __float2half(v);
    }
}

// ================= V transpose (bf16, attention path) =================
__global__ void vtrans_kernel(const __nv_bfloat16* __restrict__ qHi,
                              const __nv_bfloat16* __restrict__ qLo,
                              __nv_bfloat16* __restrict__ vtHi,
                              __nv_bfloat16* __restrict__ vtLo) {
    __shared__ __nv_bfloat16 th[32][33], tl[32][33];
    const int b = blockIdx.z;
    const int t0 = blockIdx.x * 32;
    const int f0 = blockIdx.y * 32;
    const int tx = threadIdx.x, ty = threadIdx.y;
#pragma unroll
    for (int i = 0; i < 4; i++) {
        size_t src = (size_t)(b*SEQ + t0 + ty + i*8)*QKVW + 4096 + f0 + tx;
        th[ty + i*8][tx] = qHi[src];
        tl[ty + i*8][tx] = qLo[src];
    }
    __syncthreads();
#pragma unroll
    for (int i = 0; i < 4; i++) {
        int f = f0 + ty + i*8;
        int h = f >> 6, d = f & 63;
        size_t dst = ((size_t)(b*NHEADS + h)*HDIM + d)*SEQ + t0 + tx;
        vtHi[dst] = th[tx][ty + i*8];
        vtLo[dst] = tl[tx][ty + i*8];
    }
}

// ================= single-pass fp16 wmma GEMM =================
// D = A * B  (both rounded fp16, fp32 accumulate)
// EPI 2: fp32 C = acc+bias+res; EPI 4: bf16 hi/lo split(acc); EPI 5: fp16 silu(acc+bias)
#define KC 32
#define LDA 40
#define TILE_ELEMS (128*LDA)
#define BUF_ELEMS (2*TILE_ELEMS)     /* A, B */
#define SMEM_WG (128*132*4)          /* 67584 > 2*BUF_ELEMS*2 = 40960 */
#define SLD 132

template<int EPI>
__global__ __launch_bounds__(256, 2)
void wmma_gemm(const __half* __restrict__ A, const __half* __restrict__ B,
               float* __restrict__ C, void* __restrict__ CHv, void* __restrict__ CLv,
               int M, int N, int K,
               const float* __restrict__ bias, const float* __restrict__ res) {
    extern __shared__ char smem_raw[];
    __half* sm = (__half*)smem_raw;
    const uint32_t sm_addr = smem_u32(sm);

    const int tid = threadIdx.x;
    const int wid = tid >> 5;
    const int row0 = blockIdx.y * 128;
    const int col0 = blockIdx.x * 128;
    const int wr = (wid >> 1) * 32;
    const int wc = (wid & 1) * 64;

    const __half* gsrc[2] = { A + (size_t)row0*K, B + (size_t)col0*K };

    int u_arr[4], u_row[4], u_col[4];
#pragma unroll
    for (int i = 0; i < 4; i++) {
        int idx = tid + i*256;               // 0..1023 units of 16B
        u_arr[i] = idx >> 9;
        int rem = idx & 511;
        u_row[i] = rem >> 2;
        u_col[i] = (rem & 3) * 8;
    }

    auto issue_chunk = [&](int k0, int buf) {
        uint32_t dbase = sm_addr + (uint32_t)buf * (BUF_ELEMS*2);
#pragma unroll
        for (int i = 0; i < 4; i++) {
            const __half* src = gsrc[u_arr[i]] + (size_t)u_row[i]*K + k0 + u_col[i];
            uint32_t dst = dbase + (uint32_t)(u_arr[i]*TILE_ELEMS + u_row[i]*LDA + u_col[i]) * 2;
            CP_ASYNC16(dst, src);
        }
        CP_COMMIT();
    };

    wmma::fragment<wmma::accumulator, 16, 16, 16, float> acc[2][4];
#pragma unroll
    for (int i = 0; i < 2; i++)
#pragma unroll
        for (int j = 0; j < 4; j++) wmma::fill_fragment(acc[i][j], 0.f);

    const int nch = K / KC;
    issue_chunk(0, 0);

    for (int ch = 0; ch < nch; ch++) {
        const int cur = ch & 1;
        if (ch + 1 < nch) { issue_chunk((ch+1)*KC, cur ^ 1); CP_WAIT(1); }
        else              { CP_WAIT(0); }
        __syncthreads();

        const __half* b0 = sm + cur * BUF_ELEMS;
        const __half* tA = b0 + 0*TILE_ELEMS + wr*LDA;
        const __half* tB = b0 + 1*TILE_ELEMS + wc*LDA;

#pragma unroll
        for (int ks = 0; ks < 2; ks++) {
            wmma::fragment<wmma::matrix_a, 16, 16, 16, __half, wmma::row_major> aF[2];
            wmma::fragment<wmma::matrix_b, 16, 16, 16, __half, wmma::col_major> bF[4];
            const int ko = ks * 16;
#pragma unroll
            for (int i = 0; i < 2; i++)
                wmma::load_matrix_sync(aF[i], tA + i*16*LDA + ko, LDA);
#pragma unroll
            for (int j = 0; j < 4; j++)
                wmma::load_matrix_sync(bF[j], tB + j*16*LDA + ko, LDA);
#pragma unroll
            for (int i = 0; i < 2; i++)
#pragma unroll
                for (int j = 0; j < 4; j++)
                    wmma::mma_sync(acc[i][j], aF[i], bF[j], acc[i][j]);
        }
        __syncthreads();
    }

    float* stage = (float*)smem_raw;
#pragma unroll
    for (int i = 0; i < 2; i++)
#pragma unroll
        for (int j = 0; j < 4; j++)
            wmma::store_matrix_sync(stage + (wr + i*16)*SLD + wc + j*16,
                                    acc[i][j], SLD, wmma::mem_row_major);
    __syncthreads();

    const int r = tid >> 1;
    const int c0 = (tid & 1) * 64;
    const int row = row0 + r;

    if (EPI == 2) {
        size_t obase = (size_t)row*N + col0 + c0;
#pragma unroll
        for (int j = 0; j < 16; j++) {
            float4 v = *(float4*)(stage + r*SLD + c0 + j*4);
            float4 w;
            float* vi = (float*)&v; float* wi = (float*)&w;
#pragma unroll
            for (int q = 0; q < 4; q++)
                wi[q] = vi[q] + bias[col0 + c0 + j*4 + q] + res[obase + j*4 + q];
            *(float4*)(C + obase + j*4) = w;
        }
    } else if (EPI == 4) {
        // bf16 hi/lo split (attention input)
        __nv_bfloat16* dh = (__nv_bfloat16*)CHv + (size_t)row*N + col0 + c0;
        __nv_bfloat16* dl = (__nv_bfloat16*)CLv + (size_t)row*N + col0 + c0;
#pragma unroll
        for (int j = 0; j < 8; j++) {
            float t[8];
#pragma unroll
            for (int q = 0; q < 8; q++) t[q] = stage[r*SLD + c0 + j*8 + q];
            uint4 ph, pl;
            uint32_t* phi = (uint32_t*)&ph;
            uint32_t* pli = (uint32_t*)&pl;
#pragma unroll
            for (int q = 0; q < 4; q++) {
                phi[q] = pk2(t[2*q], t[2*q+1]);
                pli[q] = pk2lo(t[2*q], t[2*q+1], phi[q]);
            }
            *(uint4*)(dh + j*8) = ph;
            *(uint4*)(dl + j*8) = pl;
        }
    } else {
        // EPI 5: fp16 silu(acc+bias)
        __half* dh = (__half*)CHv + (size_t)row*N + col0 + c0;
#pragma unroll
        for (int j = 0; j < 8; j++) {
            float t[8];
#pragma unroll
            for (int q = 0; q < 8; q++) {
                float v = stage[r*SLD + c0 + j*8 + q] + bias[col0 + c0 + j*8 + q];
                t[q] = v / (1.f + __expf(-v));
            }
            uint4 ph;
            uint32_t* phi = (uint32_t*)&ph;
#pragma unroll
            for (int q = 0; q < 4; q++)
                phi[q] = pk2h(t[2*q], t[2*q+1]);
            *(uint4*)(dh + j*8) = ph;
        }
    }
}

// ================= tensor-core differential flash attention (bf16 3-pass, unchanged core) =================
#define AP 72
#define KVBUF 27648
#define TK1H 0
#define TK1L 4608
#define TK2H 9216
#define TK2L 13824
#define TVH  18432
#define TVL  23040
#define SMEM_ATT (2*KVBUF*2)

__device__ __forceinline__ void softmax_upd(float sc[8][4], float m[2], float l[2],
                                            float oc[8][4]) {
    float t0 = -1e30f, t1 = -1e30f;
#pragma unroll
    for (int nb = 0; nb < 8; nb++) {
        t0 = fmaxf(t0, fmaxf(sc[nb][0], sc[nb][1]));
        t1 = fmaxf(t1, fmaxf(sc[nb][2], sc[nb][3]));
    }
    t0 = fmaxf(t0, __shfl_xor_sync(0xffffffffu, t0, 1));
    t0 = fmaxf(t0, __shfl_xor_sync(0xffffffffu, t0, 2));
    t1 = fmaxf(t1, __shfl_xor_sync(0xffffffffu, t1, 1));
    t1 = fmaxf(t1, __shfl_xor_sync(0xffffffffu, t1, 2));
    float nm0 = fmaxf(m[0], t0), nm1 = fmaxf(m[1], t1);
    float c0 = __expf(m[0] - nm0), c1 = __expf(m[1] - nm1);
    float s0 = 0.f, s1 = 0.f;
#pragma unroll
    for (int nb = 0; nb < 8; nb++) {
        float p0 = __expf(sc[nb][0] - nm0); sc[nb][0] = p0; s0 += p0;
        float p1 = __expf(sc[nb][1] - nm0); sc[nb][1] = p1; s0 += p1;
        float p2 = __expf(sc[nb][2] - nm1); sc[nb][2] = p2; s1 += p2;
        float p3 = __expf(sc[nb][3] - nm1); sc[nb][3] = p3; s1 += p3;
    }
    s0 += __shfl_xor_sync(0xffffffffu, s0, 1);
    s0 += __shfl_xor_sync(0xffffffffu, s0, 2);
    s1 += __shfl_xor_sync(0xffffffffu, s1, 1);
    s1 += __shfl_xor_sync(0xffffffffu, s1, 2);
    l[0] = l[0]*c0 + s0;  l[1] = l[1]*c1 + s1;
#pragma unroll
    for (int db = 0; db < 8; db++) {
        oc[db][0] *= c0; oc[db][1] *= c0;
        oc[db][2] *= c1; oc[db][3] *= c1;
    }
    m[0] = nm0; m[1] = nm1;
}

__global__ __launch_bounds__(128)
void diff_attn_mma(const __nv_bfloat16* __restrict__ qHi, const __nv_bfloat16* __restrict__ qLo,
                   const __nv_bfloat16* __restrict__ vtHi, const __nv_bfloat16* __restrict__ vtLo,
                   __half* __restrict__ oH) {
    extern __shared__ __nv_bfloat16 sb[];
    const uint32_t smb = smem_u32(sb);
    const int tid = threadIdx.x;
    const int wid = tid >> 5, lane = tid & 31;
    const int g4 = lane >> 2, t4 = lane & 3;
    const int qt = blockIdx.x, h = blockIdx.y, b = blockIdx.z;
    const int q0 = qt * 64;
    const float lam = g_lam;

    auto ld_tile = [&](uint32_t tileEls, const __nv_bfloat16* src, int rowStride) {
#pragma unroll
        for (int i = 0; i < 4; i++) {
            int idx = tid + i*128;
            int r = idx >> 3, c8 = idx & 7;
            CP_ASYNC16(smb + tileEls*2 + r*144 + c8*16,
                       src + (size_t)r*rowStride + c8*8);
        }
    };

    // stage Q in buffer 0, hoist fragments to registers
    {
        const size_t qb = (size_t)(b*SEQ + q0)*QKVW + h*HDIM;
        ld_tile(TK1H, qHi + qb,        QKVW);
        ld_tile(TK1L, qLo + qb,        QKVW);
        ld_tile(TK2H, qHi + qb + 1024, QKVW);
        ld_tile(TK2L, qLo + qb + 1024, QKVW);
        CP_COMMIT();
        CP_WAIT(0);
        __syncthreads();
    }

    uint32_t qa1h[16], qa1l[16], qa2h[16], qa2l[16];
    {
        const int ar = wid*16 + g4;
#pragma unroll
        for (int dc = 0; dc < 4; dc++) {
            const int ac = dc*16 + t4*2;
            qa1h[dc*4+0] = *(const uint32_t*)&sb[TK1H + ar*AP + ac];
            qa1h[dc*4+1] = *(const uint32_t*)&sb[TK1H + (ar+8)*AP + ac];
            qa1h[dc*4+2] = *(const uint32_t*)&sb[TK1H + ar*AP + ac + 8];
            qa1h[dc*4+3] = *(const uint32_t*)&sb[TK1H + (ar+8)*AP + ac + 8];
            qa1l[dc*4+0] = *(const uint32_t*)&sb[TK1L + ar*AP + ac];
            qa1l[dc*4+1] = *(const uint32_t*)&sb[TK1L + (ar+8)*AP + ac];
            qa1l[dc*4+2] = *(const uint32_t*)&sb[TK1L + ar*AP + ac + 8];
            qa1l[dc*4+3] = *(const uint32_t*)&sb[TK1L + (ar+8)*AP + ac + 8];
            qa2h[dc*4+0] = *(const uint32_t*)&sb[TK2H + ar*AP + ac];
            qa2h[dc*4+1] = *(const uint32_t*)&sb[TK2H + (ar+8)*AP + ac];
            qa2h[dc*4+2] = *(const uint32_t*)&sb[TK2H + ar*AP + ac + 8];
            qa2h[dc*4+3] = *(const uint32_t*)&sb[TK2H + (ar+8)*AP + ac + 8];
            qa2l[dc*4+0] = *(const uint32_t*)&sb[TK2L + ar*AP + ac];
            qa2l[dc*4+1] = *(const uint32_t*)&sb[TK2L + (ar+8)*AP + ac];
            qa2l[dc*4+2] = *(const uint32_t*)&sb[TK2L + ar*AP + ac + 8];
            qa2l[dc*4+3] = *(const uint32_t*)&sb[TK2L + (ar+8)*AP + ac + 8];
        }
    }
    __syncthreads();

    const size_t kbase = (size_t)b*SEQ*QKVW + h*HDIM;
    const size_t vbase = ((size_t)(b*NHEADS + h)*HDIM)*SEQ;

    auto issue_kv = [&](int kt, int buf) {
        const uint32_t bo = (uint32_t)buf * KVBUF;
        const size_t kb = kbase + (size_t)(kt*64)*QKVW;
        const size_t vb = vbase + kt*64;
        ld_tile(bo + TK1H, qHi + kb + 2048, QKVW);
        ld_tile(bo + TK1L, qLo + kb + 2048, QKVW);
        ld_tile(bo + TK2H, qHi + kb + 3072, QKVW);
        ld_tile(bo + TK2L, qLo + kb + 3072, QKVW);
        ld_tile(bo + TVH,  vtHi + vb, SEQ);
        ld_tile(bo + TVL,  vtLo + vb, SEQ);
        CP_COMMIT();
    };

    issue_kv(0, 0);

    float oc1[8][4], oc2[8][4];
#pragma unroll
    for (int i = 0; i < 8; i++)
#pragma unroll
        for (int j = 0; j < 4; j++) { oc1[i][j] = 0.f; oc2[i][j] = 0.f; }
    float m1[2] = {-1e30f, -1e30f}, l1[2] = {0.f, 0.f};
    float m2[2] = {-1e30f, -1e30f}, l2[2] = {0.f, 0.f};

    for (int kt = 0; kt < 16; kt++) {
        const int cur = kt & 1;
        if (kt + 1 < 16) { issue_kv(kt + 1, cur ^ 1); CP_WAIT(1); }
        else             { CP_WAIT(0); }
        __syncthreads();

        const uint32_t kv = (uint32_t)cur * KVBUF;

        float sc1[8][4], sc2[8][4];
#pragma unroll
        for (int i = 0; i < 8; i++)
#pragma unroll
            for (int j = 0; j < 4; j++) { sc1[i][j] = 0.f; sc2[i][j] = 0.f; }

#pragma unroll
        for (int dc = 0; dc < 4; dc++) {
            const uint32_t* a1h = &qa1h[dc*4];
            const uint32_t* a1l = &qa1l[dc*4];
            const uint32_t* a2h = &qa2h[dc*4];
            const uint32_t* a2l = &qa2l[dc*4];
#pragma unroll
            for (int nb = 0; nb < 8; nb++) {
                const int bo = (nb*8 + g4)*AP + dc*16 + t4*2;
                uint32_t b1h[2], b1l[2], b2h[2], b2l[2];
                b1h[0] = *(const uint32_t*)&sb[kv + TK1H + bo];
                b1h[1] = *(const uint32_t*)&sb[kv + TK1H + bo + 8];
                b1l[0] = *(const uint32_t*)&sb[kv + TK1L + bo];
                b1l[1] = *(const uint32_t*)&sb[kv + TK1L + bo + 8];
                b2h[0] = *(const uint32_t*)&sb[kv + TK2H + bo];
                b2h[1] = *(const uint32_t*)&sb[kv + TK2H + bo + 8];
                b2l[0] = *(const uint32_t*)&sb[kv + TK2L + bo];
                b2l[1] = *(const uint32_t*)&sb[kv + TK2L + bo + 8];
                MMA_BF16(sc1[nb], a1h, b1h);
                MMA_BF16(sc1[nb], a1l, b1h);
                MMA_BF16(sc1[nb], a1h, b1l);
                MMA_BF16(sc2[nb], a2h, b2h);
                MMA_BF16(sc2[nb], a2l, b2h);
                MMA_BF16(sc2[nb], a2h, b2l);
            }
        }

#pragma unroll
        for (int nb = 0; nb < 8; nb++)
#pragma unroll
            for (int j = 0; j < 4; j++) {
                sc1[nb][j] = fminf(fmaxf(sc1[nb][j]*0.125f, -ATTN_CLIP), ATTN_CLIP);
                sc2[nb][j] = fminf(fmaxf(sc2[nb][j]*0.125f, -ATTN_CLIP), ATTN_CLIP);
            }

        softmax_upd(sc1, m1, l1, oc1);
        softmax_upd(sc2, m2, l2, oc2);

#pragma unroll
        for (int kc = 0; kc < 4; kc++) {
            uint32_t p1h[4], p1l[4], p2h[4], p2l[4];
            p1h[0] = pk2(sc1[2*kc][0],   sc1[2*kc][1]);
            p1h[1] = pk2(sc1[2*kc][2],   sc1[2*kc][3]);
            p1h[2] = pk2(sc1[2*kc+1][0], sc1[2*kc+1][1]);
            p1h[3] = pk2(sc1[2*kc+1][2], sc1[2*kc+1][3]);
            p1l[0] = pk2lo(sc1[2*kc][0],   sc1[2*kc][1],   p1h[0]);
            p1l[1] = pk2lo(sc1[2*kc][2],   sc1[2*kc][3],   p1h[1]);
            p1l[2] = pk2lo(sc1[2*kc+1][0], sc1[2*kc+1][1], p1h[2]);
            p1l[3] = pk2lo(sc1[2*kc+1][2], sc1[2*kc+1][3], p1h[3]);
            p2h[0] = pk2(sc2[2*kc][0],   sc2[2*kc][1]);
            p2h[1] = pk2(sc2[2*kc][2],   sc2[2*kc][3]);
            p2h[2] = pk2(sc2[2*kc+1][0], sc2[2*kc+1][1]);
            p2h[3] = pk2(sc2[2*kc+1][2], sc2[2*kc+1][3]);
            p2l[0] = pk2lo(sc2[2*kc][0],   sc2[2*kc][1],   p2h[0]);
            p2l[1] = pk2lo(sc2[2*kc][2],   sc2[2*kc][3],   p2h[1]);
            p2l[2] = pk2lo(sc2[2*kc+1][0], sc2[2*kc+1][1], p2h[2]);
            p2l[3] = pk2lo(sc2[2*kc+1][2], sc2[2*kc+1][3], p2h[3]);
#pragma unroll
            for (int db = 0; db < 8; db++) {
                const int vo = (db*8 + g4)*AP + kc*16 + t4*2;
                uint32_t bvh[2], bvl[2];
                bvh[0] = *(const uint32_t*)&sb[kv + TVH + vo];
                bvh[1] = *(const uint32_t*)&sb[kv + TVH + vo + 8];
                bvl[0] = *(const uint32_t*)&sb[kv + TVL + vo];
                bvl[1] = *(const uint32_t*)&sb[kv + TVL + vo + 8];
                MMA_BF16(oc1[db], p1h, bvh);
                MMA_BF16(oc1[db], p1l, bvh);
                MMA_BF16(oc1[db], p1h, bvl);
                MMA_BF16(oc2[db], p2h, bvh);
                MMA_BF16(oc2[db], p2l, bvh);
                MMA_BF16(oc2[db], p2h, bvl);
            }
        }
        __syncthreads();
    }

    // epilogue: combine streams -> fp16 (proj GEMM input)
    const float i10 = 1.f/(l1[0]+EPSF), i11 = 1.f/(l1[1]+EPSF);
    const float i20 = 1.f/(l2[0]+EPSF), i21 = 1.f/(l2[1]+EPSF);
    const int r0 = q0 + wid*16 + g4;
    size_t ob0 = ((size_t)b*SEQ + r0)*DIM + (size_t)h*HDIM;
    size_t ob1 = ob0 + (size_t)8*DIM;
#pragma unroll
    for (int db = 0; db < 8; db++) {
        const int c = db*8 + t4*2;
        float v0 = oc1[db][0]*i10 - lam*(oc2[db][0]*i20);
        float v1 = oc1[db][1]*i10 - lam*(oc2[db][1]*i20);
        float v2 = oc1[db][2]*i11 - lam*(oc2[db][2]*i21);
        float v3 = oc1[db][3]*i11 - lam*(oc2[db][3]*i21);
        *(uint32_t*)(oH + ob0 + c) = pk2h(v0, v1);
        *(uint32_t*)(oH + ob1 + c) = pk2h(v2, v3);
    }
}

// ================= launch =================
extern "C" void kernel_launch(void* const* d_in, const int* in_sizes, int n_in,
                              void* d_out, int out_size) {
    const float* x      = (const float*)d_in[0];
    const float* w_qkv  = (const float*)d_in[1];
    const float* lq1    = (const float*)d_in[2];
    const float* lk1    = (const float*)d_in[3];
    const float* lq2    = (const float*)d_in[4];
    const float* lk2    = (const float*)d_in[5];
    const float* w_proj = (const float*)d_in[6];
    const float* b_proj = (const float*)d_in[7];
    const float* gamma1 = (const float*)d_in[8];
    const float* beta1  = (const float*)d_in[9];
    const float* gamma2 = (const float*)d_in[10];
    const float* beta2  = (const float*)d_in[11];
    const float* w1     = (const float*)d_in[12];
    const float* b1     = (const float*)d_in[13];
    const float* w2     = (const float*)d_in[14];
    const float* b2     = (const float*)d_in[15];
    float* out = (float*)d_out;

    float *p_x2;
    __half *p_ah, *p_bh;
    __nv_bfloat16 *p_qhi, *p_qlo, *p_vthi, *p_vtlo;
    cudaGetSymbolAddress((void**)&p_x2,   g_x2);
    cudaGetSymbolAddress((void**)&p_ah,   g_ah);
    cudaGetSymbolAddress((void**)&p_qhi,  g_qhi);
    cudaGetSymbolAddress((void**)&p_qlo,  g_qlo);
    cudaGetSymbolAddress((void**)&p_bh,   g_bh);
    cudaGetSymbolAddress((void**)&p_vthi, g_vthi);
    cudaGetSymbolAddress((void**)&p_vtlo, g_vtlo);

    cudaFuncSetAttribute(diff_attn_mma,
                         cudaFuncAttributeMaxDynamicSharedMemorySize, SMEM_ATT);
    cudaFuncSetAttribute(wmma_gemm<2>, cudaFuncAttributeMaxDynamicSharedMemorySize, SMEM_WG);
    cudaFuncSetAttribute(wmma_gemm<4>, cudaFuncAttributeMaxDynamicSharedMemorySize, SMEM_WG);
    cudaFuncSetAttribute(wmma_gemm<5>, cudaFuncAttributeMaxDynamicSharedMemorySize, SMEM_WG);

    // scalars
    reduce_sq_kernel<<<dim3(128, BATCH), 256>>>(x);
    compute_nx_kernel<<<1, 32>>>();
    compute_lam_kernel<<<1, 1>>>(lq1, lk1, lq2, lk2);

    // GRN1 -> h fp16
    grn_half_kernel<<<(MTOT*DIM)/4/256, 256>>>(x, gamma1, beta1, p_ah);

    // QKV GEMM -> qkv bf16 hi/lo (attention input)
    transpose_half_kernel<<<dim3(QKVW/32, DIM/32), dim3(32, 8)>>>(w_qkv, p_bh, DIM, QKVW);
    wmma_gemm<4><<<dim3(QKVW/128, MTOT/128), 256, SMEM_WG>>>(
        p_ah, p_bh, nullptr, p_qhi, p_qlo, MTOT, QKVW, DIM, nullptr, nullptr);

    // V transpose -> vt[bh][d][kk] (bf16)
    vtrans_kernel<<<dim3(SEQ/32, 32, BATCH), dim3(32, 8)>>>(p_qhi, p_qlo, p_vthi, p_vtlo);

    // attention -> o fp16 (into a array)
    diff_attn_mma<<<dim3(SEQ/64, NHEADS, BATCH), 128, SMEM_ATT>>>(
        p_qhi, p_qlo, p_vthi, p_vtlo, p_ah);

    // proj + bias + residual(x) -> x2 fp32
    transpose_half_kernel<<<dim3(DIM/32, DIM/32), dim3(32, 8)>>>(w_proj, p_bh, DIM, DIM);
    wmma_gemm<2><<<dim3(DIM/128, MTOT/128), 256, SMEM_WG>>>(
        p_ah, p_bh, p_x2, nullptr, nullptr, MTOT, DIM, DIM, b_proj, x);

    // GRN2 -> h2 fp16
    reduce_sq_kernel<<<dim3(128, BATCH), 256>>>(p_x2);
    compute_nx_kernel<<<1, 32>>>();
    grn_half_kernel<<<(MTOT*DIM)/4/256, 256>>>(p_x2, gamma2, beta2, p_ah);

    // FFN1: silu(h2 @ w1 + b1) -> f fp16 (into q array)
    transpose_half_kernel<<<dim3(MLP/32, DIM/32), dim3(32, 8)>>>(w1, p_bh, DIM, MLP);
    wmma_gemm<5><<<dim3(MLP/128, MTOT/128), 256, SMEM_WG>>>(
        p_ah, p_bh, nullptr, (void*)p_qhi, nullptr, MTOT, MLP, DIM, b1, nullptr);

    // FFN2: f @ w2 + b2 + residual(x2) -> out
    transpose_half_kernel<<<dim3(DIM/32, MLP/32), dim3(32, 8)>>>(w2, p_bh, MLP, DIM);
    wmma_gemm<2><<<dim3(DIM/128, MTOT/128), 256, SMEM_WG>>>(
        (const __half*)p_qhi, p_bh, out, nullptr, nullptr, MTOT, DIM, MLP, b2, p_x2);
}

// round 16
// speedup vs baseline: 2.9081x; 1.1204x over previous
#include <cuda_runtime.h>
#include <cuda_bf16.h>
#include <cuda_fp16.h>
#include <mma.h>
#include <math.h>
#include <cstdint>

using namespace nvcuda;

#define BATCH 4
#define SEQ 1024
#define DIM 1024
#define NHEADS 16
#define HDIM 64
#define MLP 4096
#define MTOT (BATCH*SEQ)        /* 4096 */
#define QKVW (5*NHEADS*HDIM)    /* 5120 */
#define ATTN_CLIP 100.0f
#define NORM_CLIP 1000.0f
#define EPSF 1e-6f

// ================= scratch =================
__device__ float g_x2 [MTOT*DIM];
__device__ __half g_ah [(size_t)MTOT*MLP];                   // GEMM A (h / o / h2) fp16
__device__ __nv_bfloat16 g_qhi[(size_t)MTOT*QKVW];           // qkv bf16 hi; later f (half)
__device__ __nv_bfloat16 g_qlo[(size_t)MTOT*QKVW];
__device__ __half g_bh [(size_t)QKVW*DIM];                   // weights^T fp16
__device__ __half g_vt [(size_t)BATCH*NHEADS*HDIM*SEQ];      // V^T fp16
__device__ float g_part[BATCH*128];
__device__ float g_nx[BATCH];
__device__ float g_lam;

// ================= helpers =================
__device__ __forceinline__ uint32_t smem_u32(const void* p) {
    uint32_t a;
    asm("{ .reg .u64 t; cvta.to.shared.u64 t, %1; cvt.u32.u64 %0, t; }" : "=r"(a) : "l"(p));
    return a;
}
#define CP_ASYNC16(dst, src) \
    asm volatile("cp.async.cg.shared.global [%0], [%1], 16;" :: "r"(dst), "l"(src))
#define CP_COMMIT() asm volatile("cp.async.commit_group;" ::: "memory")
#define CP_WAIT(n)  asm volatile("cp.async.wait_group %0;" :: "n"(n) : "memory")

#define MMA_BF16(d, a, b) \
    asm volatile("mma.sync.aligned.m16n8k16.row.col.f32.bf16.bf16.f32 " \
        "{%0,%1,%2,%3}, {%4,%5,%6,%7}, {%8,%9}, {%0,%1,%2,%3};" \
        : "+f"((d)[0]), "+f"((d)[1]), "+f"((d)[2]), "+f"((d)[3]) \
        : "r"((a)[0]), "r"((a)[1]), "r"((a)[2]), "r"((a)[3]), \
          "r"((b)[0]), "r"((b)[1]))

#define MMA_FP16(d, a, b) \
    asm volatile("mma.sync.aligned.m16n8k16.row.col.f32.f16.f16.f32 " \
        "{%0,%1,%2,%3}, {%4,%5,%6,%7}, {%8,%9}, {%0,%1,%2,%3};" \
        : "+f"((d)[0]), "+f"((d)[1]), "+f"((d)[2]), "+f"((d)[3]) \
        : "r"((a)[0]), "r"((a)[1]), "r"((a)[2]), "r"((a)[3]), \
          "r"((b)[0]), "r"((b)[1]))

// bf16 packers (attention QK path)
__device__ __forceinline__ uint32_t pk2(float x, float y) {
    __nv_bfloat162 t = __floats2bfloat162_rn(x, y);
    return *(uint32_t*)&t;
}
__device__ __forceinline__ uint32_t pk2lo(float x, float y, uint32_t hipk) {
    __nv_bfloat162 hp = *(__nv_bfloat162*)&hipk;
    return pk2(x - __bfloat162float(hp.x), y - __bfloat162float(hp.y));
}
// fp16 packers
__device__ __forceinline__ uint32_t pk2h(float x, float y) {
    __half2 t = __floats2half2_rn(x, y);
    return *(uint32_t*)&t;
}
__device__ __forceinline__ uint32_t pk2hlo(float x, float y, uint32_t hipk) {
    __half2 hp = *(__half2*)&hipk;
    return pk2h(x - __half2float(hp.x), y - __half2float(hp.y));
}

// ================= scalar kernels =================
__global__ void reduce_sq_kernel(const float* __restrict__ x) {
    const int b = blockIdx.y, blk = blockIdx.x;
    const int N = SEQ*DIM;
    const int per = N / 128;
    const float* p = x + (size_t)b*N + (size_t)blk*per;
    float s = 0.f;
    for (int i = threadIdx.x; i < per; i += 256) { float v = p[i]; s += v*v; }
    __shared__ float red[8];
    int lane = threadIdx.x & 31, w = threadIdx.x >> 5;
#pragma unroll
    for (int o = 16; o; o >>= 1) s += __shfl_down_sync(0xffffffffu, s, o);
    if (lane == 0) red[w] = s;
    __syncthreads();
    if (w == 0) {
        s = (lane < 8) ? red[lane] : 0.f;
#pragma unroll
        for (int o = 4; o; o >>= 1) s += __shfl_down_sync(0xffffffffu, s, o);
        if (lane == 0) g_part[b*128 + blk] = s;
    }
}

__global__ void compute_nx_kernel() {
    int b = threadIdx.x;
    if (b < BATCH) {
        float s = 0.f;
        for (int i = 0; i < 128; i++) s += g_part[b*128 + i];
        s = fminf(fmaxf(s, EPSF), NORM_CLIP);
        float gx = sqrtf(s);
        float nx = gx / (gx + EPSF);
        nx = fminf(fmaxf(nx, -NORM_CLIP), NORM_CLIP);
        g_nx[b] = nx;
    }
}

__global__ void compute_lam_kernel(const float* __restrict__ lq1, const float* __restrict__ lk1,
                                   const float* __restrict__ lq2, const float* __restrict__ lk2) {
    float s1 = 0.f, s2 = 0.f;
    for (int d = 0; d < HDIM; d++) { s1 += lq1[d]*lk1[d]; s2 += lq2[d]*lk2[d]; }
    s1 = fminf(fmaxf(s1, -10.f), 10.f);
    s2 = fminf(fmaxf(s2, -10.f), 10.f);
    float lam_init = 0.8f - 0.6f*expf(-0.0f);
    float lam = expf(s1) - expf(s2) + lam_init;
    g_lam = fminf(fmaxf(lam, 0.1f), 5.f);
}

// ================= GRN fused, fp16 output =================
__global__ void grn_half_kernel(const float* __restrict__ x, const float* __restrict__ gamma,
                                const float* __restrict__ beta, __half* __restrict__ o) {
    int idx = blockIdx.x*blockDim.x + threadIdx.x;
    int e = idx * 4;
    int b = e >> 20;
    int d = e & (DIM-1);
    float nx = g_nx[b];
    float4 xv = *(const float4*)(x + e);
    float4 gv = *(const float4*)(gamma + d);
    float4 bv = *(const float4*)(beta + d);
    float r0 = gv.x*(xv.x*nx) + bv.x + xv.x;
    float r1 = gv.y*(xv.y*nx) + bv.y + xv.y;
    float r2 = gv.z*(xv.z*nx) + bv.z + xv.z;
    float r3 = gv.w*(xv.w*nx) + bv.w + xv.w;
    uint2 ph;
    ph.x = pk2h(r0, r1); ph.y = pk2h(r2, r3);
    *(uint2*)(o + e) = ph;
}

// ================= weight transpose to fp16: w[K][N] -> t[N][K] =================
__global__ void transpose_half_kernel(const float* __restrict__ w,
                                      __half* __restrict__ th, int K, int N) {
    __shared__ float tile[32][33];
    int n0 = blockIdx.x * 32, k0 = blockIdx.y * 32;
    int tx = threadIdx.x, ty = threadIdx.y;
#pragma unroll
    for (int i = 0; i < 4; i++)
        tile[ty + i*8][tx] = w[(size_t)(k0 + ty + i*8)*N + n0 + tx];
    __syncthreads();
#pragma unroll
    for (int i = 0; i < 4; i++) {
        float v = tile[tx][ty + i*8];
        th[(size_t)(n0 + ty + i*8)*K + k0 + tx] = __float2half(v);
    }
}

// ================= V transpose -> single fp16 vt[bh][d][kk] =================
__global__ void vtrans_kernel(const __nv_bfloat16* __restrict__ qHi,
                              const __nv_bfloat16* __restrict__ qLo,
                              __half* __restrict__ vt) {
    __shared__ float tv[32][33];
    const int b = blockIdx.z;
    const int t0 = blockIdx.x * 32;
    const int f0 = blockIdx.y * 32;
    const int tx = threadIdx.x, ty = threadIdx.y;
#pragma unroll
    for (int i = 0; i < 4; i++) {
        size_t src = (size_t)(b*SEQ + t0 + ty + i*8)*QKVW + 4096 + f0 + tx;
        tv[ty + i*8][tx] = __bfloat162float(qHi[src]) + __bfloat162float(qLo[src]);
    }
    __syncthreads();
#pragma unroll
    for (int i = 0; i < 4; i++) {
        int f = f0 + ty + i*8;
        int h = f >> 6, d = f & 63;
        size_t dst = ((size_t)(b*NHEADS + h)*HDIM + d)*SEQ + t0 + tx;
        vt[dst] = __float2half(tv[tx][ty + i*8]);
    }
}

// ================= single-pass fp16 wmma GEMM, K-chunk 64 =================
// EPI 2: fp32 C = acc+bias+res; EPI 4: bf16 hi/lo split(acc); EPI 5: fp16 silu(acc+bias)
#define KC 64
#define LDA 72
#define TILE_ELEMS (128*LDA)         /* 9216 */
#define BUF_ELEMS (2*TILE_ELEMS)     /* A, B: 18432 elems = 36864 B */
#define SMEM_WG (2*BUF_ELEMS*2)      /* 73728 B > stage 67584 B */
#define SLD 132

template<int EPI>
__global__ __launch_bounds__(256, 2)
void wmma_gemm(const __half* __restrict__ A, const __half* __restrict__ B,
               float* __restrict__ C, void* __restrict__ CHv, void* __restrict__ CLv,
               int M, int N, int K,
               const float* __restrict__ bias, const float* __restrict__ res) {
    extern __shared__ char smem_raw[];
    __half* sm = (__half*)smem_raw;
    const uint32_t sm_addr = smem_u32(sm);

    const int tid = threadIdx.x;
    const int wid = tid >> 5;
    const int row0 = blockIdx.y * 128;
    const int col0 = blockIdx.x * 128;
    const int wr = (wid >> 1) * 32;
    const int wc = (wid & 1) * 64;

    const __half* gsrc[2] = { A + (size_t)row0*K, B + (size_t)col0*K };

    int u_arr[8], u_row[8], u_col[8];
#pragma unroll
    for (int i = 0; i < 8; i++) {
        int idx = tid + i*256;               // 0..2047 units of 16B
        u_arr[i] = idx >> 10;
        int rem = idx & 1023;
        u_row[i] = rem >> 3;
        u_col[i] = (rem & 7) * 8;
    }

    auto issue_chunk = [&](int k0, int buf) {
        uint32_t dbase = sm_addr + (uint32_t)buf * (BUF_ELEMS*2);
#pragma unroll
        for (int i = 0; i < 8; i++) {
            const __half* src = gsrc[u_arr[i]] + (size_t)u_row[i]*K + k0 + u_col[i];
            uint32_t dst = dbase + (uint32_t)(u_arr[i]*TILE_ELEMS + u_row[i]*LDA + u_col[i]) * 2;
            CP_ASYNC16(dst, src);
        }
        CP_COMMIT();
    };

    wmma::fragment<wmma::accumulator, 16, 16, 16, float> acc[2][4];
#pragma unroll
    for (int i = 0; i < 2; i++)
#pragma unroll
        for (int j = 0; j < 4; j++) wmma::fill_fragment(acc[i][j], 0.f);

    const int nch = K / KC;
    issue_chunk(0, 0);

    for (int ch = 0; ch < nch; ch++) {
        const int cur = ch & 1;
        if (ch + 1 < nch) { issue_chunk((ch+1)*KC, cur ^ 1); CP_WAIT(1); }
        else              { CP_WAIT(0); }
        __syncthreads();

        const __half* b0 = sm + cur * BUF_ELEMS;
        const __half* tA = b0 + 0*TILE_ELEMS + wr*LDA;
        const __half* tB = b0 + 1*TILE_ELEMS + wc*LDA;

#pragma unroll
        for (int ks = 0; ks < 4; ks++) {
            wmma::fragment<wmma::matrix_a, 16, 16, 16, __half, wmma::row_major> aF[2];
            wmma::fragment<wmma::matrix_b, 16, 16, 16, __half, wmma::col_major> bF[4];
            const int ko = ks * 16;
#pragma unroll
            for (int i = 0; i < 2; i++)
                wmma::load_matrix_sync(aF[i], tA + i*16*LDA + ko, LDA);
#pragma unroll
            for (int j = 0; j < 4; j++)
                wmma::load_matrix_sync(bF[j], tB + j*16*LDA + ko, LDA);
#pragma unroll
            for (int i = 0; i < 2; i++)
#pragma unroll
                for (int j = 0; j < 4; j++)
                    wmma::mma_sync(acc[i][j], aF[i], bF[j], acc[i][j]);
        }
        __syncthreads();
    }

    float* stage = (float*)smem_raw;
#pragma unroll
    for (int i = 0; i < 2; i++)
#pragma unroll
        for (int j = 0; j < 4; j++)
            wmma::store_matrix_sync(stage + (wr + i*16)*SLD + wc + j*16,
                                    acc[i][j], SLD, wmma::mem_row_major);
    __syncthreads();

    const int r = tid >> 1;
    const int c0 = (tid & 1) * 64;
    const int row = row0 + r;

    if (EPI == 2) {
        size_t obase = (size_t)row*N + col0 + c0;
#pragma unroll
        for (int j = 0; j < 16; j++) {
            float4 v = *(float4*)(stage + r*SLD + c0 + j*4);
            float4 w;
            float* vi = (float*)&v; float* wi = (float*)&w;
#pragma unroll
            for (int q = 0; q < 4; q++)
                wi[q] = vi[q] + bias[col0 + c0 + j*4 + q] + res[obase + j*4 + q];
            *(float4*)(C + obase + j*4) = w;
        }
    } else if (EPI == 4) {
        __nv_bfloat16* dh = (__nv_bfloat16*)CHv + (size_t)row*N + col0 + c0;
        __nv_bfloat16* dl = (__nv_bfloat16*)CLv + (size_t)row*N + col0 + c0;
#pragma unroll
        for (int j = 0; j < 8; j++) {
            float t[8];
#pragma unroll
            for (int q = 0; q < 8; q++) t[q] = stage[r*SLD + c0 + j*8 + q];
            uint4 ph, pl;
            uint32_t* phi = (uint32_t*)&ph;
            uint32_t* pli = (uint32_t*)&pl;
#pragma unroll
            for (int q = 0; q < 4; q++) {
                phi[q] = pk2(t[2*q], t[2*q+1]);
                pli[q] = pk2lo(t[2*q], t[2*q+1], phi[q]);
            }
            *(uint4*)(dh + j*8) = ph;
            *(uint4*)(dl + j*8) = pl;
        }
    } else {
        __half* dh = (__half*)CHv + (size_t)row*N + col0 + c0;
#pragma unroll
        for (int j = 0; j < 8; j++) {
            float t[8];
#pragma unroll
            for (int q = 0; q < 8; q++) {
                float v = stage[r*SLD + c0 + j*8 + q] + bias[col0 + c0 + j*8 + q];
                t[q] = v / (1.f + __expf(-v));
            }
            uint4 ph;
            uint32_t* phi = (uint32_t*)&ph;
#pragma unroll
            for (int q = 0; q < 4; q++)
                phi[q] = pk2h(t[2*q], t[2*q+1]);
            *(uint4*)(dh + j*8) = ph;
        }
    }
}

// ================= differential flash attention: bf16 3-pass QK, fp16 2-pass PV =================
#define AP 72
#define KVBUF 23040            /* 5 tiles: K1h,K1l,K2h,K2l,V(fp16) */
#define TK1H 0
#define TK1L 4608
#define TK2H 9216
#define TK2L 13824
#define TVH  18432
#define SMEM_ATT (2*KVBUF*2)   /* 92160 B */

__device__ __forceinline__ void softmax_upd(float sc[8][4], float m[2], float l[2],
                                            float oc[8][4]) {
    float t0 = -1e30f, t1 = -1e30f;
#pragma unroll
    for (int nb = 0; nb < 8; nb++) {
        t0 = fmaxf(t0, fmaxf(sc[nb][0], sc[nb][1]));
        t1 = fmaxf(t1, fmaxf(sc[nb][2], sc[nb][3]));
    }
    t0 = fmaxf(t0, __shfl_xor_sync(0xffffffffu, t0, 1));
    t0 = fmaxf(t0, __shfl_xor_sync(0xffffffffu, t0, 2));
    t1 = fmaxf(t1, __shfl_xor_sync(0xffffffffu, t1, 1));
    t1 = fmaxf(t1, __shfl_xor_sync(0xffffffffu, t1, 2));
    float nm0 = fmaxf(m[0], t0), nm1 = fmaxf(m[1], t1);
    float c0 = __expf(m[0] - nm0), c1 = __expf(m[1] - nm1);
    float s0 = 0.f, s1 = 0.f;
#pragma unroll
    for (int nb = 0; nb < 8; nb++) {
        float p0 = __expf(sc[nb][0] - nm0); sc[nb][0] = p0; s0 += p0;
        float p1 = __expf(sc[nb][1] - nm0); sc[nb][1] = p1; s0 += p1;
        float p2 = __expf(sc[nb][2] - nm1); sc[nb][2] = p2; s1 += p2;
        float p3 = __expf(sc[nb][3] - nm1); sc[nb][3] = p3; s1 += p3;
    }
    s0 += __shfl_xor_sync(0xffffffffu, s0, 1);
    s0 += __shfl_xor_sync(0xffffffffu, s0, 2);
    s1 += __shfl_xor_sync(0xffffffffu, s1, 1);
    s1 += __shfl_xor_sync(0xffffffffu, s1, 2);
    l[0] = l[0]*c0 + s0;  l[1] = l[1]*c1 + s1;
#pragma unroll
    for (int db = 0; db < 8; db++) {
        oc[db][0] *= c0; oc[db][1] *= c0;
        oc[db][2] *= c1; oc[db][3] *= c1;
    }
    m[0] = nm0; m[1] = nm1;
}

__global__ __launch_bounds__(128)
void diff_attn_mma(const __nv_bfloat16* __restrict__ qHi, const __nv_bfloat16* __restrict__ qLo,
                   const __half* __restrict__ vt, __half* __restrict__ oH) {
    extern __shared__ __nv_bfloat16 sb[];
    const uint32_t smb = smem_u32(sb);
    const int tid = threadIdx.x;
    const int wid = tid >> 5, lane = tid & 31;
    const int g4 = lane >> 2, t4 = lane & 3;
    const int qt = blockIdx.x, h = blockIdx.y, b = blockIdx.z;
    const int q0 = qt * 64;
    const float lam = g_lam;

    auto ld_tile = [&](uint32_t tileEls, const void* src, int rowStrideBytes) {
#pragma unroll
        for (int i = 0; i < 4; i++) {
            int idx = tid + i*128;
            int r = idx >> 3, c8 = idx & 7;
            CP_ASYNC16(smb + tileEls*2 + r*144 + c8*16,
                       (const char*)src + (size_t)r*rowStrideBytes + c8*16);
        }
    };

    // stage Q in buffer 0, hoist fragments to registers
    {
        const size_t qb = (size_t)(b*SEQ + q0)*QKVW + h*HDIM;
        ld_tile(TK1H, qHi + qb,        QKVW*2);
        ld_tile(TK1L, qLo + qb,        QKVW*2);
        ld_tile(TK2H, qHi + qb + 1024, QKVW*2);
        ld_tile(TK2L, qLo + qb + 1024, QKVW*2);
        CP_COMMIT();
        CP_WAIT(0);
        __syncthreads();
    }

    uint32_t qa1h[16], qa1l[16], qa2h[16], qa2l[16];
    {
        const int ar = wid*16 + g4;
#pragma unroll
        for (int dc = 0; dc < 4; dc++) {
            const int ac = dc*16 + t4*2;
            qa1h[dc*4+0] = *(const uint32_t*)&sb[TK1H + ar*AP + ac];
            qa1h[dc*4+1] = *(const uint32_t*)&sb[TK1H + (ar+8)*AP + ac];
            qa1h[dc*4+2] = *(const uint32_t*)&sb[TK1H + ar*AP + ac + 8];
            qa1h[dc*4+3] = *(const uint32_t*)&sb[TK1H + (ar+8)*AP + ac + 8];
            qa1l[dc*4+0] = *(const uint32_t*)&sb[TK1L + ar*AP + ac];
            qa1l[dc*4+1] = *(const uint32_t*)&sb[TK1L + (ar+8)*AP + ac];
            qa1l[dc*4+2] = *(const uint32_t*)&sb[TK1L + ar*AP + ac + 8];
            qa1l[dc*4+3] = *(const uint32_t*)&sb[TK1L + (ar+8)*AP + ac + 8];
            qa2h[dc*4+0] = *(const uint32_t*)&sb[TK2H + ar*AP + ac];
            qa2h[dc*4+1] = *(const uint32_t*)&sb[TK2H + (ar+8)*AP + ac];
            qa2h[dc*4+2] = *(const uint32_t*)&sb[TK2H + ar*AP + ac + 8];
            qa2h[dc*4+3] = *(const uint32_t*)&sb[TK2H + (ar+8)*AP + ac + 8];
            qa2l[dc*4+0] = *(const uint32_t*)&sb[TK2L + ar*AP + ac];
            qa2l[dc*4+1] = *(const uint32_t*)&sb[TK2L + (ar+8)*AP + ac];
            qa2l[dc*4+2] = *(const uint32_t*)&sb[TK2L + ar*AP + ac + 8];
            qa2l[dc*4+3] = *(const uint32_t*)&sb[TK2L + (ar+8)*AP + ac + 8];
        }
    }
    __syncthreads();

    const size_t kbase = (size_t)b*SEQ*QKVW + h*HDIM;
    const size_t vbase = ((size_t)(b*NHEADS + h)*HDIM)*SEQ;

    auto issue_kv = [&](int kt, int buf) {
        const uint32_t bo = (uint32_t)buf * KVBUF;
        const size_t kb = kbase + (size_t)(kt*64)*QKVW;
        const size_t vb = vbase + kt*64;
        ld_tile(bo + TK1H, qHi + kb + 2048, QKVW*2);
        ld_tile(bo + TK1L, qLo + kb + 2048, QKVW*2);
        ld_tile(bo + TK2H, qHi + kb + 3072, QKVW*2);
        ld_tile(bo + TK2L, qLo + kb + 3072, QKVW*2);
        ld_tile(bo + TVH,  vt + vb, SEQ*2);
        CP_COMMIT();
    };

    issue_kv(0, 0);

    float oc1[8][4], oc2[8][4];
#pragma unroll
    for (int i = 0; i < 8; i++)
#pragma unroll
        for (int j = 0; j < 4; j++) { oc1[i][j] = 0.f; oc2[i][j] = 0.f; }
    float m1[2] = {-1e30f, -1e30f}, l1[2] = {0.f, 0.f};
    float m2[2] = {-1e30f, -1e30f}, l2[2] = {0.f, 0.f};

    for (int kt = 0; kt < 16; kt++) {
        const int cur = kt & 1;
        if (kt + 1 < 16) { issue_kv(kt + 1, cur ^ 1); CP_WAIT(1); }
        else             { CP_WAIT(0); }
        __syncthreads();

        const uint32_t kv = (uint32_t)cur * KVBUF;

        float sc1[8][4], sc2[8][4];
#pragma unroll
        for (int i = 0; i < 8; i++)
#pragma unroll
            for (int j = 0; j < 4; j++) { sc1[i][j] = 0.f; sc2[i][j] = 0.f; }

#pragma unroll
        for (int dc = 0; dc < 4; dc++) {
            const uint32_t* a1h = &qa1h[dc*4];
            const uint32_t* a1l = &qa1l[dc*4];
            const uint32_t* a2h = &qa2h[dc*4];
            const uint32_t* a2l = &qa2l[dc*4];
#pragma unroll
            for (int nb = 0; nb < 8; nb++) {
                const int bo = (nb*8 + g4)*AP + dc*16 + t4*2;
                uint32_t b1h[2], b1l[2], b2h[2], b2l[2];
                b1h[0] = *(const uint32_t*)&sb[kv + TK1H + bo];
                b1h[1] = *(const uint32_t*)&sb[kv + TK1H + bo + 8];
                b1l[0] = *(const uint32_t*)&sb[kv + TK1L + bo];
                b1l[1] = *(const uint32_t*)&sb[kv + TK1L + bo + 8];
                b2h[0] = *(const uint32_t*)&sb[kv + TK2H + bo];
                b2h[1] = *(const uint32_t*)&sb[kv + TK2H + bo + 8];
                b2l[0] = *(const uint32_t*)&sb[kv + TK2L + bo];
                b2l[1] = *(const uint32_t*)&sb[kv + TK2L + bo + 8];
                MMA_BF16(sc1[nb], a1h, b1h);
                MMA_BF16(sc1[nb], a1l, b1h);
                MMA_BF16(sc1[nb], a1h, b1l);
                MMA_BF16(sc2[nb], a2h, b2h);
                MMA_BF16(sc2[nb], a2l, b2h);
                MMA_BF16(sc2[nb], a2h, b2l);
            }
        }

#pragma unroll
        for (int nb = 0; nb < 8; nb++)
#pragma unroll
            for (int j = 0; j < 4; j++) {
                sc1[nb][j] = fminf(fmaxf(sc1[nb][j]*0.125f, -ATTN_CLIP), ATTN_CLIP);
                sc2[nb][j] = fminf(fmaxf(sc2[nb][j]*0.125f, -ATTN_CLIP), ATTN_CLIP);
            }

        softmax_upd(sc1, m1, l1, oc1);
        softmax_upd(sc2, m2, l2, oc2);

        // ---- O += P V : P fp16 hi/lo (2-pass), V fp16 single ----
#pragma unroll
        for (int kc = 0; kc < 4; kc++) {
            uint32_t p1h[4], p1l[4], p2h[4], p2l[4];
            p1h[0] = pk2h(sc1[2*kc][0],   sc1[2*kc][1]);
            p1h[1] = pk2h(sc1[2*kc][2],   sc1[2*kc][3]);
            p1h[2] = pk2h(sc1[2*kc+1][0], sc1[2*kc+1][1]);
            p1h[3] = pk2h(sc1[2*kc+1][2], sc1[2*kc+1][3]);
            p1l[0] = pk2hlo(sc1[2*kc][0],   sc1[2*kc][1],   p1h[0]);
            p1l[1] = pk2hlo(sc1[2*kc][2],   sc1[2*kc][3],   p1h[1]);
            p1l[2] = pk2hlo(sc1[2*kc+1][0], sc1[2*kc+1][1], p1h[2]);
            p1l[3] = pk2hlo(sc1[2*kc+1][2], sc1[2*kc+1][3], p1h[3]);
            p2h[0] = pk2h(sc2[2*kc][0],   sc2[2*kc][1]);
            p2h[1] = pk2h(sc2[2*kc][2],   sc2[2*kc][3]);
            p2h[2] = pk2h(sc2[2*kc+1][0], sc2[2*kc+1][1]);
            p2h[3] = pk2h(sc2[2*kc+1][2], sc2[2*kc+1][3]);
            p2l[0] = pk2hlo(sc2[2*kc][0],   sc2[2*kc][1],   p2h[0]);
            p2l[1] = pk2hlo(sc2[2*kc][2],   sc2[2*kc][3],   p2h[1]);
            p2l[2] = pk2hlo(sc2[2*kc+1][0], sc2[2*kc+1][1], p2h[2]);
            p2l[3] = pk2hlo(sc2[2*kc+1][2], sc2[2*kc+1][3], p2h[3]);
#pragma unroll
            for (int db = 0; db < 8; db++) {
                const int vo = (db*8 + g4)*AP + kc*16 + t4*2;
                uint32_t bvh[2];
                bvh[0] = *(const uint32_t*)&sb[kv + TVH + vo];
                bvh[1] = *(const uint32_t*)&sb[kv + TVH + vo + 8];
                MMA_FP16(oc1[db], p1h, bvh);
                MMA_FP16(oc1[db], p1l, bvh);
                MMA_FP16(oc2[db], p2h, bvh);
                MMA_FP16(oc2[db], p2l, bvh);
            }
        }
        __syncthreads();
    }

    // epilogue: combine streams -> fp16 (proj GEMM input)
    const float i10 = 1.f/(l1[0]+EPSF), i11 = 1.f/(l1[1]+EPSF);
    const float i20 = 1.f/(l2[0]+EPSF), i21 = 1.f/(l2[1]+EPSF);
    const int r0 = q0 + wid*16 + g4;
    size_t ob0 = ((size_t)b*SEQ + r0)*DIM + (size_t)h*HDIM;
    size_t ob1 = ob0 + (size_t)8*DIM;
#pragma unroll
    for (int db = 0; db < 8; db++) {
        const int c = db*8 + t4*2;
        float v0 = oc1[db][0]*i10 - lam*(oc2[db][0]*i20);
        float v1 = oc1[db][1]*i10 - lam*(oc2[db][1]*i20);
        float v2 = oc1[db][2]*i11 - lam*(oc2[db][2]*i21);
        float v3 = oc1[db][3]*i11 - lam*(oc2[db][3]*i21);
        *(uint32_t*)(oH + ob0 + c) = pk2h(v0, v1);
        *(uint32_t*)(oH + ob1 + c) = pk2h(v2, v3);
    }
}

// ================= launch =================
extern "C" void kernel_launch(void* const* d_in, const int* in_sizes, int n_in,
                              void* d_out, int out_size) {
    const float* x      = (const float*)d_in[0];
    const float* w_qkv  = (const float*)d_in[1];
    const float* lq1    = (const float*)d_in[2];
    const float* lk1    = (const float*)d_in[3];
    const float* lq2    = (const float*)d_in[4];
    const float* lk2    = (const float*)d_in[5];
    const float* w_proj = (const float*)d_in[6];
    const float* b_proj = (const float*)d_in[7];
    const float* gamma1 = (const float*)d_in[8];
    const float* beta1  = (const float*)d_in[9];
    const float* gamma2 = (const float*)d_in[10];
    const float* beta2  = (const float*)d_in[11];
    const float* w1     = (const float*)d_in[12];
    const float* b1     = (const float*)d_in[13];
    const float* w2     = (const float*)d_in[14];
    const float* b2     = (const float*)d_in[15];
    float* out = (float*)d_out;

    float *p_x2;
    __half *p_ah, *p_bh, *p_vt;
    __nv_bfloat16 *p_qhi, *p_qlo;
    cudaGetSymbolAddress((void**)&p_x2,  g_x2);
    cudaGetSymbolAddress((void**)&p_ah,  g_ah);
    cudaGetSymbolAddress((void**)&p_qhi, g_qhi);
    cudaGetSymbolAddress((void**)&p_qlo, g_qlo);
    cudaGetSymbolAddress((void**)&p_bh,  g_bh);
    cudaGetSymbolAddress((void**)&p_vt,  g_vt);

    cudaFuncSetAttribute(diff_attn_mma,
                         cudaFuncAttributeMaxDynamicSharedMemorySize, SMEM_ATT);
    cudaFuncSetAttribute(wmma_gemm<2>, cudaFuncAttributeMaxDynamicSharedMemorySize, SMEM_WG);
    cudaFuncSetAttribute(wmma_gemm<4>, cudaFuncAttributeMaxDynamicSharedMemorySize, SMEM_WG);
    cudaFuncSetAttribute(wmma_gemm<5>, cudaFuncAttributeMaxDynamicSharedMemorySize, SMEM_WG);

    // scalars
    reduce_sq_kernel<<<dim3(128, BATCH), 256>>>(x);
    compute_nx_kernel<<<1, 32>>>();
    compute_lam_kernel<<<1, 1>>>(lq1, lk1, lq2, lk2);

    // GRN1 -> h fp16
    grn_half_kernel<<<(MTOT*DIM)/4/256, 256>>>(x, gamma1, beta1, p_ah);

    // QKV GEMM -> qkv bf16 hi/lo (attention input)
    transpose_half_kernel<<<dim3(QKVW/32, DIM/32), dim3(32, 8)>>>(w_qkv, p_bh, DIM, QKVW);
    wmma_gemm<4><<<dim3(QKVW/128, MTOT/128), 256, SMEM_WG>>>(
        p_ah, p_bh, nullptr, p_qhi, p_qlo, MTOT, QKVW, DIM, nullptr, nullptr);

    // V transpose -> vt[bh][d][kk] (fp16)
    vtrans_kernel<<<dim3(SEQ/32, 32, BATCH), dim3(32, 8)>>>(p_qhi, p_qlo, p_vt);

    // attention -> o fp16 (into a array)
    diff_attn_mma<<<dim3(SEQ/64, NHEADS, BATCH), 128, SMEM_ATT>>>(
        p_qhi, p_qlo, p_vt, p_ah);

    // proj + bias + residual(x) -> x2 fp32
    transpose_half_kernel<<<dim3(DIM/32, DIM/32), dim3(32, 8)>>>(w_proj, p_bh, DIM, DIM);
    wmma_gemm<2><<<dim3(DIM/128, MTOT/128), 256, SMEM_WG>>>(
        p_ah, p_bh, p_x2, nullptr, nullptr, MTOT, DIM, DIM, b_proj, x);

    // GRN2 -> h2 fp16
    reduce_sq_kernel<<<dim3(128, BATCH), 256>>>(p_x2);
    compute_nx_kernel<<<1, 32>>>();
    grn_half_kernel<<<(MTOT*DIM)/4/256, 256>>>(p_x2, gamma2, beta2, p_ah);

    // FFN1: silu(h2 @ w1 + b1) -> f fp16 (into q array)
    transpose_half_kernel<<<dim3(MLP/32, DIM/32), dim3(32, 8)>>>(w1, p_bh, DIM, MLP);
    wmma_gemm<5><<<dim3(MLP/128, MTOT/128), 256, SMEM_WG>>>(
        p_ah, p_bh, nullptr, (void*)p_qhi, nullptr, MTOT, MLP, DIM, b1, nullptr);

    // FFN2: f @ w2 + b2 + residual(x2) -> out
    transpose_half_kernel<<<dim3(DIM/32, MLP/32), dim3(32, 8)>>>(w2, p_bh, MLP, DIM);
    wmma_gemm<2><<<dim3(DIM/128, MTOT/128), 256, SMEM_WG>>>(
        (const __half*)p_qhi, p_bh, out, nullptr, nullptr, MTOT, DIM, MLP, b2, p_x2);
}

// round 17
// speedup vs baseline: 3.0986x; 1.0655x over previous
#include <cuda_runtime.h>
#include <cuda_bf16.h>
#include <cuda_fp16.h>
#include <mma.h>
#include <math.h>
#include <cstdint>

using namespace nvcuda;

#define BATCH 4
#define SEQ 1024
#define DIM 1024
#define NHEADS 16
#define HDIM 64
#define MLP 4096
#define MTOT (BATCH*SEQ)        /* 4096 */
#define QKVW (5*NHEADS*HDIM)    /* 5120 */
#define ATTN_CLIP 100.0f
#define NORM_CLIP 1000.0f
#define EPSF 1e-6f

// ================= scratch =================
__device__ float g_x2 [MTOT*DIM];
__device__ __half g_ah [(size_t)MTOT*MLP];                   // GEMM A (h / o / h2) fp16
__device__ __half g_qh [(size_t)MTOT*QKVW];                  // qkv fp16 hi; later f
__device__ __half g_ql [(size_t)MTOT*QKVW];                  // qkv fp16 lo
__device__ __half g_bh [(size_t)QKVW*DIM];                   // weights^T fp16
__device__ __half g_vt [(size_t)BATCH*NHEADS*HDIM*SEQ];      // V^T fp16
__device__ float g_part[BATCH*128];
__device__ float g_nx[BATCH];
__device__ float g_lam;

// ================= helpers =================
__device__ __forceinline__ uint32_t smem_u32(const void* p) {
    uint32_t a;
    asm("{ .reg .u64 t; cvta.to.shared.u64 t, %1; cvt.u32.u64 %0, t; }" : "=r"(a) : "l"(p));
    return a;
}
#define CP_ASYNC16(dst, src) \
    asm volatile("cp.async.cg.shared.global [%0], [%1], 16;" :: "r"(dst), "l"(src))
#define CP_COMMIT() asm volatile("cp.async.commit_group;" ::: "memory")
#define CP_WAIT(n)  asm volatile("cp.async.wait_group %0;" :: "n"(n) : "memory")

#define MMA_FP16(d, a, b) \
    asm volatile("mma.sync.aligned.m16n8k16.row.col.f32.f16.f16.f32 " \
        "{%0,%1,%2,%3}, {%4,%5,%6,%7}, {%8,%9}, {%0,%1,%2,%3};" \
        : "+f"((d)[0]), "+f"((d)[1]), "+f"((d)[2]), "+f"((d)[3]) \
        : "r"((a)[0]), "r"((a)[1]), "r"((a)[2]), "r"((a)[3]), \
          "r"((b)[0]), "r"((b)[1]))

// fp16 packers
__device__ __forceinline__ uint32_t pk2h(float x, float y) {
    __half2 t = __floats2half2_rn(x, y);
    return *(uint32_t*)&t;
}
__device__ __forceinline__ uint32_t pk2hlo(float x, float y, uint32_t hipk) {
    __half2 hp = *(__half2*)&hipk;
    return pk2h(x - __half2float(hp.x), y - __half2float(hp.y));
}

// ================= scalar kernels =================
__global__ void reduce_sq_kernel(const float* __restrict__ x) {
    const int b = blockIdx.y, blk = blockIdx.x;
    const int N = SEQ*DIM;
    const int per = N / 128;
    const float* p = x + (size_t)b*N + (size_t)blk*per;
    float s = 0.f;
    for (int i = threadIdx.x; i < per; i += 256) { float v = p[i]; s += v*v; }
    __shared__ float red[8];
    int lane = threadIdx.x & 31, w = threadIdx.x >> 5;
#pragma unroll
    for (int o = 16; o; o >>= 1) s += __shfl_down_sync(0xffffffffu, s, o);
    if (lane == 0) red[w] = s;
    __syncthreads();
    if (w == 0) {
        s = (lane < 8) ? red[lane] : 0.f;
#pragma unroll
        for (int o = 4; o; o >>= 1) s += __shfl_down_sync(0xffffffffu, s, o);
        if (lane == 0) g_part[b*128 + blk] = s;
    }
}

__global__ void compute_nx_kernel() {
    int b = threadIdx.x;
    if (b < BATCH) {
        float s = 0.f;
        for (int i = 0; i < 128; i++) s += g_part[b*128 + i];
        s = fminf(fmaxf(s, EPSF), NORM_CLIP);
        float gx = sqrtf(s);
        float nx = gx / (gx + EPSF);
        nx = fminf(fmaxf(nx, -NORM_CLIP), NORM_CLIP);
        g_nx[b] = nx;
    }
}

__global__ void compute_lam_kernel(const float* __restrict__ lq1, const float* __restrict__ lk1,
                                   const float* __restrict__ lq2, const float* __restrict__ lk2) {
    float s1 = 0.f, s2 = 0.f;
    for (int d = 0; d < HDIM; d++) { s1 += lq1[d]*lk1[d]; s2 += lq2[d]*lk2[d]; }
    s1 = fminf(fmaxf(s1, -10.f), 10.f);
    s2 = fminf(fmaxf(s2, -10.f), 10.f);
    float lam_init = 0.8f - 0.6f*expf(-0.0f);
    float lam = expf(s1) - expf(s2) + lam_init;
    g_lam = fminf(fmaxf(lam, 0.1f), 5.f);
}

// ================= GRN fused, fp16 output =================
__global__ void grn_half_kernel(const float* __restrict__ x, const float* __restrict__ gamma,
                                const float* __restrict__ beta, __half* __restrict__ o) {
    int idx = blockIdx.x*blockDim.x + threadIdx.x;
    int e = idx * 4;
    int b = e >> 20;
    int d = e & (DIM-1);
    float nx = g_nx[b];
    float4 xv = *(const float4*)(x + e);
    float4 gv = *(const float4*)(gamma + d);
    float4 bv = *(const float4*)(beta + d);
    float r0 = gv.x*(xv.x*nx) + bv.x + xv.x;
    float r1 = gv.y*(xv.y*nx) + bv.y + xv.y;
    float r2 = gv.z*(xv.z*nx) + bv.z + xv.z;
    float r3 = gv.w*(xv.w*nx) + bv.w + xv.w;
    uint2 ph;
    ph.x = pk2h(r0, r1); ph.y = pk2h(r2, r3);
    *(uint2*)(o + e) = ph;
}

// ================= weight transpose to fp16: w[K][N] -> t[N][K] =================
__global__ void transpose_half_kernel(const float* __restrict__ w,
                                      __half* __restrict__ th, int K, int N) {
    __shared__ float tile[32][33];
    int n0 = blockIdx.x * 32, k0 = blockIdx.y * 32;
    int tx = threadIdx.x, ty = threadIdx.y;
#pragma unroll
    for (int i = 0; i < 4; i++)
        tile[ty + i*8][tx] = w[(size_t)(k0 + ty + i*8)*N + n0 + tx];
    __syncthreads();
#pragma unroll
    for (int i = 0; i < 4; i++) {
        float v = tile[tx][ty + i*8];
        th[(size_t)(n0 + ty + i*8)*K + k0 + tx] = __float2half(v);
    }
}

// ================= V transpose -> single fp16 vt[bh][d][kk] =================
__global__ void vtrans_kernel(const __half* __restrict__ qH,
                              const __half* __restrict__ qL,
                              __half* __restrict__ vt) {
    __shared__ float tv[32][33];
    const int b = blockIdx.z;
    const int t0 = blockIdx.x * 32;
    const int f0 = blockIdx.y * 32;
    const int tx = threadIdx.x, ty = threadIdx.y;
#pragma unroll
    for (int i = 0; i < 4; i++) {
        size_t src = (size_t)(b*SEQ + t0 + ty + i*8)*QKVW + 4096 + f0 + tx;
        tv[ty + i*8][tx] = __half2float(qH[src]) + __half2float(qL[src]);
    }
    __syncthreads();
#pragma unroll
    for (int i = 0; i < 4; i++) {
        int f = f0 + ty + i*8;
        int h = f >> 6, d = f & 63;
        size_t dst = ((size_t)(b*NHEADS + h)*HDIM + d)*SEQ + t0 + tx;
        vt[dst] = __float2half(tv[tx][ty + i*8]);
    }
}

// ================= single-pass fp16 wmma GEMM, K-chunk 64 =================
// EPI 2: fp32 C = acc+bias+res; EPI 4: fp16 hi/lo split(acc); EPI 5: fp16 silu(acc+bias)
#define KC 64
#define LDA 72
#define TILE_ELEMS (128*LDA)
#define BUF_ELEMS (2*TILE_ELEMS)
#define SMEM_WG (2*BUF_ELEMS*2)
#define SLD 132

template<int EPI>
__global__ __launch_bounds__(256, 2)
void wmma_gemm(const __half* __restrict__ A, const __half* __restrict__ B,
               float* __restrict__ C, void* __restrict__ CHv, void* __restrict__ CLv,
               int M, int N, int K,
               const float* __restrict__ bias, const float* __restrict__ res) {
    extern __shared__ char smem_raw[];
    __half* sm = (__half*)smem_raw;
    const uint32_t sm_addr = smem_u32(sm);

    const int tid = threadIdx.x;
    const int wid = tid >> 5;
    const int row0 = blockIdx.y * 128;
    const int col0 = blockIdx.x * 128;
    const int wr = (wid >> 1) * 32;
    const int wc = (wid & 1) * 64;

    const __half* gsrc[2] = { A + (size_t)row0*K, B + (size_t)col0*K };

    int u_arr[8], u_row[8], u_col[8];
#pragma unroll
    for (int i = 0; i < 8; i++) {
        int idx = tid + i*256;
        u_arr[i] = idx >> 10;
        int rem = idx & 1023;
        u_row[i] = rem >> 3;
        u_col[i] = (rem & 7) * 8;
    }

    auto issue_chunk = [&](int k0, int buf) {
        uint32_t dbase = sm_addr + (uint32_t)buf * (BUF_ELEMS*2);
#pragma unroll
        for (int i = 0; i < 8; i++) {
            const __half* src = gsrc[u_arr[i]] + (size_t)u_row[i]*K + k0 + u_col[i];
            uint32_t dst = dbase + (uint32_t)(u_arr[i]*TILE_ELEMS + u_row[i]*LDA + u_col[i]) * 2;
            CP_ASYNC16(dst, src);
        }
        CP_COMMIT();
    };

    wmma::fragment<wmma::accumulator, 16, 16, 16, float> acc[2][4];
#pragma unroll
    for (int i = 0; i < 2; i++)
#pragma unroll
        for (int j = 0; j < 4; j++) wmma::fill_fragment(acc[i][j], 0.f);

    const int nch = K / KC;
    issue_chunk(0, 0);

    for (int ch = 0; ch < nch; ch++) {
        const int cur = ch & 1;
        if (ch + 1 < nch) { issue_chunk((ch+1)*KC, cur ^ 1); CP_WAIT(1); }
        else              { CP_WAIT(0); }
        __syncthreads();

        const __half* b0 = sm + cur * BUF_ELEMS;
        const __half* tA = b0 + 0*TILE_ELEMS + wr*LDA;
        const __half* tB = b0 + 1*TILE_ELEMS + wc*LDA;

#pragma unroll
        for (int ks = 0; ks < 4; ks++) {
            wmma::fragment<wmma::matrix_a, 16, 16, 16, __half, wmma::row_major> aF[2];
            wmma::fragment<wmma::matrix_b, 16, 16, 16, __half, wmma::col_major> bF[4];
            const int ko = ks * 16;
#pragma unroll
            for (int i = 0; i < 2; i++)
                wmma::load_matrix_sync(aF[i], tA + i*16*LDA + ko, LDA);
#pragma unroll
            for (int j = 0; j < 4; j++)
                wmma::load_matrix_sync(bF[j], tB + j*16*LDA + ko, LDA);
#pragma unroll
            for (int i = 0; i < 2; i++)
#pragma unroll
                for (int j = 0; j < 4; j++)
                    wmma::mma_sync(acc[i][j], aF[i], bF[j], acc[i][j]);
        }
        __syncthreads();
    }

    float* stage = (float*)smem_raw;
#pragma unroll
    for (int i = 0; i < 2; i++)
#pragma unroll
        for (int j = 0; j < 4; j++)
            wmma::store_matrix_sync(stage + (wr + i*16)*SLD + wc + j*16,
                                    acc[i][j], SLD, wmma::mem_row_major);
    __syncthreads();

    const int r = tid >> 1;
    const int c0 = (tid & 1) * 64;
    const int row = row0 + r;

    if (EPI == 2) {
        size_t obase = (size_t)row*N + col0 + c0;
#pragma unroll
        for (int j = 0; j < 16; j++) {
            float4 v = *(float4*)(stage + r*SLD + c0 + j*4);
            float4 w;
            float* vi = (float*)&v; float* wi = (float*)&w;
#pragma unroll
            for (int q = 0; q < 4; q++)
                wi[q] = vi[q] + bias[col0 + c0 + j*4 + q] + res[obase + j*4 + q];
            *(float4*)(C + obase + j*4) = w;
        }
    } else if (EPI == 4) {
        // fp16 hi/lo split (attention input)
        __half* dh = (__half*)CHv + (size_t)row*N + col0 + c0;
        __half* dl = (__half*)CLv + (size_t)row*N + col0 + c0;
#pragma unroll
        for (int j = 0; j < 8; j++) {
            float t[8];
#pragma unroll
            for (int q = 0; q < 8; q++) t[q] = stage[r*SLD + c0 + j*8 + q];
            uint4 ph, pl;
            uint32_t* phi = (uint32_t*)&ph;
            uint32_t* pli = (uint32_t*)&pl;
#pragma unroll
            for (int q = 0; q < 4; q++) {
                phi[q] = pk2h(t[2*q], t[2*q+1]);
                pli[q] = pk2hlo(t[2*q], t[2*q+1], phi[q]);
            }
            *(uint4*)(dh + j*8) = ph;
            *(uint4*)(dl + j*8) = pl;
        }
    } else {
        __half* dh = (__half*)CHv + (size_t)row*N + col0 + c0;
#pragma unroll
        for (int j = 0; j < 8; j++) {
            float t[8];
#pragma unroll
            for (int q = 0; q < 8; q++) {
                float v = stage[r*SLD + c0 + j*8 + q] + bias[col0 + c0 + j*8 + q];
                t[q] = v / (1.f + __expf(-v));
            }
            uint4 ph;
            uint32_t* phi = (uint32_t*)&ph;
#pragma unroll
            for (int q = 0; q < 4; q++)
                phi[q] = pk2h(t[2*q], t[2*q+1]);
            *(uint4*)(dh + j*8) = ph;
        }
    }
}

// ================= differential flash attention: fp16 2-pass QK + 2-pass PV =================
#define AP 72
#define KVBUF 13824            /* 3 tiles: K1, K2, V (all fp16) */
#define TK1 0
#define TK2 4608
#define TV  9216
#define SMEM_ATT (2*KVBUF*2)   /* 55296 B */

__device__ __forceinline__ void softmax_upd(float sc[8][4], float m[2], float l[2],
                                            float oc[8][4]) {
    float t0 = -1e30f, t1 = -1e30f;
#pragma unroll
    for (int nb = 0; nb < 8; nb++) {
        t0 = fmaxf(t0, fmaxf(sc[nb][0], sc[nb][1]));
        t1 = fmaxf(t1, fmaxf(sc[nb][2], sc[nb][3]));
    }
    t0 = fmaxf(t0, __shfl_xor_sync(0xffffffffu, t0, 1));
    t0 = fmaxf(t0, __shfl_xor_sync(0xffffffffu, t0, 2));
    t1 = fmaxf(t1, __shfl_xor_sync(0xffffffffu, t1, 1));
    t1 = fmaxf(t1, __shfl_xor_sync(0xffffffffu, t1, 2));
    float nm0 = fmaxf(m[0], t0), nm1 = fmaxf(m[1], t1);
    float c0 = __expf(m[0] - nm0), c1 = __expf(m[1] - nm1);
    float s0 = 0.f, s1 = 0.f;
#pragma unroll
    for (int nb = 0; nb < 8; nb++) {
        float p0 = __expf(sc[nb][0] - nm0); sc[nb][0] = p0; s0 += p0;
        float p1 = __expf(sc[nb][1] - nm0); sc[nb][1] = p1; s0 += p1;
        float p2 = __expf(sc[nb][2] - nm1); sc[nb][2] = p2; s1 += p2;
        float p3 = __expf(sc[nb][3] - nm1); sc[nb][3] = p3; s1 += p3;
    }
    s0 += __shfl_xor_sync(0xffffffffu, s0, 1);
    s0 += __shfl_xor_sync(0xffffffffu, s0, 2);
    s1 += __shfl_xor_sync(0xffffffffu, s1, 1);
    s1 += __shfl_xor_sync(0xffffffffu, s1, 2);
    l[0] = l[0]*c0 + s0;  l[1] = l[1]*c1 + s1;
#pragma unroll
    for (int db = 0; db < 8; db++) {
        oc[db][0] *= c0; oc[db][1] *= c0;
        oc[db][2] *= c1; oc[db][3] *= c1;
    }
    m[0] = nm0; m[1] = nm1;
}

__global__ __launch_bounds__(128)
void diff_attn_mma(const __half* __restrict__ qH, const __half* __restrict__ qL,
                   const __half* __restrict__ vt, __half* __restrict__ oH) {
    extern __shared__ __half sbh[];
    const uint32_t smb = smem_u32(sbh);
    const int tid = threadIdx.x;
    const int wid = tid >> 5, lane = tid & 31;
    const int g4 = lane >> 2, t4 = lane & 3;
    const int qt = blockIdx.x, h = blockIdx.y, b = blockIdx.z;
    const int q0 = qt * 64;
    const float lam = g_lam;

    auto ld_tile = [&](uint32_t tileEls, const void* src, int rowStrideBytes) {
#pragma unroll
        for (int i = 0; i < 4; i++) {
            int idx = tid + i*128;
            int r = idx >> 3, c8 = idx & 7;
            CP_ASYNC16(smb + tileEls*2 + r*144 + c8*16,
                       (const char*)src + (size_t)r*rowStrideBytes + c8*16);
        }
    };

    // stage Q hi/lo for stream 1 in buffers 0/1, hoist to registers, then stream 2
    uint32_t qa1h[16], qa1l[16], qa2h[16], qa2l[16];
    {
        const size_t qb = (size_t)(b*SEQ + q0)*QKVW + h*HDIM;
        // buffer0: q1h (TK1), q1l (TK2), q2h (TV); buffer1 slot TK1: q2l
        ld_tile(TK1, qH + qb,        QKVW*2);
        ld_tile(TK2, qL + qb,        QKVW*2);
        ld_tile(TV,  qH + qb + 1024, QKVW*2);
        ld_tile(KVBUF + TK1, qL + qb + 1024, QKVW*2);
        CP_COMMIT();
        CP_WAIT(0);
        __syncthreads();
        const int ar = wid*16 + g4;
#pragma unroll
        for (int dc = 0; dc < 4; dc++) {
            const int ac = dc*16 + t4*2;
            qa1h[dc*4+0] = *(const uint32_t*)&sbh[TK1 + ar*AP + ac];
            qa1h[dc*4+1] = *(const uint32_t*)&sbh[TK1 + (ar+8)*AP + ac];
            qa1h[dc*4+2] = *(const uint32_t*)&sbh[TK1 + ar*AP + ac + 8];
            qa1h[dc*4+3] = *(const uint32_t*)&sbh[TK1 + (ar+8)*AP + ac + 8];
            qa1l[dc*4+0] = *(const uint32_t*)&sbh[TK2 + ar*AP + ac];
            qa1l[dc*4+1] = *(const uint32_t*)&sbh[TK2 + (ar+8)*AP + ac];
            qa1l[dc*4+2] = *(const uint32_t*)&sbh[TK2 + ar*AP + ac + 8];
            qa1l[dc*4+3] = *(const uint32_t*)&sbh[TK2 + (ar+8)*AP + ac + 8];
            qa2h[dc*4+0] = *(const uint32_t*)&sbh[TV + ar*AP + ac];
            qa2h[dc*4+1] = *(const uint32_t*)&sbh[TV + (ar+8)*AP + ac];
            qa2h[dc*4+2] = *(const uint32_t*)&sbh[TV + ar*AP + ac + 8];
            qa2h[dc*4+3] = *(const uint32_t*)&sbh[TV + (ar+8)*AP + ac + 8];
            qa2l[dc*4+0] = *(const uint32_t*)&sbh[KVBUF + TK1 + ar*AP + ac];
            qa2l[dc*4+1] = *(const uint32_t*)&sbh[KVBUF + TK1 + (ar+8)*AP + ac];
            qa2l[dc*4+2] = *(const uint32_t*)&sbh[KVBUF + TK1 + ar*AP + ac + 8];
            qa2l[dc*4+3] = *(const uint32_t*)&sbh[KVBUF + TK1 + (ar+8)*AP + ac + 8];
        }
    }
    __syncthreads();   // all Q reads done before KV[0] overwrites buffers

    const size_t kbase = (size_t)b*SEQ*QKVW + h*HDIM;
    const size_t vbase = ((size_t)(b*NHEADS + h)*HDIM)*SEQ;

    auto issue_kv = [&](int kt, int buf) {
        const uint32_t bo = (uint32_t)buf * KVBUF;
        const size_t kb = kbase + (size_t)(kt*64)*QKVW;
        const size_t vb = vbase + kt*64;
        ld_tile(bo + TK1, qH + kb + 2048, QKVW*2);   // K1 fp16 (hi only)
        ld_tile(bo + TK2, qH + kb + 3072, QKVW*2);   // K2 fp16 (hi only)
        ld_tile(bo + TV,  vt + vb, SEQ*2);
        CP_COMMIT();
    };

    issue_kv(0, 0);

    float oc1[8][4], oc2[8][4];
#pragma unroll
    for (int i = 0; i < 8; i++)
#pragma unroll
        for (int j = 0; j < 4; j++) { oc1[i][j] = 0.f; oc2[i][j] = 0.f; }
    float m1[2] = {-1e30f, -1e30f}, l1[2] = {0.f, 0.f};
    float m2[2] = {-1e30f, -1e30f}, l2[2] = {0.f, 0.f};

    for (int kt = 0; kt < 16; kt++) {
        const int cur = kt & 1;
        if (kt + 1 < 16) { issue_kv(kt + 1, cur ^ 1); CP_WAIT(1); }
        else             { CP_WAIT(0); }
        __syncthreads();

        const uint32_t kv = (uint32_t)cur * KVBUF;

        float sc1[8][4], sc2[8][4];
#pragma unroll
        for (int i = 0; i < 8; i++)
#pragma unroll
            for (int j = 0; j < 4; j++) { sc1[i][j] = 0.f; sc2[i][j] = 0.f; }

        // ---- S = (Qh + Ql) K^T, K single fp16, both streams ----
#pragma unroll
        for (int dc = 0; dc < 4; dc++) {
            const uint32_t* a1h = &qa1h[dc*4];
            const uint32_t* a1l = &qa1l[dc*4];
            const uint32_t* a2h = &qa2h[dc*4];
            const uint32_t* a2l = &qa2l[dc*4];
#pragma unroll
            for (int nb = 0; nb < 8; nb++) {
                const int bo = (nb*8 + g4)*AP + dc*16 + t4*2;
                uint32_t b1[2], b2[2];
                b1[0] = *(const uint32_t*)&sbh[kv + TK1 + bo];
                b1[1] = *(const uint32_t*)&sbh[kv + TK1 + bo + 8];
                b2[0] = *(const uint32_t*)&sbh[kv + TK2 + bo];
                b2[1] = *(const uint32_t*)&sbh[kv + TK2 + bo + 8];
                MMA_FP16(sc1[nb], a1h, b1);
                MMA_FP16(sc1[nb], a1l, b1);
                MMA_FP16(sc2[nb], a2h, b2);
                MMA_FP16(sc2[nb], a2l, b2);
            }
        }

#pragma unroll
        for (int nb = 0; nb < 8; nb++)
#pragma unroll
            for (int j = 0; j < 4; j++) {
                sc1[nb][j] = fminf(fmaxf(sc1[nb][j]*0.125f, -ATTN_CLIP), ATTN_CLIP);
                sc2[nb][j] = fminf(fmaxf(sc2[nb][j]*0.125f, -ATTN_CLIP), ATTN_CLIP);
            }

        softmax_upd(sc1, m1, l1, oc1);
        softmax_upd(sc2, m2, l2, oc2);

        // ---- O += P V : P fp16 hi/lo (2-pass), V fp16 single ----
#pragma unroll
        for (int kc = 0; kc < 4; kc++) {
            uint32_t p1h[4], p1l[4], p2h[4], p2l[4];
            p1h[0] = pk2h(sc1[2*kc][0],   sc1[2*kc][1]);
            p1h[1] = pk2h(sc1[2*kc][2],   sc1[2*kc][3]);
            p1h[2] = pk2h(sc1[2*kc+1][0], sc1[2*kc+1][1]);
            p1h[3] = pk2h(sc1[2*kc+1][2], sc1[2*kc+1][3]);
            p1l[0] = pk2hlo(sc1[2*kc][0],   sc1[2*kc][1],   p1h[0]);
            p1l[1] = pk2hlo(sc1[2*kc][2],   sc1[2*kc][3],   p1h[1]);
            p1l[2] = pk2hlo(sc1[2*kc+1][0], sc1[2*kc+1][1], p1h[2]);
            p1l[3] = pk2hlo(sc1[2*kc+1][2], sc1[2*kc+1][3], p1h[3]);
            p2h[0] = pk2h(sc2[2*kc][0],   sc2[2*kc][1]);
            p2h[1] = pk2h(sc2[2*kc][2],   sc2[2*kc][3]);
            p2h[2] = pk2h(sc2[2*kc+1][0], sc2[2*kc+1][1]);
            p2h[3] = pk2h(sc2[2*kc+1][2], sc2[2*kc+1][3]);
            p2l[0] = pk2hlo(sc2[2*kc][0],   sc2[2*kc][1],   p2h[0]);
            p2l[1] = pk2hlo(sc2[2*kc][2],   sc2[2*kc][3],   p2h[1]);
            p2l[2] = pk2hlo(sc2[2*kc+1][0], sc2[2*kc+1][1], p2h[2]);
            p2l[3] = pk2hlo(sc2[2*kc+1][2], sc2[2*kc+1][3], p2h[3]);
#pragma unroll
            for (int db = 0; db < 8; db++) {
                const int vo = (db*8 + g4)*AP + kc*16 + t4*2;
                uint32_t bv[2];
                bv[0] = *(const uint32_t*)&sbh[kv + TV + vo];
                bv[1] = *(const uint32_t*)&sbh[kv + TV + vo + 8];
                MMA_FP16(oc1[db], p1h, bv);
                MMA_FP16(oc1[db], p1l, bv);
                MMA_FP16(oc2[db], p2h, bv);
                MMA_FP16(oc2[db], p2l, bv);
            }
        }
        __syncthreads();
    }

    // epilogue: combine streams -> fp16 (proj GEMM input)
    const float i10 = 1.f/(l1[0]+EPSF), i11 = 1.f/(l1[1]+EPSF);
    const float i20 = 1.f/(l2[0]+EPSF), i21 = 1.f/(l2[1]+EPSF);
    const int r0 = q0 + wid*16 + g4;
    size_t ob0 = ((size_t)b*SEQ + r0)*DIM + (size_t)h*HDIM;
    size_t ob1 = ob0 + (size_t)8*DIM;
#pragma unroll
    for (int db = 0; db < 8; db++) {
        const int c = db*8 + t4*2;
        float v0 = oc1[db][0]*i10 - lam*(oc2[db][0]*i20);
        float v1 = oc1[db][1]*i10 - lam*(oc2[db][1]*i20);
        float v2 = oc1[db][2]*i11 - lam*(oc2[db][2]*i21);
        float v3 = oc1[db][3]*i11 - lam*(oc2[db][3]*i21);
        *(uint32_t*)(oH + ob0 + c) = pk2h(v0, v1);
        *(uint32_t*)(oH + ob1 + c) = pk2h(v2, v3);
    }
}

// ================= launch =================
extern "C" void kernel_launch(void* const* d_in, const int* in_sizes, int n_in,
                              void* d_out, int out_size) {
    const float* x      = (const float*)d_in[0];
    const float* w_qkv  = (const float*)d_in[1];
    const float* lq1    = (const float*)d_in[2];
    const float* lk1    = (const float*)d_in[3];
    const float* lq2    = (const float*)d_in[4];
    const float* lk2    = (const float*)d_in[5];
    const float* w_proj = (const float*)d_in[6];
    const float* b_proj = (const float*)d_in[7];
    const float* gamma1 = (const float*)d_in[8];
    const float* beta1  = (const float*)d_in[9];
    const float* gamma2 = (const float*)d_in[10];
    const float* beta2  = (const float*)d_in[11];
    const float* w1     = (const float*)d_in[12];
    const float* b1     = (const float*)d_in[13];
    const float* w2     = (const float*)d_in[14];
    const float* b2     = (const float*)d_in[15];
    float* out = (float*)d_out;

    float *p_x2;
    __half *p_ah, *p_qh, *p_ql, *p_bh, *p_vt;
    cudaGetSymbolAddress((void**)&p_x2, g_x2);
    cudaGetSymbolAddress((void**)&p_ah, g_ah);
    cudaGetSymbolAddress((void**)&p_qh, g_qh);
    cudaGetSymbolAddress((void**)&p_ql, g_ql);
    cudaGetSymbolAddress((void**)&p_bh, g_bh);
    cudaGetSymbolAddress((void**)&p_vt, g_vt);

    cudaFuncSetAttribute(diff_attn_mma,
                         cudaFuncAttributeMaxDynamicSharedMemorySize, SMEM_ATT);
    cudaFuncSetAttribute(wmma_gemm<2>, cudaFuncAttributeMaxDynamicSharedMemorySize, SMEM_WG);
    cudaFuncSetAttribute(wmma_gemm<4>, cudaFuncAttributeMaxDynamicSharedMemorySize, SMEM_WG);
    cudaFuncSetAttribute(wmma_gemm<5>, cudaFuncAttributeMaxDynamicSharedMemorySize, SMEM_WG);

    // scalars
    reduce_sq_kernel<<<dim3(128, BATCH), 256>>>(x);
    compute_nx_kernel<<<1, 32>>>();
    compute_lam_kernel<<<1, 1>>>(lq1, lk1, lq2, lk2);

    // GRN1 -> h fp16
    grn_half_kernel<<<(MTOT*DIM)/4/256, 256>>>(x, gamma1, beta1, p_ah);

    // QKV GEMM -> qkv fp16 hi/lo (attention input)
    transpose_half_kernel<<<dim3(QKVW/32, DIM/32), dim3(32, 8)>>>(w_qkv, p_bh, DIM, QKVW);
    wmma_gemm<4><<<dim3(QKVW/128, MTOT/128), 256, SMEM_WG>>>(
        p_ah, p_bh, nullptr, p_qh, p_ql, MTOT, QKVW, DIM, nullptr, nullptr);

    // V transpose -> vt[bh][d][kk] (fp16)
    vtrans_kernel<<<dim3(SEQ/32, 32, BATCH), dim3(32, 8)>>>(p_qh, p_ql, p_vt);

    // attention -> o fp16 (into a array)
    diff_attn_mma<<<dim3(SEQ/64, NHEADS, BATCH), 128, SMEM_ATT>>>(
        p_qh, p_ql, p_vt, p_ah);

    // proj + bias + residual(x) -> x2 fp32
    transpose_half_kernel<<<dim3(DIM/32, DIM/32), dim3(32, 8)>>>(w_proj, p_bh, DIM, DIM);
    wmma_gemm<2><<<dim3(DIM/128, MTOT/128), 256, SMEM_WG>>>(
        p_ah, p_bh, p_x2, nullptr, nullptr, MTOT, DIM, DIM, b_proj, x);

    // GRN2 -> h2 fp16
    reduce_sq_kernel<<<dim3(128, BATCH), 256>>>(p_x2);
    compute_nx_kernel<<<1, 32>>>();
    grn_half_kernel<<<(MTOT*DIM)/4/256, 256>>>(p_x2, gamma2, beta2, p_ah);

    // FFN1: silu(h2 @ w1 + b1) -> f fp16 (into qh array)
    transpose_half_kernel<<<dim3(MLP/32, DIM/32), dim3(32, 8)>>>(w1, p_bh, DIM, MLP);
    wmma_gemm<5><<<dim3(MLP/128, MTOT/128), 256, SMEM_WG>>>(
        p_ah, p_bh, nullptr, (void*)p_qh, nullptr, MTOT, MLP, DIM, b1, nullptr);

    // FFN2: f @ w2 + b2 + residual(x2) -> out
    transpose_half_kernel<<<dim3(DIM/32, MLP/32), dim3(32, 8)>>>(w2, p_bh, MLP, DIM);
    wmma_gemm<2><<<dim3(DIM/128, MTOT/128), 256, SMEM_WG>>>(
        p_qh, p_bh, out, nullptr, nullptr, MTOT, DIM, MLP, b2, p_x2);
}